// round 12
// baseline (speedup 1.0000x reference)
#include <cuda_runtime.h>
#include <cuda_fp16.h>
#include <cstddef>
#include <cstdint>

#define Nn 20000
#define Ee 256
#define Hh 512
#define Ll 5
#define NCONV 15
#define MB_CAP 320000
#define MX_CAP 160000

// ---------------- scratch (device globals; no allocations allowed) ----------
__device__ float g_h[Nn * Ee];      // atom-encoder output (conv0 input)
__device__ float g_hB[Nn * Ee];     // conv output pre-outer-BN
__device__ float g_sumsH[NCONV * 2 * Hh];
__device__ float g_sumsE[NCONV * 2 * Ee];
__device__ float g_mask[Nn];
__device__ int   g_mask_dtype;

// fp16 split operands
__device__ __half g_A1hi[Nn * Ee];
__device__ __half g_A1lo[Nn * Ee];
__device__ __half g_t1hi[Nn * Hh];  // GEMM1 raw output as fp16 pair
__device__ __half g_t1lo[Nn * Hh];
// pre-transposed weights
__device__ __half g_W1Thi[NCONV * Hh * Ee];
__device__ __half g_W1Tlo[NCONV * Hh * Ee];
__device__ __half g_W2Thi[NCONV * Ee * Hh];
__device__ __half g_W2Tlo[NCONV * Ee * Hh];

// CSR (3 orientations: 0=bond by dst, 1=expander by edst, 2=expander by esrc)
__device__ int g_deg[3 * Nn];
__device__ int g_cur[3 * Nn];
__device__ int g_offs_b[Nn + 1], g_offs_l[Nn + 1], g_offs_r[Nn + 1];
__device__ int g_src_b[MB_CAP];
__device__ int g_atr_b[MB_CAP];
__device__ int g_src_l[MX_CAP];
__device__ int g_src_r[MX_CAP];

// ---------------- helpers ----------------------------------------------------
__device__ __forceinline__ uint32_t smem_u32(const void* p) {
    uint32_t a;
    asm("{ .reg .u64 t; cvta.to.shared.u64 t, %1; cvt.u32.u64 %0, t; }" : "=r"(a) : "l"(p));
    return a;
}
#define SW128(off) ((off) ^ (((off) >> 3) & 0x70))

#define LDSM_X4(r0, r1, r2, r3, addr) \
    asm volatile("ldmatrix.sync.aligned.m8n8.x4.shared.b16 {%0,%1,%2,%3}, [%4];" \
                 : "=r"(r0), "=r"(r1), "=r"(r2), "=r"(r3) : "r"(addr))

#define MMA16816(d, a0, a1, a2, a3, b0, b1) \
    asm volatile("mma.sync.aligned.m16n8k16.row.col.f32.f16.f16.f32 " \
                 "{%0,%1,%2,%3}, {%4,%5,%6,%7}, {%8,%9}, {%0,%1,%2,%3};" \
                 : "+f"((d)[0]), "+f"((d)[1]), "+f"((d)[2]), "+f"((d)[3]) \
                 : "r"(a0), "r"(a1), "r"(a2), "r"(a3), "r"(b0), "r"(b1))

#define CP_ASYNC16(dst, src, sz) \
    asm volatile("cp.async.cg.shared.global [%0], [%1], 16, %2;" \
                 :: "r"(dst), "l"(src), "r"(sz))
#define CP_COMMIT() asm volatile("cp.async.commit_group;" ::: "memory")
#define CP_WAIT0() asm volatile("cp.async.wait_group 0;" ::: "memory")
#define CP_WAIT1() asm volatile("cp.async.wait_group 1;" ::: "memory")

__device__ __forceinline__ uint32_t pack2h(float a, float b) {
    __half ha = __float2half_rn(a), hb = __float2half_rn(b);
    return (uint32_t)__half_as_ushort(ha) | ((uint32_t)__half_as_ushort(hb) << 16);
}

// ---------------- mask dtype detection ---------------------------------------
__global__ void detect_mask_k(const void* mask) {
    __shared__ int not_i32, not_f32;
    if (threadIdx.x == 0) { not_i32 = 0; not_f32 = 0; }
    __syncthreads();
    const unsigned* w = (const unsigned*)mask;
    int bad_i = 0, bad_f = 0;
    for (int i = threadIdx.x; i < Nn / 4; i += blockDim.x) {
        unsigned v = w[i];
        if (v > 1u) bad_i = 1;
        if (v != 0u && v != 0x3F800000u) bad_f = 1;
    }
    if (bad_i) atomicOr(&not_i32, 1);
    if (bad_f) atomicOr(&not_f32, 1);
    __syncthreads();
    if (threadIdx.x == 0) {
        if (!not_i32) g_mask_dtype = 0;
        else if (!not_f32) g_mask_dtype = 1;
        else g_mask_dtype = 2;
    }
}

// setup: convert mask + zero degs + zero sums slices (re-runs every replay)
__global__ void setup_k(const void* mask) {
    int i = blockIdx.x * blockDim.x + threadIdx.x;
    int stride = gridDim.x * blockDim.x;
    int dt = g_mask_dtype;
    for (int n = i; n < Nn; n += stride) {
        float m;
        if (dt == 0)      m = (((const int*)mask)[n] != 0) ? 1.f : 0.f;
        else if (dt == 1) m = (((const float*)mask)[n] != 0.f) ? 1.f : 0.f;
        else              m = (((const unsigned char*)mask)[n] != 0) ? 1.f : 0.f;
        g_mask[n] = m;
    }
    for (int n = i; n < 3 * Nn; n += stride) g_deg[n] = 0;
    for (int n = i; n < NCONV * 2 * Hh; n += stride) g_sumsH[n] = 0.f;
    for (int n = i; n < NCONV * 2 * Ee; n += stride) g_sumsE[n] = 0.f;
}

// ---------------- atom encoder ------------------------------------------------
__global__ void atom_encode_k(const int* __restrict__ x,
                              const float* __restrict__ emb,
                              float* __restrict__ h) {
    int n = blockIdx.x;
    int t = threadIdx.x;
    float4 acc = make_float4(0.f, 0.f, 0.f, 0.f);
#pragma unroll
    for (int f = 0; f < 9; f++) {
        int idx = __ldg(&x[n * 9 + f]);
        const float4* row = (const float4*)&emb[((size_t)(f * 128 + idx)) * Ee];
        float4 v = row[t];
        acc.x += v.x; acc.y += v.y; acc.z += v.z; acc.w += v.w;
    }
    ((float4*)h)[(size_t)n * (Ee / 4) + t] = acc;
}

// ---------------- CSR build (fused across 3 orientations) --------------------
__global__ void hist_all_k(const int* __restrict__ ei, const int* __restrict__ xei,
                           int M, int MX) {
    int e = blockIdx.x * blockDim.x + threadIdx.x;
    if (e < M) atomicAdd(&g_deg[ei[M + e]], 1);
    else if (e < M + MX) atomicAdd(&g_deg[Nn + xei[MX + (e - M)]], 1);
    else if (e < M + 2 * MX) atomicAdd(&g_deg[2 * Nn + xei[e - M - MX]], 1);
}

__global__ void scan_all_k() {
    int which = blockIdx.x;
    const int* deg = g_deg + which * Nn;
    int* cur = g_cur + which * Nn;
    int* offs = (which == 0) ? g_offs_b : (which == 1) ? g_offs_l : g_offs_r;
    __shared__ int ssum[1024];
    int t = threadIdx.x;
    const int PER = (Nn + 1023) / 1024;  // 20
    int loc[20];
    int s = 0;
#pragma unroll
    for (int i = 0; i < PER; i++) {
        int idx = t * PER + i;
        int v = (idx < Nn) ? deg[idx] : 0;
        loc[i] = s;
        s += v;
    }
    ssum[t] = s;
    __syncthreads();
    for (int off = 1; off < 1024; off <<= 1) {
        int v = (t >= off) ? ssum[t - off] : 0;
        __syncthreads();
        ssum[t] += v;
        __syncthreads();
    }
    int pre = (t > 0) ? ssum[t - 1] : 0;
#pragma unroll
    for (int i = 0; i < PER; i++) {
        int idx = t * PER + i;
        if (idx < Nn) {
            offs[idx] = pre + loc[i];
            cur[idx] = pre + loc[i];
        }
    }
    if (t == 1023) offs[Nn] = ssum[1023];
}

__global__ void fill_all_k(const int* __restrict__ ei, const int* __restrict__ xei,
                           const int* __restrict__ ea, int M, int MX) {
    int e = blockIdx.x * blockDim.x + threadIdx.x;
    if (e < M) {
        int p = atomicAdd(&g_cur[ei[M + e]], 1);
        if (p < MB_CAP) {
            g_src_b[p] = ei[e];
            g_atr_b[p] = ea[e * 3] | (ea[e * 3 + 1] << 3) | (ea[e * 3 + 2] << 6);
        }
    } else if (e < M + MX) {
        int j = e - M;
        int p = atomicAdd(&g_cur[Nn + xei[MX + j]], 1);
        if (p < MX_CAP) g_src_l[p] = xei[j];
    } else if (e < M + 2 * MX) {
        int j = e - M - MX;
        int p = atomicAdd(&g_cur[2 * Nn + xei[j]], 1);
        if (p < MX_CAP) g_src_r[p] = xei[MX + j];
    }
}

// ---------------- merged weight transpose + fp16 split ------------------------
__global__ void wsplit_all_k(const float* __restrict__ W1m, const float* __restrict__ W1e,
                             const float* __restrict__ W2m, const float* __restrict__ W2e) {
    int z = blockIdx.z;
    int which = z / NCONV;
    int c = z % NCONV;
    int l = c / 3, j = c % 3;
    const float* W;
    __half *Thi, *Tlo;
    int K, N;
    if (which == 0) {
        K = Ee; N = Hh;
        W = j ? W1e + (size_t)(l * 2 + j - 1) * Ee * Hh : W1m + (size_t)l * Ee * Hh;
        Thi = g_W1Thi + (size_t)c * Hh * Ee;
        Tlo = g_W1Tlo + (size_t)c * Hh * Ee;
    } else {
        K = Hh; N = Ee;
        W = j ? W2e + (size_t)(l * 2 + j - 1) * Hh * Ee : W2m + (size_t)l * Hh * Ee;
        Thi = g_W2Thi + (size_t)c * Ee * Hh;
        Tlo = g_W2Tlo + (size_t)c * Ee * Hh;
    }
    int kb = blockIdx.x * 32, nb = blockIdx.y * 32;
    if (kb >= K || nb >= N) return;
    __shared__ float t[32][33];
    int tx = threadIdx.x, ty = threadIdx.y;
    for (int i = ty; i < 32; i += 8)
        t[i][tx] = W[(size_t)(kb + i) * N + nb + tx];
    __syncthreads();
    for (int i = ty; i < 32; i += 8) {
        float v = t[tx][i];
        __half hi = __float2half_rn(v);
        float lo = v - __half2float(hi);
        Thi[(size_t)(nb + i) * K + kb + tx] = hi;
        Tlo[(size_t)(nb + i) * K + kb + tx] = __float2half_rn(lo);
    }
}

// ---------------- fused CSR gather + inline input-BN + self-term + split -----
template <bool BOND>
__global__ __launch_bounds__(256) void gather_k(
    const float* __restrict__ Xin,
    const float* __restrict__ insums, const float* __restrict__ ing,
    const float* __restrict__ inb,
    const int* __restrict__ offs, const int* __restrict__ csrc,
    const int* __restrict__ catr, const float* __restrict__ bemb,
    const float* __restrict__ mask, const float* __restrict__ eps,
    __half* __restrict__ Ahi, __half* __restrict__ Alo) {
    __shared__ float s_sc[Ee], s_sh[Ee];
    for (int c = threadIdx.x; c < Ee; c += blockDim.x) {
        if (insums) {
            float mean = insums[c] * (1.f / Nn);
            float var = insums[Ee + c] * (1.f / Nn) - mean * mean;
            float s = ing[c] * rsqrtf(var + 1e-5f);
            s_sc[c] = s;
            s_sh[c] = inb[c] - mean * s;
        } else {
            s_sc[c] = 1.f;
            s_sh[c] = 0.f;
        }
    }
    __syncthreads();

    int node = blockIdx.x * 8 + (threadIdx.x >> 5);
    if (node >= Nn) return;
    int lane = threadIdx.x & 31;
    int c0 = lane * 8;
    float flo = insums ? 0.f : -3.4e38f;

    float4 sc0 = *(const float4*)&s_sc[c0], sc1 = *(const float4*)&s_sc[c0 + 4];
    float4 sh0 = *(const float4*)&s_sh[c0], sh1 = *(const float4*)&s_sh[c0 + 4];

    float a0 = 0.f, a1 = 0.f, a2 = 0.f, a3 = 0.f, a4 = 0.f, a5 = 0.f, a6 = 0.f, a7 = 0.f;
    int e0 = __ldg(&offs[node]), e1 = __ldg(&offs[node + 1]);
    for (int e = e0; e < e1; e++) {
        int s = __ldg(&csrc[e]);
        const float4* xr = (const float4*)&Xin[(size_t)s * Ee + c0];
        float4 x0 = __ldg(xr), x1 = __ldg(xr + 1);
        float v0 = fmaxf(fmaf(x0.x, sc0.x, sh0.x), flo);
        float v1 = fmaxf(fmaf(x0.y, sc0.y, sh0.y), flo);
        float v2 = fmaxf(fmaf(x0.z, sc0.z, sh0.z), flo);
        float v3 = fmaxf(fmaf(x0.w, sc0.w, sh0.w), flo);
        float v4 = fmaxf(fmaf(x1.x, sc1.x, sh1.x), flo);
        float v5 = fmaxf(fmaf(x1.y, sc1.y, sh1.y), flo);
        float v6 = fmaxf(fmaf(x1.z, sc1.z, sh1.z), flo);
        float v7 = fmaxf(fmaf(x1.w, sc1.w, sh1.w), flo);
        if (BOND) {
            int mt = __ldg(&catr[e]);
            const float4* b0 = (const float4*)&bemb[(size_t)(mt & 7) * Ee + c0];
            const float4* b1 = (const float4*)&bemb[(size_t)(8 + ((mt >> 3) & 7)) * Ee + c0];
            const float4* b2 = (const float4*)&bemb[(size_t)(16 + ((mt >> 6) & 7)) * Ee + c0];
            float4 p0 = __ldg(b0), p1 = __ldg(b0 + 1);
            float4 q0 = __ldg(b1), q1 = __ldg(b1 + 1);
            float4 r0 = __ldg(b2), r1 = __ldg(b2 + 1);
            v0 += p0.x + q0.x + r0.x; v1 += p0.y + q0.y + r0.y;
            v2 += p0.z + q0.z + r0.z; v3 += p0.w + q0.w + r0.w;
            v4 += p1.x + q1.x + r1.x; v5 += p1.y + q1.y + r1.y;
            v6 += p1.z + q1.z + r1.z; v7 += p1.w + q1.w + r1.w;
        }
        a0 += fmaxf(v0, 0.f); a1 += fmaxf(v1, 0.f);
        a2 += fmaxf(v2, 0.f); a3 += fmaxf(v3, 0.f);
        a4 += fmaxf(v4, 0.f); a5 += fmaxf(v5, 0.f);
        a6 += fmaxf(v6, 0.f); a7 += fmaxf(v7, 0.f);
    }
    const float4* xr = (const float4*)&Xin[(size_t)node * Ee + c0];
    float4 x0 = __ldg(xr), x1 = __ldg(xr + 1);
    float s0 = fmaxf(fmaf(x0.x, sc0.x, sh0.x), flo);
    float s1 = fmaxf(fmaf(x0.y, sc0.y, sh0.y), flo);
    float s2 = fmaxf(fmaf(x0.z, sc0.z, sh0.z), flo);
    float s3 = fmaxf(fmaf(x0.w, sc0.w, sh0.w), flo);
    float s4 = fmaxf(fmaf(x1.x, sc1.x, sh1.x), flo);
    float s5 = fmaxf(fmaf(x1.y, sc1.y, sh1.y), flo);
    float s6 = fmaxf(fmaf(x1.z, sc1.z, sh1.z), flo);
    float s7 = fmaxf(fmaf(x1.w, sc1.w, sh1.w), flo);
    float m = mask ? __ldg(&mask[node]) : 1.f;
    float ef = (1.f + __ldg(eps)) * m;
    float p0 = fmaf(ef, s0, a0), p1 = fmaf(ef, s1, a1);
    float p2 = fmaf(ef, s2, a2), p3 = fmaf(ef, s3, a3);
    float p4 = fmaf(ef, s4, a4), p5 = fmaf(ef, s5, a5);
    float p6 = fmaf(ef, s6, a6), p7 = fmaf(ef, s7, a7);
    uint4 hi, lo;
    {
        __half h0 = __float2half_rn(p0), h1 = __float2half_rn(p1);
        __half h2 = __float2half_rn(p2), h3 = __float2half_rn(p3);
        __half h4 = __float2half_rn(p4), h5 = __float2half_rn(p5);
        __half h6 = __float2half_rn(p6), h7 = __float2half_rn(p7);
        hi.x = (uint32_t)__half_as_ushort(h0) | ((uint32_t)__half_as_ushort(h1) << 16);
        hi.y = (uint32_t)__half_as_ushort(h2) | ((uint32_t)__half_as_ushort(h3) << 16);
        hi.z = (uint32_t)__half_as_ushort(h4) | ((uint32_t)__half_as_ushort(h5) << 16);
        hi.w = (uint32_t)__half_as_ushort(h6) | ((uint32_t)__half_as_ushort(h7) << 16);
        lo.x = pack2h(p0 - __half2float(h0), p1 - __half2float(h1));
        lo.y = pack2h(p2 - __half2float(h2), p3 - __half2float(h3));
        lo.z = pack2h(p4 - __half2float(h4), p5 - __half2float(h5));
        lo.w = pack2h(p6 - __half2float(h6), p7 - __half2float(h7));
    }
    *(uint4*)&Ahi[(size_t)node * Ee + c0] = hi;
    *(uint4*)&Alo[(size_t)node * Ee + c0] = lo;
}

// ---------------- mma.sync fp16x3 GEMM, 64x128 tile, 2 CTA/SM ----------------
// TRANSFORM_A: A = raw t1 pair; per K-tile, transform the A smem tile in place
// (BN+relu+resplit, once per element; padded rows zeroed) before ldmatrix.
#define SA_HI 0
#define SA_LO 8192
#define SB_HI 16384
#define SB_LO 32768
#define STAGE_BYTES 49152
#define GEMM_SMEM_BASE 98304

template <bool TRANSFORM_A, bool HALF_OUT>
__global__ __launch_bounds__(256, 2) void mma_gemm_k(
    const __half* __restrict__ Ahi, const __half* __restrict__ Alo,
    const __half* __restrict__ Bhi, const __half* __restrict__ Blo,
    float* __restrict__ C, __half* __restrict__ Chi, __half* __restrict__ Clo,
    float* __restrict__ sums,
    const float* __restrict__ tsums, const float* __restrict__ tg,
    const float* __restrict__ tb,
    int Mr, int K, int Nc) {
    extern __shared__ char smem[];
    const uint32_t sb = smem_u32(smem);
    const int tid = threadIdx.x;
    const int lane = tid & 31, wid = tid >> 5;
    const int wm = (wid >> 2) * 32;
    const int wn = (wid & 3) * 32;
    const int m0 = blockIdx.y * 64;
    const int n0 = blockIdx.x * 128;
    const int nkt = K >> 6;

    float* s_scale = (float*)(smem + GEMM_SMEM_BASE);
    float* s_shift = s_scale + (TRANSFORM_A ? K : 0);
    if (TRANSFORM_A) {
        for (int c = tid; c < K; c += 256) {
            float mean = tsums[c] * (1.f / Nn);
            float var = tsums[K + c] * (1.f / Nn) - mean * mean;
            float s = tg[c] * rsqrtf(var + 1e-5f);
            s_scale[c] = s;
            s_shift[c] = tb[c] - mean * s;
        }
    }

    float acc[2][4][4];
#pragma unroll
    for (int a = 0; a < 2; a++)
#pragma unroll
        for (int b = 0; b < 4; b++)
#pragma unroll
            for (int c = 0; c < 4; c++) acc[a][b][c] = 0.f;

    const int brow = tid >> 1, bhalf = tid & 1;
    const int arow = tid >> 2, aq = tid & 3;
    const bool arow_ok = (m0 + arow) < Mr;
    const int arow_cl = arow_ok ? (m0 + arow) : 0;
    const char* pAhi = (const char*)(Ahi + (size_t)arow_cl * K);
    const char* pAlo = (const char*)(Alo + (size_t)arow_cl * K);
    const char* pBhi = (const char*)(Bhi + (size_t)(n0 + brow) * K + bhalf * 32);
    const char* pBlo = (const char*)(Blo + (size_t)(n0 + brow) * K + bhalf * 32);
    const int asz = arow_ok ? 16 : 0;

    auto issue = [&](int stage, int kt) {
        const size_t gk = (size_t)kt * 128;
        const uint32_t st = sb + stage * STAGE_BYTES;
#pragma unroll
        for (int j = 0; j < 2; j++) {
            uint32_t so = SW128((uint32_t)(arow * 128 + aq * 32 + j * 16));
            CP_ASYNC16(st + SA_HI + so, pAhi + gk + aq * 32 + j * 16, asz);
            CP_ASYNC16(st + SA_LO + so, pAlo + gk + aq * 32 + j * 16, asz);
        }
#pragma unroll
        for (int j = 0; j < 4; j++) {
            uint32_t so = SW128((uint32_t)(brow * 128 + bhalf * 64 + j * 16));
            CP_ASYNC16(st + SB_HI + so, pBhi + gk + j * 16, 16);
            CP_ASYNC16(st + SB_LO + so, pBlo + gk + j * 16, 16);
        }
    };

    issue(0, 0);
    CP_COMMIT();

    for (int kt = 0; kt < nkt; kt++) {
        const int buf = kt & 1;
        if (kt + 1 < nkt) {
            issue(buf ^ 1, kt + 1);
            CP_COMMIT();
            CP_WAIT1();
        } else {
            CP_WAIT0();
        }
        __syncthreads();

        char* stp = smem + buf * STAGE_BYTES;
        const uint32_t st = sb + buf * STAGE_BYTES;

        if (TRANSFORM_A) {
            // in-smem transform of A tile: thread -> row tid>>2, 16 cols at aq*16
            const int trow = tid >> 2, tq = tid & 3;
            const float rmask = ((m0 + trow) < Mr) ? 1.f : 0.f;
            const uint32_t rbase = (uint32_t)trow * 128;
#pragma unroll
            for (int j = 0; j < 8; j++) {
                int colh = tq * 16 + j * 2;  // column pair
                uint32_t so = SW128(rbase + (uint32_t)colh * 2);
                uint32_t vh = *(uint32_t*)(stp + SA_HI + so);
                uint32_t vl = *(uint32_t*)(stp + SA_LO + so);
                float2 hv = __half22float2(*(__half2*)&vh);
                float2 lv = __half22float2(*(__half2*)&vl);
                int gc = kt * 64 + colh;
                float y0 = fmaxf(fmaf(hv.x + lv.x, s_scale[gc], s_shift[gc]), 0.f) * rmask;
                float y1 = fmaxf(fmaf(hv.y + lv.y, s_scale[gc + 1], s_shift[gc + 1]), 0.f) * rmask;
                __half2 nh = __floats2half2_rn(y0, y1);
                float2 nhf = __half22float2(nh);
                __half2 nl = __floats2half2_rn(y0 - nhf.x, y1 - nhf.y);
                *(uint32_t*)(stp + SA_HI + so) = *(uint32_t*)&nh;
                *(uint32_t*)(stp + SA_LO + so) = *(uint32_t*)&nl;
            }
            __syncthreads();
        }

#pragma unroll
        for (int ks = 0; ks < 4; ks++) {
            const int k0 = ks * 16;
            const uint32_t ar = wm + (lane & 15);
            const uint32_t ac = k0 + ((lane >> 4) << 3);
            const uint32_t br = wn + (lane & 7) + ((lane >> 4) << 3);
            const uint32_t bc = k0 + (((lane >> 3) & 1) << 3);
            uint32_t bhi[8], blo[8], af[8];
#pragma unroll
            for (int nb = 0; nb < 2; nb++) {
                uint32_t off = SW128((br + nb * 16) * 128 + bc * 2);
                LDSM_X4(bhi[nb * 4 + 0], bhi[nb * 4 + 1], bhi[nb * 4 + 2], bhi[nb * 4 + 3],
                        st + SB_HI + off);
                LDSM_X4(blo[nb * 4 + 0], blo[nb * 4 + 1], blo[nb * 4 + 2], blo[nb * 4 + 3],
                        st + SB_LO + off);
            }
#pragma unroll
            for (int mf = 0; mf < 2; mf++) {
                uint32_t off = SW128((ar + mf * 16) * 128 + ac * 2);
                LDSM_X4(af[mf * 4 + 0], af[mf * 4 + 1], af[mf * 4 + 2], af[mf * 4 + 3],
                        st + SA_HI + off);
            }
#pragma unroll
            for (int mf = 0; mf < 2; mf++)
#pragma unroll
                for (int nf = 0; nf < 4; nf++) {
                    int bi = (nf >> 1) * 4 + (nf & 1) * 2;
                    MMA16816(acc[mf][nf], af[mf * 4], af[mf * 4 + 1], af[mf * 4 + 2],
                             af[mf * 4 + 3], bhi[bi], bhi[bi + 1]);
                    MMA16816(acc[mf][nf], af[mf * 4], af[mf * 4 + 1], af[mf * 4 + 2],
                             af[mf * 4 + 3], blo[bi], blo[bi + 1]);
                }
#pragma unroll
            for (int mf = 0; mf < 2; mf++) {
                uint32_t off = SW128((ar + mf * 16) * 128 + ac * 2);
                LDSM_X4(af[mf * 4 + 0], af[mf * 4 + 1], af[mf * 4 + 2], af[mf * 4 + 3],
                        st + SA_LO + off);
            }
#pragma unroll
            for (int mf = 0; mf < 2; mf++)
#pragma unroll
                for (int nf = 0; nf < 4; nf++) {
                    int bi = (nf >> 1) * 4 + (nf & 1) * 2;
                    MMA16816(acc[mf][nf], af[mf * 4], af[mf * 4 + 1], af[mf * 4 + 2],
                             af[mf * 4 + 3], bhi[bi], bhi[bi + 1]);
                }
        }
        __syncthreads();
    }

    // epilogue
#pragma unroll
    for (int mf = 0; mf < 2; mf++) {
        int r = m0 + wm + mf * 16 + (lane >> 2);
#pragma unroll
        for (int nf = 0; nf < 4; nf++) {
            int col = n0 + wn + nf * 8 + (lane & 3) * 2;
            float a0 = acc[mf][nf][0], a1 = acc[mf][nf][1];
            float a2 = acc[mf][nf][2], a3 = acc[mf][nf][3];
            if (HALF_OUT) {
                if (r < Mr) {
                    __half h0 = __float2half_rn(a0), h1 = __float2half_rn(a1);
                    *(uint32_t*)&Chi[(size_t)r * Nc + col] =
                        (uint32_t)__half_as_ushort(h0) | ((uint32_t)__half_as_ushort(h1) << 16);
                    *(uint32_t*)&Clo[(size_t)r * Nc + col] =
                        pack2h(a0 - __half2float(h0), a1 - __half2float(h1));
                }
                if (r + 8 < Mr) {
                    __half h2 = __float2half_rn(a2), h3 = __float2half_rn(a3);
                    *(uint32_t*)&Chi[(size_t)(r + 8) * Nc + col] =
                        (uint32_t)__half_as_ushort(h2) | ((uint32_t)__half_as_ushort(h3) << 16);
                    *(uint32_t*)&Clo[(size_t)(r + 8) * Nc + col] =
                        pack2h(a2 - __half2float(h2), a3 - __half2float(h3));
                }
            } else {
                if (r < Mr)
                    *(float2*)&C[(size_t)r * Nc + col] = make_float2(a0, a1);
                if (r + 8 < Mr)
                    *(float2*)&C[(size_t)(r + 8) * Nc + col] = make_float2(a2, a3);
            }
        }
    }

    // fused BN column stats (padded rows contribute exactly 0)
#pragma unroll
    for (int nf = 0; nf < 4; nf++) {
        float s0 = 0.f, s1 = 0.f, q0 = 0.f, q1 = 0.f;
#pragma unroll
        for (int mf = 0; mf < 2; mf++) {
            float a0 = acc[mf][nf][0], a1 = acc[mf][nf][1];
            float a2 = acc[mf][nf][2], a3 = acc[mf][nf][3];
            s0 += a0 + a2; s1 += a1 + a3;
            q0 += a0 * a0 + a2 * a2; q1 += a1 * a1 + a3 * a3;
        }
#pragma unroll
        for (int off = 4; off < 32; off <<= 1) {
            s0 += __shfl_xor_sync(0xffffffff, s0, off);
            s1 += __shfl_xor_sync(0xffffffff, s1, off);
            q0 += __shfl_xor_sync(0xffffffff, q0, off);
            q1 += __shfl_xor_sync(0xffffffff, q1, off);
        }
        if (lane < 4) {
            int c = n0 + wn + nf * 8 + lane * 2;
            atomicAdd(&sums[c], s0);
            atomicAdd(&sums[c + 1], s1);
            atomicAdd(&sums[Nc + c], q0);
            atomicAdd(&sums[Nc + c + 1], q1);
        }
    }
}

// ---------------- final BN apply (inline scale/shift) ------------------------
__global__ void bn_apply_final_k(const float* __restrict__ X,
                                 const float* __restrict__ sums,
                                 const float* __restrict__ g,
                                 const float* __restrict__ b,
                                 float* __restrict__ Y) {
    __shared__ float s_sc[Ee], s_sh[Ee];
    for (int c = threadIdx.x; c < Ee; c += blockDim.x) {
        float mean = sums[c] * (1.f / Nn);
        float var = sums[Ee + c] * (1.f / Nn) - mean * mean;
        float s = g[c] * rsqrtf(var + 1e-5f);
        s_sc[c] = s;
        s_sh[c] = b[c] - mean * s;
    }
    __syncthreads();
    int i = blockIdx.x * blockDim.x + threadIdx.x;
    if (i >= Nn * Ee / 4) return;
    int c = (i & 63) * 4;
    float4 v = ((const float4*)X)[i];
    v.x = fmaf(v.x, s_sc[c + 0], s_sh[c + 0]);
    v.y = fmaf(v.y, s_sc[c + 1], s_sh[c + 1]);
    v.z = fmaf(v.z, s_sc[c + 2], s_sh[c + 2]);
    v.w = fmaf(v.w, s_sc[c + 3], s_sh[c + 3]);
    ((float4*)Y)[i] = v;
}

// ---------------- host orchestration ----------------------------------------
struct Scratch {
    float *h, *hB, *sumsH, *sumsE, *mask;
    __half *A1hi, *A1lo, *t1hi, *t1lo;
    __half *W1Thi, *W1Tlo, *W2Thi, *W2Tlo;
    int *offs_b, *offs_l, *offs_r, *src_b, *atr_b, *src_l, *src_r;
};

extern "C" void kernel_launch(void* const* d_in, const int* in_sizes, int n_in,
                              void* d_out, int out_size) {
    const int* x       = (const int*)d_in[0];
    const int* ei      = (const int*)d_in[1];
    const int* ea      = (const int*)d_in[2];
    const int* xei     = (const int*)d_in[3];
    const void* mask_raw = d_in[4];
    const float* atom_emb = (const float*)d_in[5];
    const float* bond_emb = (const float*)d_in[6];
    const float* eps_m = (const float*)d_in[7];
    const float* W1_m  = (const float*)d_in[8];
    const float* g1_m  = (const float*)d_in[10];
    const float* be1_m = (const float*)d_in[11];
    const float* W2_m  = (const float*)d_in[12];
    const float* bn_g_m = (const float*)d_in[14];
    const float* bn_b_m = (const float*)d_in[15];
    const float* eps_e = (const float*)d_in[16];
    const float* W1_e  = (const float*)d_in[17];
    const float* g1_e  = (const float*)d_in[18];
    const float* be1_e = (const float*)d_in[19];
    const float* W2_e  = (const float*)d_in[20];
    const float* bn_g_e = (const float*)d_in[21];
    const float* bn_b_e = (const float*)d_in[22];

    const int M  = in_sizes[1] / 2;
    const int MX = in_sizes[3] / 2;

    const int SM1 = GEMM_SMEM_BASE;                // gemm1: no transform
    const int SM2 = GEMM_SMEM_BASE + 2 * Hh * 4;   // gemm2: + scale/shift[512]
    cudaFuncSetAttribute(mma_gemm_k<false, true>,
                         cudaFuncAttributeMaxDynamicSharedMemorySize, SM1);
    cudaFuncSetAttribute(mma_gemm_k<true, false>,
                         cudaFuncAttributeMaxDynamicSharedMemorySize, SM2);

    Scratch S;
    cudaGetSymbolAddress((void**)&S.h, g_h);
    cudaGetSymbolAddress((void**)&S.hB, g_hB);
    cudaGetSymbolAddress((void**)&S.sumsH, g_sumsH);
    cudaGetSymbolAddress((void**)&S.sumsE, g_sumsE);
    cudaGetSymbolAddress((void**)&S.mask, g_mask);
    cudaGetSymbolAddress((void**)&S.A1hi, g_A1hi);
    cudaGetSymbolAddress((void**)&S.A1lo, g_A1lo);
    cudaGetSymbolAddress((void**)&S.t1hi, g_t1hi);
    cudaGetSymbolAddress((void**)&S.t1lo, g_t1lo);
    cudaGetSymbolAddress((void**)&S.W1Thi, g_W1Thi);
    cudaGetSymbolAddress((void**)&S.W1Tlo, g_W1Tlo);
    cudaGetSymbolAddress((void**)&S.W2Thi, g_W2Thi);
    cudaGetSymbolAddress((void**)&S.W2Tlo, g_W2Tlo);
    cudaGetSymbolAddress((void**)&S.offs_b, g_offs_b);
    cudaGetSymbolAddress((void**)&S.offs_l, g_offs_l);
    cudaGetSymbolAddress((void**)&S.offs_r, g_offs_r);
    cudaGetSymbolAddress((void**)&S.src_b, g_src_b);
    cudaGetSymbolAddress((void**)&S.atr_b, g_atr_b);
    cudaGetSymbolAddress((void**)&S.src_l, g_src_l);
    cudaGetSymbolAddress((void**)&S.src_r, g_src_r);

    const int TOT = M + 2 * MX;

    detect_mask_k<<<1, 256>>>(mask_raw);
    setup_k<<<79, 256>>>(mask_raw);
    atom_encode_k<<<Nn, 64>>>(x, atom_emb, S.h);
    hist_all_k<<<(TOT + 255) / 256, 256>>>(ei, xei, M, MX);
    scan_all_k<<<3, 1024>>>();
    fill_all_k<<<(TOT + 255) / 256, 256>>>(ei, xei, ea, M, MX);
    wsplit_all_k<<<dim3(16, 16, 2 * NCONV), dim3(32, 8)>>>(W1_m, W1_e, W2_m, W2_e);

    const float* prev_sums = nullptr;
    const float* prev_g = nullptr;
    const float* prev_b = nullptr;

    dim3 g1d(Hh / 128, (Nn + 63) / 64);
    dim3 g2d(Ee / 128, (Nn + 63) / 64);

    for (int l = 0; l < Ll; l++) {
        for (int j = 0; j < 3; j++) {
            int c = l * 3 + j;
            const float* Xin = (c == 0) ? S.h : S.hB;
            const float* eps;
            const float* g1;
            const float* be1;
            const float* bng;
            const float* bnb;
            const float* mask = nullptr;
            const int* offs;
            const int* csrc;
            const int* catr = nullptr;
            if (j == 0) {
                eps = eps_m + l;
                g1 = g1_m + (size_t)l * Hh;  be1 = be1_m + (size_t)l * Hh;
                bng = bn_g_m + (size_t)l * Ee; bnb = bn_b_m + (size_t)l * Ee;
                offs = S.offs_b; csrc = S.src_b; catr = S.atr_b;
            } else {
                int s = l * 2 + (j - 1);
                eps = eps_e + s;
                g1 = g1_e + (size_t)s * Hh;  be1 = be1_e + (size_t)s * Hh;
                bng = bn_g_e + (size_t)s * Ee; bnb = bn_b_e + (size_t)s * Ee;
                offs = (j == 1) ? S.offs_l : S.offs_r;
                csrc = (j == 1) ? S.src_l : S.src_r;
                mask = S.mask;
            }
            float* sumsH_c = S.sumsH + (size_t)c * 2 * Hh;
            float* sumsE_c = S.sumsE + (size_t)c * 2 * Ee;

            if (catr)
                gather_k<true><<<(Nn + 7) / 8, 256>>>(Xin, prev_sums, prev_g, prev_b,
                                                      offs, csrc, catr, bond_emb,
                                                      mask, eps, S.A1hi, S.A1lo);
            else
                gather_k<false><<<(Nn + 7) / 8, 256>>>(Xin, prev_sums, prev_g, prev_b,
                                                       offs, csrc, nullptr, nullptr,
                                                       mask, eps, S.A1hi, S.A1lo);

            mma_gemm_k<false, true><<<g1d, 256, SM1>>>(
                S.A1hi, S.A1lo,
                S.W1Thi + (size_t)c * Hh * Ee, S.W1Tlo + (size_t)c * Hh * Ee,
                nullptr, S.t1hi, S.t1lo, sumsH_c,
                nullptr, nullptr, nullptr, Nn, Ee, Hh);

            mma_gemm_k<true, false><<<g2d, 256, SM2>>>(
                S.t1hi, S.t1lo,
                S.W2Thi + (size_t)c * Ee * Hh, S.W2Tlo + (size_t)c * Ee * Hh,
                S.hB, nullptr, nullptr, sumsE_c,
                sumsH_c, g1, be1, Nn, Hh, Ee);

            prev_sums = sumsE_c;
            prev_g = bng;
            prev_b = bnb;
        }
    }

    bn_apply_final_k<<<(Nn * Ee / 4 + 255) / 256, 256>>>(S.hB, prev_sums, prev_g, prev_b,
                                                         (float*)d_out);
}

// round 13
// speedup vs baseline: 1.0519x; 1.0519x over previous
#include <cuda_runtime.h>
#include <cuda_fp16.h>
#include <cstddef>
#include <cstdint>

#define Nn 20000
#define Ee 256
#define Hh 512
#define Ll 5
#define NCONV 15
#define MB_CAP 320000
#define MX_CAP 160000

// ---------------- scratch (device globals; no allocations allowed) ----------
__device__ float g_h[Nn * Ee];
__device__ float g_hB[Nn * Ee];
__device__ float g_sumsH[NCONV * 2 * Hh];
__device__ float g_sumsE[NCONV * 2 * Ee];
__device__ float g_mask[Nn];
__device__ int   g_mask_dtype;

__device__ __half g_A1hi[Nn * Ee];
__device__ __half g_A1lo[Nn * Ee];
__device__ __half g_t1hi[Nn * Hh];
__device__ __half g_t1lo[Nn * Hh];
__device__ __half g_A2hi[Nn * Hh];
__device__ __half g_A2lo[Nn * Hh];
__device__ __half g_W1Thi[NCONV * Hh * Ee];
__device__ __half g_W1Tlo[NCONV * Hh * Ee];
__device__ __half g_W2Thi[NCONV * Ee * Hh];
__device__ __half g_W2Tlo[NCONV * Ee * Hh];

__device__ int g_deg[3 * Nn];
__device__ int g_cur[3 * Nn];
__device__ int g_offs_b[Nn + 1], g_offs_l[Nn + 1], g_offs_r[Nn + 1];
__device__ int g_src_b[MB_CAP];
__device__ int g_atr_b[MB_CAP];
__device__ int g_src_l[MX_CAP];
__device__ int g_src_r[MX_CAP];

// ---------------- helpers ----------------------------------------------------
__device__ __forceinline__ uint32_t smem_u32(const void* p) {
    uint32_t a;
    asm("{ .reg .u64 t; cvta.to.shared.u64 t, %1; cvt.u32.u64 %0, t; }" : "=r"(a) : "l"(p));
    return a;
}
#define SW128(off) ((off) ^ (((off) >> 3) & 0x70))

#define LDSM_X4(r0, r1, r2, r3, addr) \
    asm volatile("ldmatrix.sync.aligned.m8n8.x4.shared.b16 {%0,%1,%2,%3}, [%4];" \
                 : "=r"(r0), "=r"(r1), "=r"(r2), "=r"(r3) : "r"(addr))

#define MMA16816(d, a0, a1, a2, a3, b0, b1) \
    asm volatile("mma.sync.aligned.m16n8k16.row.col.f32.f16.f16.f32 " \
                 "{%0,%1,%2,%3}, {%4,%5,%6,%7}, {%8,%9}, {%0,%1,%2,%3};" \
                 : "+f"((d)[0]), "+f"((d)[1]), "+f"((d)[2]), "+f"((d)[3]) \
                 : "r"(a0), "r"(a1), "r"(a2), "r"(a3), "r"(b0), "r"(b1))

#define CP_ASYNC16(dst, src, sz) \
    asm volatile("cp.async.cg.shared.global [%0], [%1], 16, %2;" \
                 :: "r"(dst), "l"(src), "r"(sz))
#define CP_COMMIT() asm volatile("cp.async.commit_group;" ::: "memory")
#define CP_WAIT0() asm volatile("cp.async.wait_group 0;" ::: "memory")
#define CP_WAIT1() asm volatile("cp.async.wait_group 1;" ::: "memory")

__device__ __forceinline__ uint32_t pack2h(float a, float b) {
    __half ha = __float2half_rn(a), hb = __float2half_rn(b);
    return (uint32_t)__half_as_ushort(ha) | ((uint32_t)__half_as_ushort(hb) << 16);
}

// ---------------- mask dtype detection ---------------------------------------
__global__ void detect_mask_k(const void* mask) {
    __shared__ int not_i32, not_f32;
    if (threadIdx.x == 0) { not_i32 = 0; not_f32 = 0; }
    __syncthreads();
    const unsigned* w = (const unsigned*)mask;
    int bad_i = 0, bad_f = 0;
    for (int i = threadIdx.x; i < Nn / 4; i += blockDim.x) {
        unsigned v = w[i];
        if (v > 1u) bad_i = 1;
        if (v != 0u && v != 0x3F800000u) bad_f = 1;
    }
    if (bad_i) atomicOr(&not_i32, 1);
    if (bad_f) atomicOr(&not_f32, 1);
    __syncthreads();
    if (threadIdx.x == 0) {
        if (!not_i32) g_mask_dtype = 0;
        else if (!not_f32) g_mask_dtype = 1;
        else g_mask_dtype = 2;
    }
}

__global__ void setup_k(const void* mask) {
    int i = blockIdx.x * blockDim.x + threadIdx.x;
    int stride = gridDim.x * blockDim.x;
    int dt = g_mask_dtype;
    for (int n = i; n < Nn; n += stride) {
        float m;
        if (dt == 0)      m = (((const int*)mask)[n] != 0) ? 1.f : 0.f;
        else if (dt == 1) m = (((const float*)mask)[n] != 0.f) ? 1.f : 0.f;
        else              m = (((const unsigned char*)mask)[n] != 0) ? 1.f : 0.f;
        g_mask[n] = m;
    }
    for (int n = i; n < 3 * Nn; n += stride) g_deg[n] = 0;
    for (int n = i; n < NCONV * 2 * Hh; n += stride) g_sumsH[n] = 0.f;
    for (int n = i; n < NCONV * 2 * Ee; n += stride) g_sumsE[n] = 0.f;
}

// ---------------- atom encoder ------------------------------------------------
__global__ void atom_encode_k(const int* __restrict__ x,
                              const float* __restrict__ emb,
                              float* __restrict__ h) {
    int n = blockIdx.x;
    int t = threadIdx.x;
    float4 acc = make_float4(0.f, 0.f, 0.f, 0.f);
#pragma unroll
    for (int f = 0; f < 9; f++) {
        int idx = __ldg(&x[n * 9 + f]);
        const float4* row = (const float4*)&emb[((size_t)(f * 128 + idx)) * Ee];
        float4 v = row[t];
        acc.x += v.x; acc.y += v.y; acc.z += v.z; acc.w += v.w;
    }
    ((float4*)h)[(size_t)n * (Ee / 4) + t] = acc;
}

// ---------------- CSR build (fused across 3 orientations) --------------------
__global__ void hist_all_k(const int* __restrict__ ei, const int* __restrict__ xei,
                           int M, int MX) {
    int e = blockIdx.x * blockDim.x + threadIdx.x;
    if (e < M) atomicAdd(&g_deg[ei[M + e]], 1);
    else if (e < M + MX) atomicAdd(&g_deg[Nn + xei[MX + (e - M)]], 1);
    else if (e < M + 2 * MX) atomicAdd(&g_deg[2 * Nn + xei[e - M - MX]], 1);
}

__global__ void scan_all_k() {
    int which = blockIdx.x;
    const int* deg = g_deg + which * Nn;
    int* cur = g_cur + which * Nn;
    int* offs = (which == 0) ? g_offs_b : (which == 1) ? g_offs_l : g_offs_r;
    __shared__ int ssum[1024];
    int t = threadIdx.x;
    const int PER = (Nn + 1023) / 1024;  // 20
    int loc[20];
    int s = 0;
#pragma unroll
    for (int i = 0; i < PER; i++) {
        int idx = t * PER + i;
        int v = (idx < Nn) ? deg[idx] : 0;
        loc[i] = s;
        s += v;
    }
    ssum[t] = s;
    __syncthreads();
    for (int off = 1; off < 1024; off <<= 1) {
        int v = (t >= off) ? ssum[t - off] : 0;
        __syncthreads();
        ssum[t] += v;
        __syncthreads();
    }
    int pre = (t > 0) ? ssum[t - 1] : 0;
#pragma unroll
    for (int i = 0; i < PER; i++) {
        int idx = t * PER + i;
        if (idx < Nn) {
            offs[idx] = pre + loc[i];
            cur[idx] = pre + loc[i];
        }
    }
    if (t == 1023) offs[Nn] = ssum[1023];
}

__global__ void fill_all_k(const int* __restrict__ ei, const int* __restrict__ xei,
                           const int* __restrict__ ea, int M, int MX) {
    int e = blockIdx.x * blockDim.x + threadIdx.x;
    if (e < M) {
        int p = atomicAdd(&g_cur[ei[M + e]], 1);
        if (p < MB_CAP) {
            g_src_b[p] = ei[e];
            g_atr_b[p] = ea[e * 3] | (ea[e * 3 + 1] << 3) | (ea[e * 3 + 2] << 6);
        }
    } else if (e < M + MX) {
        int j = e - M;
        int p = atomicAdd(&g_cur[Nn + xei[MX + j]], 1);
        if (p < MX_CAP) g_src_l[p] = xei[j];
    } else if (e < M + 2 * MX) {
        int j = e - M - MX;
        int p = atomicAdd(&g_cur[2 * Nn + xei[j]], 1);
        if (p < MX_CAP) g_src_r[p] = xei[MX + j];
    }
}

// ---------------- merged weight transpose + fp16 split ------------------------
__global__ void wsplit_all_k(const float* __restrict__ W1m, const float* __restrict__ W1e,
                             const float* __restrict__ W2m, const float* __restrict__ W2e) {
    int z = blockIdx.z;
    int which = z / NCONV;
    int c = z % NCONV;
    int l = c / 3, j = c % 3;
    const float* W;
    __half *Thi, *Tlo;
    int K, N;
    if (which == 0) {
        K = Ee; N = Hh;
        W = j ? W1e + (size_t)(l * 2 + j - 1) * Ee * Hh : W1m + (size_t)l * Ee * Hh;
        Thi = g_W1Thi + (size_t)c * Hh * Ee;
        Tlo = g_W1Tlo + (size_t)c * Hh * Ee;
    } else {
        K = Hh; N = Ee;
        W = j ? W2e + (size_t)(l * 2 + j - 1) * Hh * Ee : W2m + (size_t)l * Hh * Ee;
        Thi = g_W2Thi + (size_t)c * Ee * Hh;
        Tlo = g_W2Tlo + (size_t)c * Ee * Hh;
    }
    int kb = blockIdx.x * 32, nb = blockIdx.y * 32;
    if (kb >= K || nb >= N) return;
    __shared__ float t[32][33];
    int tx = threadIdx.x, ty = threadIdx.y;
    for (int i = ty; i < 32; i += 8)
        t[i][tx] = W[(size_t)(kb + i) * N + nb + tx];
    __syncthreads();
    for (int i = ty; i < 32; i += 8) {
        float v = t[tx][i];
        __half hi = __float2half_rn(v);
        float lo = v - __half2float(hi);
        Thi[(size_t)(nb + i) * K + kb + tx] = hi;
        Tlo[(size_t)(nb + i) * K + kb + tx] = __float2half_rn(lo);
    }
}

// ---------------- fused CSR gather (edge loop unrolled x2) --------------------
template <bool BOND>
__global__ __launch_bounds__(256) void gather_k(
    const float* __restrict__ Xin,
    const float* __restrict__ insums, const float* __restrict__ ing,
    const float* __restrict__ inb,
    const int* __restrict__ offs, const int* __restrict__ csrc,
    const int* __restrict__ catr, const float* __restrict__ bemb,
    const float* __restrict__ mask, const float* __restrict__ eps,
    __half* __restrict__ Ahi, __half* __restrict__ Alo) {
    __shared__ float s_sc[Ee], s_sh[Ee];
    for (int c = threadIdx.x; c < Ee; c += blockDim.x) {
        if (insums) {
            float mean = insums[c] * (1.f / Nn);
            float var = insums[Ee + c] * (1.f / Nn) - mean * mean;
            float s = ing[c] * rsqrtf(var + 1e-5f);
            s_sc[c] = s;
            s_sh[c] = inb[c] - mean * s;
        } else {
            s_sc[c] = 1.f;
            s_sh[c] = 0.f;
        }
    }
    __syncthreads();

    int node = blockIdx.x * 8 + (threadIdx.x >> 5);
    if (node >= Nn) return;
    int lane = threadIdx.x & 31;
    int c0 = lane * 8;
    float flo = insums ? 0.f : -3.4e38f;

    float4 sc0 = *(const float4*)&s_sc[c0], sc1 = *(const float4*)&s_sc[c0 + 4];
    float4 sh0 = *(const float4*)&s_sh[c0], sh1 = *(const float4*)&s_sh[c0 + 4];

    float a0 = 0.f, a1 = 0.f, a2 = 0.f, a3 = 0.f, a4 = 0.f, a5 = 0.f, a6 = 0.f, a7 = 0.f;
    int e0 = __ldg(&offs[node]), e1 = __ldg(&offs[node + 1]);

    int e = e0;
    // unrolled-by-2 main loop: both edges' loads issued before any math
    for (; e + 2 <= e1; e += 2) {
        int sA = __ldg(&csrc[e]);
        int sB = __ldg(&csrc[e + 1]);
        const float4* xrA = (const float4*)&Xin[(size_t)sA * Ee + c0];
        const float4* xrB = (const float4*)&Xin[(size_t)sB * Ee + c0];
        float4 xA0 = __ldg(xrA), xA1 = __ldg(xrA + 1);
        float4 xB0 = __ldg(xrB), xB1 = __ldg(xrB + 1);
        float4 bA0, bA1, bB0, bB1;
        if (BOND) {
            int mtA = __ldg(&catr[e]);
            int mtB = __ldg(&catr[e + 1]);
            const float4* pA0 = (const float4*)&bemb[(size_t)(mtA & 7) * Ee + c0];
            const float4* pA1 = (const float4*)&bemb[(size_t)(8 + ((mtA >> 3) & 7)) * Ee + c0];
            const float4* pA2 = (const float4*)&bemb[(size_t)(16 + ((mtA >> 6) & 7)) * Ee + c0];
            const float4* pB0 = (const float4*)&bemb[(size_t)(mtB & 7) * Ee + c0];
            const float4* pB1 = (const float4*)&bemb[(size_t)(8 + ((mtB >> 3) & 7)) * Ee + c0];
            const float4* pB2 = (const float4*)&bemb[(size_t)(16 + ((mtB >> 6) & 7)) * Ee + c0];
            float4 a00 = __ldg(pA0), a01 = __ldg(pA0 + 1);
            float4 a10 = __ldg(pA1), a11 = __ldg(pA1 + 1);
            float4 a20 = __ldg(pA2), a21 = __ldg(pA2 + 1);
            float4 b00 = __ldg(pB0), b01 = __ldg(pB0 + 1);
            float4 b10 = __ldg(pB1), b11 = __ldg(pB1 + 1);
            float4 b20 = __ldg(pB2), b21 = __ldg(pB2 + 1);
            bA0.x = a00.x + a10.x + a20.x; bA0.y = a00.y + a10.y + a20.y;
            bA0.z = a00.z + a10.z + a20.z; bA0.w = a00.w + a10.w + a20.w;
            bA1.x = a01.x + a11.x + a21.x; bA1.y = a01.y + a11.y + a21.y;
            bA1.z = a01.z + a11.z + a21.z; bA1.w = a01.w + a11.w + a21.w;
            bB0.x = b00.x + b10.x + b20.x; bB0.y = b00.y + b10.y + b20.y;
            bB0.z = b00.z + b10.z + b20.z; bB0.w = b00.w + b10.w + b20.w;
            bB1.x = b01.x + b11.x + b21.x; bB1.y = b01.y + b11.y + b21.y;
            bB1.z = b01.z + b11.z + b21.z; bB1.w = b01.w + b11.w + b21.w;
        }
        // edge A
        {
            float v0 = fmaxf(fmaf(xA0.x, sc0.x, sh0.x), flo);
            float v1 = fmaxf(fmaf(xA0.y, sc0.y, sh0.y), flo);
            float v2 = fmaxf(fmaf(xA0.z, sc0.z, sh0.z), flo);
            float v3 = fmaxf(fmaf(xA0.w, sc0.w, sh0.w), flo);
            float v4 = fmaxf(fmaf(xA1.x, sc1.x, sh1.x), flo);
            float v5 = fmaxf(fmaf(xA1.y, sc1.y, sh1.y), flo);
            float v6 = fmaxf(fmaf(xA1.z, sc1.z, sh1.z), flo);
            float v7 = fmaxf(fmaf(xA1.w, sc1.w, sh1.w), flo);
            if (BOND) {
                v0 += bA0.x; v1 += bA0.y; v2 += bA0.z; v3 += bA0.w;
                v4 += bA1.x; v5 += bA1.y; v6 += bA1.z; v7 += bA1.w;
            }
            a0 += fmaxf(v0, 0.f); a1 += fmaxf(v1, 0.f);
            a2 += fmaxf(v2, 0.f); a3 += fmaxf(v3, 0.f);
            a4 += fmaxf(v4, 0.f); a5 += fmaxf(v5, 0.f);
            a6 += fmaxf(v6, 0.f); a7 += fmaxf(v7, 0.f);
        }
        // edge B
        {
            float v0 = fmaxf(fmaf(xB0.x, sc0.x, sh0.x), flo);
            float v1 = fmaxf(fmaf(xB0.y, sc0.y, sh0.y), flo);
            float v2 = fmaxf(fmaf(xB0.z, sc0.z, sh0.z), flo);
            float v3 = fmaxf(fmaf(xB0.w, sc0.w, sh0.w), flo);
            float v4 = fmaxf(fmaf(xB1.x, sc1.x, sh1.x), flo);
            float v5 = fmaxf(fmaf(xB1.y, sc1.y, sh1.y), flo);
            float v6 = fmaxf(fmaf(xB1.z, sc1.z, sh1.z), flo);
            float v7 = fmaxf(fmaf(xB1.w, sc1.w, sh1.w), flo);
            if (BOND) {
                v0 += bB0.x; v1 += bB0.y; v2 += bB0.z; v3 += bB0.w;
                v4 += bB1.x; v5 += bB1.y; v6 += bB1.z; v7 += bB1.w;
            }
            a0 += fmaxf(v0, 0.f); a1 += fmaxf(v1, 0.f);
            a2 += fmaxf(v2, 0.f); a3 += fmaxf(v3, 0.f);
            a4 += fmaxf(v4, 0.f); a5 += fmaxf(v5, 0.f);
            a6 += fmaxf(v6, 0.f); a7 += fmaxf(v7, 0.f);
        }
    }
    // remainder edge
    for (; e < e1; e++) {
        int s = __ldg(&csrc[e]);
        const float4* xr = (const float4*)&Xin[(size_t)s * Ee + c0];
        float4 x0 = __ldg(xr), x1 = __ldg(xr + 1);
        float v0 = fmaxf(fmaf(x0.x, sc0.x, sh0.x), flo);
        float v1 = fmaxf(fmaf(x0.y, sc0.y, sh0.y), flo);
        float v2 = fmaxf(fmaf(x0.z, sc0.z, sh0.z), flo);
        float v3 = fmaxf(fmaf(x0.w, sc0.w, sh0.w), flo);
        float v4 = fmaxf(fmaf(x1.x, sc1.x, sh1.x), flo);
        float v5 = fmaxf(fmaf(x1.y, sc1.y, sh1.y), flo);
        float v6 = fmaxf(fmaf(x1.z, sc1.z, sh1.z), flo);
        float v7 = fmaxf(fmaf(x1.w, sc1.w, sh1.w), flo);
        if (BOND) {
            int mt = __ldg(&catr[e]);
            const float4* b0 = (const float4*)&bemb[(size_t)(mt & 7) * Ee + c0];
            const float4* b1 = (const float4*)&bemb[(size_t)(8 + ((mt >> 3) & 7)) * Ee + c0];
            const float4* b2 = (const float4*)&bemb[(size_t)(16 + ((mt >> 6) & 7)) * Ee + c0];
            float4 p0 = __ldg(b0), p1 = __ldg(b0 + 1);
            float4 q0 = __ldg(b1), q1 = __ldg(b1 + 1);
            float4 r0 = __ldg(b2), r1 = __ldg(b2 + 1);
            v0 += p0.x + q0.x + r0.x; v1 += p0.y + q0.y + r0.y;
            v2 += p0.z + q0.z + r0.z; v3 += p0.w + q0.w + r0.w;
            v4 += p1.x + q1.x + r1.x; v5 += p1.y + q1.y + r1.y;
            v6 += p1.z + q1.z + r1.z; v7 += p1.w + q1.w + r1.w;
        }
        a0 += fmaxf(v0, 0.f); a1 += fmaxf(v1, 0.f);
        a2 += fmaxf(v2, 0.f); a3 += fmaxf(v3, 0.f);
        a4 += fmaxf(v4, 0.f); a5 += fmaxf(v5, 0.f);
        a6 += fmaxf(v6, 0.f); a7 += fmaxf(v7, 0.f);
    }

    const float4* xr = (const float4*)&Xin[(size_t)node * Ee + c0];
    float4 x0 = __ldg(xr), x1 = __ldg(xr + 1);
    float s0 = fmaxf(fmaf(x0.x, sc0.x, sh0.x), flo);
    float s1 = fmaxf(fmaf(x0.y, sc0.y, sh0.y), flo);
    float s2 = fmaxf(fmaf(x0.z, sc0.z, sh0.z), flo);
    float s3 = fmaxf(fmaf(x0.w, sc0.w, sh0.w), flo);
    float s4 = fmaxf(fmaf(x1.x, sc1.x, sh1.x), flo);
    float s5 = fmaxf(fmaf(x1.y, sc1.y, sh1.y), flo);
    float s6 = fmaxf(fmaf(x1.z, sc1.z, sh1.z), flo);
    float s7 = fmaxf(fmaf(x1.w, sc1.w, sh1.w), flo);
    float m = mask ? __ldg(&mask[node]) : 1.f;
    float ef = (1.f + __ldg(eps)) * m;
    float p0 = fmaf(ef, s0, a0), p1 = fmaf(ef, s1, a1);
    float p2 = fmaf(ef, s2, a2), p3 = fmaf(ef, s3, a3);
    float p4 = fmaf(ef, s4, a4), p5 = fmaf(ef, s5, a5);
    float p6 = fmaf(ef, s6, a6), p7 = fmaf(ef, s7, a7);
    uint4 hi, lo;
    {
        __half h0 = __float2half_rn(p0), h1 = __float2half_rn(p1);
        __half h2 = __float2half_rn(p2), h3 = __float2half_rn(p3);
        __half h4 = __float2half_rn(p4), h5 = __float2half_rn(p5);
        __half h6 = __float2half_rn(p6), h7 = __float2half_rn(p7);
        hi.x = (uint32_t)__half_as_ushort(h0) | ((uint32_t)__half_as_ushort(h1) << 16);
        hi.y = (uint32_t)__half_as_ushort(h2) | ((uint32_t)__half_as_ushort(h3) << 16);
        hi.z = (uint32_t)__half_as_ushort(h4) | ((uint32_t)__half_as_ushort(h5) << 16);
        hi.w = (uint32_t)__half_as_ushort(h6) | ((uint32_t)__half_as_ushort(h7) << 16);
        lo.x = pack2h(p0 - __half2float(h0), p1 - __half2float(h1));
        lo.y = pack2h(p2 - __half2float(h2), p3 - __half2float(h3));
        lo.z = pack2h(p4 - __half2float(h4), p5 - __half2float(h5));
        lo.w = pack2h(p6 - __half2float(h6), p7 - __half2float(h7));
    }
    *(uint4*)&Ahi[(size_t)node * Ee + c0] = hi;
    *(uint4*)&Alo[(size_t)node * Ee + c0] = lo;
}

// ---------------- t1 pair -> inline BN finalize -> relu -> split -------------
__global__ void bnrelu_split_k(const __half* __restrict__ Thi, const __half* __restrict__ Tlo,
                               const float* __restrict__ sums,
                               const float* __restrict__ g,
                               const float* __restrict__ b,
                               __half* __restrict__ Ahi, __half* __restrict__ Alo) {
    __shared__ float s_sc[Hh], s_sh[Hh];
    for (int c = threadIdx.x; c < Hh; c += blockDim.x) {
        float mean = sums[c] * (1.f / Nn);
        float var = sums[Hh + c] * (1.f / Nn) - mean * mean;
        float s = g[c] * rsqrtf(var + 1e-5f);
        s_sc[c] = s;
        s_sh[c] = b[c] - mean * s;
    }
    __syncthreads();
    int i = blockIdx.x * blockDim.x + threadIdx.x;
    if (i >= Nn * Hh / 4) return;
    int c = (i & (Hh / 4 - 1)) * 4;
    uint2 vh = ((const uint2*)Thi)[i];
    uint2 vl = ((const uint2*)Tlo)[i];
    float2 h0 = __half22float2(*(__half2*)&vh.x);
    float2 h1 = __half22float2(*(__half2*)&vh.y);
    float2 l0 = __half22float2(*(__half2*)&vl.x);
    float2 l1 = __half22float2(*(__half2*)&vl.y);
    float x0 = h0.x + l0.x, x1 = h0.y + l0.y, x2 = h1.x + l1.x, x3 = h1.y + l1.y;
    x0 = fmaxf(fmaf(x0, s_sc[c + 0], s_sh[c + 0]), 0.f);
    x1 = fmaxf(fmaf(x1, s_sc[c + 1], s_sh[c + 1]), 0.f);
    x2 = fmaxf(fmaf(x2, s_sc[c + 2], s_sh[c + 2]), 0.f);
    x3 = fmaxf(fmaf(x3, s_sc[c + 3], s_sh[c + 3]), 0.f);
    __half q0 = __float2half_rn(x0), q1 = __float2half_rn(x1);
    __half q2 = __float2half_rn(x2), q3 = __float2half_rn(x3);
    uint2 hi, lo;
    hi.x = (uint32_t)__half_as_ushort(q0) | ((uint32_t)__half_as_ushort(q1) << 16);
    hi.y = (uint32_t)__half_as_ushort(q2) | ((uint32_t)__half_as_ushort(q3) << 16);
    lo.x = pack2h(x0 - __half2float(q0), x1 - __half2float(q1));
    lo.y = pack2h(x2 - __half2float(q2), x3 - __half2float(q3));
    ((uint2*)Ahi)[i] = hi;
    ((uint2*)Alo)[i] = lo;
}

// ---------------- mma.sync fp16x3 GEMM, 64x128 tile, 2 CTA/SM ----------------
#define SA_HI 0
#define SA_LO 8192
#define SB_HI 16384
#define SB_LO 32768
#define STAGE_BYTES 49152
#define GEMM_SMEM 98304

template <bool HALF_OUT>
__global__ __launch_bounds__(256, 2) void mma_gemm_k(
    const __half* __restrict__ Ahi, const __half* __restrict__ Alo,
    const __half* __restrict__ Bhi, const __half* __restrict__ Blo,
    float* __restrict__ C, __half* __restrict__ Chi, __half* __restrict__ Clo,
    float* __restrict__ sums, int Mr, int K, int Nc) {
    extern __shared__ char smem[];
    const uint32_t sb = smem_u32(smem);
    const int tid = threadIdx.x;
    const int lane = tid & 31, wid = tid >> 5;
    const int wm = (wid >> 2) * 32;
    const int wn = (wid & 3) * 32;
    const int m0 = blockIdx.y * 64;
    const int n0 = blockIdx.x * 128;
    const int nkt = K >> 6;

    float acc[2][4][4];
#pragma unroll
    for (int a = 0; a < 2; a++)
#pragma unroll
        for (int b = 0; b < 4; b++)
#pragma unroll
            for (int c = 0; c < 4; c++) acc[a][b][c] = 0.f;

    const int brow = tid >> 1, bhalf = tid & 1;
    const int arow = tid >> 2, aq = tid & 3;
    const bool arow_ok = (m0 + arow) < Mr;
    const int arow_cl = arow_ok ? (m0 + arow) : 0;
    const char* pAhi = (const char*)(Ahi + (size_t)arow_cl * K);
    const char* pAlo = (const char*)(Alo + (size_t)arow_cl * K);
    const char* pBhi = (const char*)(Bhi + (size_t)(n0 + brow) * K + bhalf * 32);
    const char* pBlo = (const char*)(Blo + (size_t)(n0 + brow) * K + bhalf * 32);
    const int asz = arow_ok ? 16 : 0;

    auto issue = [&](int stage, int kt) {
        const size_t gk = (size_t)kt * 128;
        const uint32_t st = sb + stage * STAGE_BYTES;
#pragma unroll
        for (int j = 0; j < 2; j++) {
            uint32_t so = SW128((uint32_t)(arow * 128 + aq * 32 + j * 16));
            CP_ASYNC16(st + SA_HI + so, pAhi + gk + aq * 32 + j * 16, asz);
            CP_ASYNC16(st + SA_LO + so, pAlo + gk + aq * 32 + j * 16, asz);
        }
#pragma unroll
        for (int j = 0; j < 4; j++) {
            uint32_t so = SW128((uint32_t)(brow * 128 + bhalf * 64 + j * 16));
            CP_ASYNC16(st + SB_HI + so, pBhi + gk + j * 16, 16);
            CP_ASYNC16(st + SB_LO + so, pBlo + gk + j * 16, 16);
        }
    };

    issue(0, 0);
    CP_COMMIT();

    for (int kt = 0; kt < nkt; kt++) {
        const int buf = kt & 1;
        if (kt + 1 < nkt) {
            issue(buf ^ 1, kt + 1);
            CP_COMMIT();
            CP_WAIT1();
        } else {
            CP_WAIT0();
        }
        __syncthreads();

        const uint32_t st = sb + buf * STAGE_BYTES;
#pragma unroll
        for (int ks = 0; ks < 4; ks++) {
            const int k0 = ks * 16;
            const uint32_t ar = wm + (lane & 15);
            const uint32_t ac = k0 + ((lane >> 4) << 3);
            const uint32_t br = wn + (lane & 7) + ((lane >> 4) << 3);
            const uint32_t bc = k0 + (((lane >> 3) & 1) << 3);
            uint32_t bhi[8], blo[8], af[8];
#pragma unroll
            for (int nb = 0; nb < 2; nb++) {
                uint32_t off = SW128((br + nb * 16) * 128 + bc * 2);
                LDSM_X4(bhi[nb * 4 + 0], bhi[nb * 4 + 1], bhi[nb * 4 + 2], bhi[nb * 4 + 3],
                        st + SB_HI + off);
                LDSM_X4(blo[nb * 4 + 0], blo[nb * 4 + 1], blo[nb * 4 + 2], blo[nb * 4 + 3],
                        st + SB_LO + off);
            }
#pragma unroll
            for (int mf = 0; mf < 2; mf++) {
                uint32_t off = SW128((ar + mf * 16) * 128 + ac * 2);
                LDSM_X4(af[mf * 4 + 0], af[mf * 4 + 1], af[mf * 4 + 2], af[mf * 4 + 3],
                        st + SA_HI + off);
            }
#pragma unroll
            for (int mf = 0; mf < 2; mf++)
#pragma unroll
                for (int nf = 0; nf < 4; nf++) {
                    int bi = (nf >> 1) * 4 + (nf & 1) * 2;
                    MMA16816(acc[mf][nf], af[mf * 4], af[mf * 4 + 1], af[mf * 4 + 2],
                             af[mf * 4 + 3], bhi[bi], bhi[bi + 1]);
                    MMA16816(acc[mf][nf], af[mf * 4], af[mf * 4 + 1], af[mf * 4 + 2],
                             af[mf * 4 + 3], blo[bi], blo[bi + 1]);
                }
#pragma unroll
            for (int mf = 0; mf < 2; mf++) {
                uint32_t off = SW128((ar + mf * 16) * 128 + ac * 2);
                LDSM_X4(af[mf * 4 + 0], af[mf * 4 + 1], af[mf * 4 + 2], af[mf * 4 + 3],
                        st + SA_LO + off);
            }
#pragma unroll
            for (int mf = 0; mf < 2; mf++)
#pragma unroll
                for (int nf = 0; nf < 4; nf++) {
                    int bi = (nf >> 1) * 4 + (nf & 1) * 2;
                    MMA16816(acc[mf][nf], af[mf * 4], af[mf * 4 + 1], af[mf * 4 + 2],
                             af[mf * 4 + 3], bhi[bi], bhi[bi + 1]);
                }
        }
        __syncthreads();
    }

    // epilogue
#pragma unroll
    for (int mf = 0; mf < 2; mf++) {
        int r = m0 + wm + mf * 16 + (lane >> 2);
#pragma unroll
        for (int nf = 0; nf < 4; nf++) {
            int col = n0 + wn + nf * 8 + (lane & 3) * 2;
            float a0 = acc[mf][nf][0], a1 = acc[mf][nf][1];
            float a2 = acc[mf][nf][2], a3 = acc[mf][nf][3];
            if (HALF_OUT) {
                if (r < Mr) {
                    __half h0 = __float2half_rn(a0), h1 = __float2half_rn(a1);
                    *(uint32_t*)&Chi[(size_t)r * Nc + col] =
                        (uint32_t)__half_as_ushort(h0) | ((uint32_t)__half_as_ushort(h1) << 16);
                    *(uint32_t*)&Clo[(size_t)r * Nc + col] =
                        pack2h(a0 - __half2float(h0), a1 - __half2float(h1));
                }
                if (r + 8 < Mr) {
                    __half h2 = __float2half_rn(a2), h3 = __float2half_rn(a3);
                    *(uint32_t*)&Chi[(size_t)(r + 8) * Nc + col] =
                        (uint32_t)__half_as_ushort(h2) | ((uint32_t)__half_as_ushort(h3) << 16);
                    *(uint32_t*)&Clo[(size_t)(r + 8) * Nc + col] =
                        pack2h(a2 - __half2float(h2), a3 - __half2float(h3));
                }
            } else {
                if (r < Mr)
                    *(float2*)&C[(size_t)r * Nc + col] = make_float2(a0, a1);
                if (r + 8 < Mr)
                    *(float2*)&C[(size_t)(r + 8) * Nc + col] = make_float2(a2, a3);
            }
        }
    }

    // fused BN column stats
#pragma unroll
    for (int nf = 0; nf < 4; nf++) {
        float s0 = 0.f, s1 = 0.f, q0 = 0.f, q1 = 0.f;
#pragma unroll
        for (int mf = 0; mf < 2; mf++) {
            float a0 = acc[mf][nf][0], a1 = acc[mf][nf][1];
            float a2 = acc[mf][nf][2], a3 = acc[mf][nf][3];
            s0 += a0 + a2; s1 += a1 + a3;
            q0 += a0 * a0 + a2 * a2; q1 += a1 * a1 + a3 * a3;
        }
#pragma unroll
        for (int off = 4; off < 32; off <<= 1) {
            s0 += __shfl_xor_sync(0xffffffff, s0, off);
            s1 += __shfl_xor_sync(0xffffffff, s1, off);
            q0 += __shfl_xor_sync(0xffffffff, q0, off);
            q1 += __shfl_xor_sync(0xffffffff, q1, off);
        }
        if (lane < 4) {
            int c = n0 + wn + nf * 8 + lane * 2;
            atomicAdd(&sums[c], s0);
            atomicAdd(&sums[c + 1], s1);
            atomicAdd(&sums[Nc + c], q0);
            atomicAdd(&sums[Nc + c + 1], q1);
        }
    }
}

// ---------------- final BN apply (inline scale/shift) ------------------------
__global__ void bn_apply_final_k(const float* __restrict__ X,
                                 const float* __restrict__ sums,
                                 const float* __restrict__ g,
                                 const float* __restrict__ b,
                                 float* __restrict__ Y) {
    __shared__ float s_sc[Ee], s_sh[Ee];
    for (int c = threadIdx.x; c < Ee; c += blockDim.x) {
        float mean = sums[c] * (1.f / Nn);
        float var = sums[Ee + c] * (1.f / Nn) - mean * mean;
        float s = g[c] * rsqrtf(var + 1e-5f);
        s_sc[c] = s;
        s_sh[c] = b[c] - mean * s;
    }
    __syncthreads();
    int i = blockIdx.x * blockDim.x + threadIdx.x;
    if (i >= Nn * Ee / 4) return;
    int c = (i & 63) * 4;
    float4 v = ((const float4*)X)[i];
    v.x = fmaf(v.x, s_sc[c + 0], s_sh[c + 0]);
    v.y = fmaf(v.y, s_sc[c + 1], s_sh[c + 1]);
    v.z = fmaf(v.z, s_sc[c + 2], s_sh[c + 2]);
    v.w = fmaf(v.w, s_sc[c + 3], s_sh[c + 3]);
    ((float4*)Y)[i] = v;
}

// ---------------- host orchestration ----------------------------------------
struct Scratch {
    float *h, *hB, *sumsH, *sumsE, *mask;
    __half *A1hi, *A1lo, *t1hi, *t1lo, *A2hi, *A2lo;
    __half *W1Thi, *W1Tlo, *W2Thi, *W2Tlo;
    int *offs_b, *offs_l, *offs_r, *src_b, *atr_b, *src_l, *src_r;
};

extern "C" void kernel_launch(void* const* d_in, const int* in_sizes, int n_in,
                              void* d_out, int out_size) {
    const int* x       = (const int*)d_in[0];
    const int* ei      = (const int*)d_in[1];
    const int* ea      = (const int*)d_in[2];
    const int* xei     = (const int*)d_in[3];
    const void* mask_raw = d_in[4];
    const float* atom_emb = (const float*)d_in[5];
    const float* bond_emb = (const float*)d_in[6];
    const float* eps_m = (const float*)d_in[7];
    const float* W1_m  = (const float*)d_in[8];
    const float* g1_m  = (const float*)d_in[10];
    const float* be1_m = (const float*)d_in[11];
    const float* W2_m  = (const float*)d_in[12];
    const float* bn_g_m = (const float*)d_in[14];
    const float* bn_b_m = (const float*)d_in[15];
    const float* eps_e = (const float*)d_in[16];
    const float* W1_e  = (const float*)d_in[17];
    const float* g1_e  = (const float*)d_in[18];
    const float* be1_e = (const float*)d_in[19];
    const float* W2_e  = (const float*)d_in[20];
    const float* bn_g_e = (const float*)d_in[21];
    const float* bn_b_e = (const float*)d_in[22];

    const int M  = in_sizes[1] / 2;
    const int MX = in_sizes[3] / 2;

    cudaFuncSetAttribute(mma_gemm_k<true>, cudaFuncAttributeMaxDynamicSharedMemorySize, GEMM_SMEM);
    cudaFuncSetAttribute(mma_gemm_k<false>, cudaFuncAttributeMaxDynamicSharedMemorySize, GEMM_SMEM);

    Scratch S;
    cudaGetSymbolAddress((void**)&S.h, g_h);
    cudaGetSymbolAddress((void**)&S.hB, g_hB);
    cudaGetSymbolAddress((void**)&S.sumsH, g_sumsH);
    cudaGetSymbolAddress((void**)&S.sumsE, g_sumsE);
    cudaGetSymbolAddress((void**)&S.mask, g_mask);
    cudaGetSymbolAddress((void**)&S.A1hi, g_A1hi);
    cudaGetSymbolAddress((void**)&S.A1lo, g_A1lo);
    cudaGetSymbolAddress((void**)&S.t1hi, g_t1hi);
    cudaGetSymbolAddress((void**)&S.t1lo, g_t1lo);
    cudaGetSymbolAddress((void**)&S.A2hi, g_A2hi);
    cudaGetSymbolAddress((void**)&S.A2lo, g_A2lo);
    cudaGetSymbolAddress((void**)&S.W1Thi, g_W1Thi);
    cudaGetSymbolAddress((void**)&S.W1Tlo, g_W1Tlo);
    cudaGetSymbolAddress((void**)&S.W2Thi, g_W2Thi);
    cudaGetSymbolAddress((void**)&S.W2Tlo, g_W2Tlo);
    cudaGetSymbolAddress((void**)&S.offs_b, g_offs_b);
    cudaGetSymbolAddress((void**)&S.offs_l, g_offs_l);
    cudaGetSymbolAddress((void**)&S.offs_r, g_offs_r);
    cudaGetSymbolAddress((void**)&S.src_b, g_src_b);
    cudaGetSymbolAddress((void**)&S.atr_b, g_atr_b);
    cudaGetSymbolAddress((void**)&S.src_l, g_src_l);
    cudaGetSymbolAddress((void**)&S.src_r, g_src_r);

    const int TOT = M + 2 * MX;

    detect_mask_k<<<1, 256>>>(mask_raw);
    setup_k<<<79, 256>>>(mask_raw);
    atom_encode_k<<<Nn, 64>>>(x, atom_emb, S.h);
    hist_all_k<<<(TOT + 255) / 256, 256>>>(ei, xei, M, MX);
    scan_all_k<<<3, 1024>>>();
    fill_all_k<<<(TOT + 255) / 256, 256>>>(ei, xei, ea, M, MX);
    wsplit_all_k<<<dim3(16, 16, 2 * NCONV), dim3(32, 8)>>>(W1_m, W1_e, W2_m, W2_e);

    const float* prev_sums = nullptr;
    const float* prev_g = nullptr;
    const float* prev_b = nullptr;

    dim3 g1d(Hh / 128, (Nn + 63) / 64);
    dim3 g2d(Ee / 128, (Nn + 63) / 64);

    for (int l = 0; l < Ll; l++) {
        for (int j = 0; j < 3; j++) {
            int c = l * 3 + j;
            const float* Xin = (c == 0) ? S.h : S.hB;
            const float* eps;
            const float* g1;
            const float* be1;
            const float* bng;
            const float* bnb;
            const float* mask = nullptr;
            const int* offs;
            const int* csrc;
            const int* catr = nullptr;
            if (j == 0) {
                eps = eps_m + l;
                g1 = g1_m + (size_t)l * Hh;  be1 = be1_m + (size_t)l * Hh;
                bng = bn_g_m + (size_t)l * Ee; bnb = bn_b_m + (size_t)l * Ee;
                offs = S.offs_b; csrc = S.src_b; catr = S.atr_b;
            } else {
                int s = l * 2 + (j - 1);
                eps = eps_e + s;
                g1 = g1_e + (size_t)s * Hh;  be1 = be1_e + (size_t)s * Hh;
                bng = bn_g_e + (size_t)s * Ee; bnb = bn_b_e + (size_t)s * Ee;
                offs = (j == 1) ? S.offs_l : S.offs_r;
                csrc = (j == 1) ? S.src_l : S.src_r;
                mask = S.mask;
            }
            float* sumsH_c = S.sumsH + (size_t)c * 2 * Hh;
            float* sumsE_c = S.sumsE + (size_t)c * 2 * Ee;

            if (catr)
                gather_k<true><<<(Nn + 7) / 8, 256>>>(Xin, prev_sums, prev_g, prev_b,
                                                      offs, csrc, catr, bond_emb,
                                                      mask, eps, S.A1hi, S.A1lo);
            else
                gather_k<false><<<(Nn + 7) / 8, 256>>>(Xin, prev_sums, prev_g, prev_b,
                                                       offs, csrc, nullptr, nullptr,
                                                       mask, eps, S.A1hi, S.A1lo);

            mma_gemm_k<true><<<g1d, 256, GEMM_SMEM>>>(
                S.A1hi, S.A1lo,
                S.W1Thi + (size_t)c * Hh * Ee, S.W1Tlo + (size_t)c * Hh * Ee,
                nullptr, S.t1hi, S.t1lo, sumsH_c, Nn, Ee, Hh);

            bnrelu_split_k<<<(Nn * Hh / 4 + 255) / 256, 256>>>(
                S.t1hi, S.t1lo, sumsH_c, g1, be1, S.A2hi, S.A2lo);

            mma_gemm_k<false><<<g2d, 256, GEMM_SMEM>>>(
                S.A2hi, S.A2lo,
                S.W2Thi + (size_t)c * Ee * Hh, S.W2Tlo + (size_t)c * Ee * Hh,
                S.hB, nullptr, nullptr, sumsE_c, Nn, Hh, Ee);

            prev_sums = sumsE_c;
            prev_g = bng;
            prev_b = bnb;
        }
    }

    bn_apply_final_k<<<(Nn * Ee / 4 + 255) / 256, 256>>>(S.hB, prev_sums, prev_g, prev_b,
                                                         (float*)d_out);
}

// round 14
// speedup vs baseline: 1.0826x; 1.0292x over previous
#include <cuda_runtime.h>
#include <cuda_fp16.h>
#include <cstddef>
#include <cstdint>

#define Nn 20000
#define Ee 256
#define Hh 512
#define Ll 5
#define NCONV 15
#define MB_CAP 320000
#define MX_CAP 160000

// ---------------- scratch (device globals; no allocations allowed) ----------
__device__ float g_h[Nn * Ee];
__device__ float g_hB[Nn * Ee];
__device__ float g_sumsH[NCONV * 2 * Hh];
__device__ float g_sumsE[NCONV * 2 * Ee];
__device__ float g_mask[Nn];
__device__ int   g_mask_dtype;

__device__ __half g_A1hi[Nn * Ee];
__device__ __half g_A1lo[Nn * Ee];
__device__ __half g_t1hi[Nn * Hh];
__device__ __half g_t1lo[Nn * Hh];
__device__ __half g_A2hi[Nn * Hh];
__device__ __half g_A2lo[Nn * Hh];
__device__ __half g_W1Thi[NCONV * Hh * Ee];
__device__ __half g_W1Tlo[NCONV * Hh * Ee];
__device__ __half g_W2Thi[NCONV * Ee * Hh];
__device__ __half g_W2Tlo[NCONV * Ee * Hh];

__device__ int g_deg[3 * Nn];
__device__ int g_cur[3 * Nn];
__device__ int g_offs_b[Nn + 1], g_offs_l[Nn + 1], g_offs_r[Nn + 1];
__device__ int g_src_b[MB_CAP];
__device__ int g_atr_b[MB_CAP];
__device__ int g_src_l[MX_CAP];
__device__ int g_src_r[MX_CAP];

// ---------------- helpers ----------------------------------------------------
__device__ __forceinline__ uint32_t smem_u32(const void* p) {
    uint32_t a;
    asm("{ .reg .u64 t; cvta.to.shared.u64 t, %1; cvt.u32.u64 %0, t; }" : "=r"(a) : "l"(p));
    return a;
}
#define SW128(off) ((off) ^ (((off) >> 3) & 0x70))
#define SW64(off)  ((off) ^ (((off) >> 3) & 0x30))

#define LDSM_X4(r0, r1, r2, r3, addr) \
    asm volatile("ldmatrix.sync.aligned.m8n8.x4.shared.b16 {%0,%1,%2,%3}, [%4];" \
                 : "=r"(r0), "=r"(r1), "=r"(r2), "=r"(r3) : "r"(addr))

#define MMA16816(d, a0, a1, a2, a3, b0, b1) \
    asm volatile("mma.sync.aligned.m16n8k16.row.col.f32.f16.f16.f32 " \
                 "{%0,%1,%2,%3}, {%4,%5,%6,%7}, {%8,%9}, {%0,%1,%2,%3};" \
                 : "+f"((d)[0]), "+f"((d)[1]), "+f"((d)[2]), "+f"((d)[3]) \
                 : "r"(a0), "r"(a1), "r"(a2), "r"(a3), "r"(b0), "r"(b1))

#define CP_ASYNC16(dst, src, sz) \
    asm volatile("cp.async.cg.shared.global [%0], [%1], 16, %2;" \
                 :: "r"(dst), "l"(src), "r"(sz))
#define CP_COMMIT() asm volatile("cp.async.commit_group;" ::: "memory")
#define CP_WAIT0() asm volatile("cp.async.wait_group 0;" ::: "memory")
#define CP_WAIT1() asm volatile("cp.async.wait_group 1;" ::: "memory")

__device__ __forceinline__ uint32_t pack2h(float a, float b) {
    __half ha = __float2half_rn(a), hb = __float2half_rn(b);
    return (uint32_t)__half_as_ushort(ha) | ((uint32_t)__half_as_ushort(hb) << 16);
}

// ---------------- mask dtype detection ---------------------------------------
__global__ void detect_mask_k(const void* mask) {
    __shared__ int not_i32, not_f32;
    if (threadIdx.x == 0) { not_i32 = 0; not_f32 = 0; }
    __syncthreads();
    const unsigned* w = (const unsigned*)mask;
    int bad_i = 0, bad_f = 0;
    for (int i = threadIdx.x; i < Nn / 4; i += blockDim.x) {
        unsigned v = w[i];
        if (v > 1u) bad_i = 1;
        if (v != 0u && v != 0x3F800000u) bad_f = 1;
    }
    if (bad_i) atomicOr(&not_i32, 1);
    if (bad_f) atomicOr(&not_f32, 1);
    __syncthreads();
    if (threadIdx.x == 0) {
        if (!not_i32) g_mask_dtype = 0;
        else if (!not_f32) g_mask_dtype = 1;
        else g_mask_dtype = 2;
    }
}

__global__ void setup_k(const void* mask) {
    int i = blockIdx.x * blockDim.x + threadIdx.x;
    int stride = gridDim.x * blockDim.x;
    int dt = g_mask_dtype;
    for (int n = i; n < Nn; n += stride) {
        float m;
        if (dt == 0)      m = (((const int*)mask)[n] != 0) ? 1.f : 0.f;
        else if (dt == 1) m = (((const float*)mask)[n] != 0.f) ? 1.f : 0.f;
        else              m = (((const unsigned char*)mask)[n] != 0) ? 1.f : 0.f;
        g_mask[n] = m;
    }
    for (int n = i; n < 3 * Nn; n += stride) g_deg[n] = 0;
    for (int n = i; n < NCONV * 2 * Hh; n += stride) g_sumsH[n] = 0.f;
    for (int n = i; n < NCONV * 2 * Ee; n += stride) g_sumsE[n] = 0.f;
}

// ---------------- atom encoder ------------------------------------------------
__global__ void atom_encode_k(const int* __restrict__ x,
                              const float* __restrict__ emb,
                              float* __restrict__ h) {
    int n = blockIdx.x;
    int t = threadIdx.x;
    float4 acc = make_float4(0.f, 0.f, 0.f, 0.f);
#pragma unroll
    for (int f = 0; f < 9; f++) {
        int idx = __ldg(&x[n * 9 + f]);
        const float4* row = (const float4*)&emb[((size_t)(f * 128 + idx)) * Ee];
        float4 v = row[t];
        acc.x += v.x; acc.y += v.y; acc.z += v.z; acc.w += v.w;
    }
    ((float4*)h)[(size_t)n * (Ee / 4) + t] = acc;
}

// ---------------- CSR build (fused across 3 orientations) --------------------
__global__ void hist_all_k(const int* __restrict__ ei, const int* __restrict__ xei,
                           int M, int MX) {
    int e = blockIdx.x * blockDim.x + threadIdx.x;
    if (e < M) atomicAdd(&g_deg[ei[M + e]], 1);
    else if (e < M + MX) atomicAdd(&g_deg[Nn + xei[MX + (e - M)]], 1);
    else if (e < M + 2 * MX) atomicAdd(&g_deg[2 * Nn + xei[e - M - MX]], 1);
}

__global__ void scan_all_k() {
    int which = blockIdx.x;
    const int* deg = g_deg + which * Nn;
    int* cur = g_cur + which * Nn;
    int* offs = (which == 0) ? g_offs_b : (which == 1) ? g_offs_l : g_offs_r;
    __shared__ int ssum[1024];
    int t = threadIdx.x;
    const int PER = (Nn + 1023) / 1024;  // 20
    int loc[20];
    int s = 0;
#pragma unroll
    for (int i = 0; i < PER; i++) {
        int idx = t * PER + i;
        int v = (idx < Nn) ? deg[idx] : 0;
        loc[i] = s;
        s += v;
    }
    ssum[t] = s;
    __syncthreads();
    for (int off = 1; off < 1024; off <<= 1) {
        int v = (t >= off) ? ssum[t - off] : 0;
        __syncthreads();
        ssum[t] += v;
        __syncthreads();
    }
    int pre = (t > 0) ? ssum[t - 1] : 0;
#pragma unroll
    for (int i = 0; i < PER; i++) {
        int idx = t * PER + i;
        if (idx < Nn) {
            offs[idx] = pre + loc[i];
            cur[idx] = pre + loc[i];
        }
    }
    if (t == 1023) offs[Nn] = ssum[1023];
}

__global__ void fill_all_k(const int* __restrict__ ei, const int* __restrict__ xei,
                           const int* __restrict__ ea, int M, int MX) {
    int e = blockIdx.x * blockDim.x + threadIdx.x;
    if (e < M) {
        int p = atomicAdd(&g_cur[ei[M + e]], 1);
        if (p < MB_CAP) {
            g_src_b[p] = ei[e];
            g_atr_b[p] = ea[e * 3] | (ea[e * 3 + 1] << 3) | (ea[e * 3 + 2] << 6);
        }
    } else if (e < M + MX) {
        int j = e - M;
        int p = atomicAdd(&g_cur[Nn + xei[MX + j]], 1);
        if (p < MX_CAP) g_src_l[p] = xei[j];
    } else if (e < M + 2 * MX) {
        int j = e - M - MX;
        int p = atomicAdd(&g_cur[2 * Nn + xei[j]], 1);
        if (p < MX_CAP) g_src_r[p] = xei[MX + j];
    }
}

// ---------------- merged weight transpose + fp16 split ------------------------
__global__ void wsplit_all_k(const float* __restrict__ W1m, const float* __restrict__ W1e,
                             const float* __restrict__ W2m, const float* __restrict__ W2e) {
    int z = blockIdx.z;
    int which = z / NCONV;
    int c = z % NCONV;
    int l = c / 3, j = c % 3;
    const float* W;
    __half *Thi, *Tlo;
    int K, N;
    if (which == 0) {
        K = Ee; N = Hh;
        W = j ? W1e + (size_t)(l * 2 + j - 1) * Ee * Hh : W1m + (size_t)l * Ee * Hh;
        Thi = g_W1Thi + (size_t)c * Hh * Ee;
        Tlo = g_W1Tlo + (size_t)c * Hh * Ee;
    } else {
        K = Hh; N = Ee;
        W = j ? W2e + (size_t)(l * 2 + j - 1) * Hh * Ee : W2m + (size_t)l * Hh * Ee;
        Thi = g_W2Thi + (size_t)c * Ee * Hh;
        Tlo = g_W2Tlo + (size_t)c * Ee * Hh;
    }
    int kb = blockIdx.x * 32, nb = blockIdx.y * 32;
    if (kb >= K || nb >= N) return;
    __shared__ float t[32][33];
    int tx = threadIdx.x, ty = threadIdx.y;
    for (int i = ty; i < 32; i += 8)
        t[i][tx] = W[(size_t)(kb + i) * N + nb + tx];
    __syncthreads();
    for (int i = ty; i < 32; i += 8) {
        float v = t[tx][i];
        __half hi = __float2half_rn(v);
        float lo = v - __half2float(hi);
        Thi[(size_t)(nb + i) * K + kb + tx] = hi;
        Tlo[(size_t)(nb + i) * K + kb + tx] = __float2half_rn(lo);
    }
}

// ---------------- fused CSR gather (edge loop unrolled x2) --------------------
template <bool BOND>
__global__ __launch_bounds__(256) void gather_k(
    const float* __restrict__ Xin,
    const float* __restrict__ insums, const float* __restrict__ ing,
    const float* __restrict__ inb,
    const int* __restrict__ offs, const int* __restrict__ csrc,
    const int* __restrict__ catr, const float* __restrict__ bemb,
    const float* __restrict__ mask, const float* __restrict__ eps,
    __half* __restrict__ Ahi, __half* __restrict__ Alo) {
    __shared__ float s_sc[Ee], s_sh[Ee];
    for (int c = threadIdx.x; c < Ee; c += blockDim.x) {
        if (insums) {
            float mean = insums[c] * (1.f / Nn);
            float var = insums[Ee + c] * (1.f / Nn) - mean * mean;
            float s = ing[c] * rsqrtf(var + 1e-5f);
            s_sc[c] = s;
            s_sh[c] = inb[c] - mean * s;
        } else {
            s_sc[c] = 1.f;
            s_sh[c] = 0.f;
        }
    }
    __syncthreads();

    int node = blockIdx.x * 8 + (threadIdx.x >> 5);
    if (node >= Nn) return;
    int lane = threadIdx.x & 31;
    int c0 = lane * 8;
    float flo = insums ? 0.f : -3.4e38f;

    float4 sc0 = *(const float4*)&s_sc[c0], sc1 = *(const float4*)&s_sc[c0 + 4];
    float4 sh0 = *(const float4*)&s_sh[c0], sh1 = *(const float4*)&s_sh[c0 + 4];

    float a0 = 0.f, a1 = 0.f, a2 = 0.f, a3 = 0.f, a4 = 0.f, a5 = 0.f, a6 = 0.f, a7 = 0.f;
    int e0 = __ldg(&offs[node]), e1 = __ldg(&offs[node + 1]);

    int e = e0;
    for (; e + 2 <= e1; e += 2) {
        int sA = __ldg(&csrc[e]);
        int sB = __ldg(&csrc[e + 1]);
        const float4* xrA = (const float4*)&Xin[(size_t)sA * Ee + c0];
        const float4* xrB = (const float4*)&Xin[(size_t)sB * Ee + c0];
        float4 xA0 = __ldg(xrA), xA1 = __ldg(xrA + 1);
        float4 xB0 = __ldg(xrB), xB1 = __ldg(xrB + 1);
        float4 bA0, bA1, bB0, bB1;
        if (BOND) {
            int mtA = __ldg(&catr[e]);
            int mtB = __ldg(&catr[e + 1]);
            const float4* pA0 = (const float4*)&bemb[(size_t)(mtA & 7) * Ee + c0];
            const float4* pA1 = (const float4*)&bemb[(size_t)(8 + ((mtA >> 3) & 7)) * Ee + c0];
            const float4* pA2 = (const float4*)&bemb[(size_t)(16 + ((mtA >> 6) & 7)) * Ee + c0];
            const float4* pB0 = (const float4*)&bemb[(size_t)(mtB & 7) * Ee + c0];
            const float4* pB1 = (const float4*)&bemb[(size_t)(8 + ((mtB >> 3) & 7)) * Ee + c0];
            const float4* pB2 = (const float4*)&bemb[(size_t)(16 + ((mtB >> 6) & 7)) * Ee + c0];
            float4 a00 = __ldg(pA0), a01 = __ldg(pA0 + 1);
            float4 a10 = __ldg(pA1), a11 = __ldg(pA1 + 1);
            float4 a20 = __ldg(pA2), a21 = __ldg(pA2 + 1);
            float4 b00 = __ldg(pB0), b01 = __ldg(pB0 + 1);
            float4 b10 = __ldg(pB1), b11 = __ldg(pB1 + 1);
            float4 b20 = __ldg(pB2), b21 = __ldg(pB2 + 1);
            bA0.x = a00.x + a10.x + a20.x; bA0.y = a00.y + a10.y + a20.y;
            bA0.z = a00.z + a10.z + a20.z; bA0.w = a00.w + a10.w + a20.w;
            bA1.x = a01.x + a11.x + a21.x; bA1.y = a01.y + a11.y + a21.y;
            bA1.z = a01.z + a11.z + a21.z; bA1.w = a01.w + a11.w + a21.w;
            bB0.x = b00.x + b10.x + b20.x; bB0.y = b00.y + b10.y + b20.y;
            bB0.z = b00.z + b10.z + b20.z; bB0.w = b00.w + b10.w + b20.w;
            bB1.x = b01.x + b11.x + b21.x; bB1.y = b01.y + b11.y + b21.y;
            bB1.z = b01.z + b11.z + b21.z; bB1.w = b01.w + b11.w + b21.w;
        }
        {
            float v0 = fmaxf(fmaf(xA0.x, sc0.x, sh0.x), flo);
            float v1 = fmaxf(fmaf(xA0.y, sc0.y, sh0.y), flo);
            float v2 = fmaxf(fmaf(xA0.z, sc0.z, sh0.z), flo);
            float v3 = fmaxf(fmaf(xA0.w, sc0.w, sh0.w), flo);
            float v4 = fmaxf(fmaf(xA1.x, sc1.x, sh1.x), flo);
            float v5 = fmaxf(fmaf(xA1.y, sc1.y, sh1.y), flo);
            float v6 = fmaxf(fmaf(xA1.z, sc1.z, sh1.z), flo);
            float v7 = fmaxf(fmaf(xA1.w, sc1.w, sh1.w), flo);
            if (BOND) {
                v0 += bA0.x; v1 += bA0.y; v2 += bA0.z; v3 += bA0.w;
                v4 += bA1.x; v5 += bA1.y; v6 += bA1.z; v7 += bA1.w;
            }
            a0 += fmaxf(v0, 0.f); a1 += fmaxf(v1, 0.f);
            a2 += fmaxf(v2, 0.f); a3 += fmaxf(v3, 0.f);
            a4 += fmaxf(v4, 0.f); a5 += fmaxf(v5, 0.f);
            a6 += fmaxf(v6, 0.f); a7 += fmaxf(v7, 0.f);
        }
        {
            float v0 = fmaxf(fmaf(xB0.x, sc0.x, sh0.x), flo);
            float v1 = fmaxf(fmaf(xB0.y, sc0.y, sh0.y), flo);
            float v2 = fmaxf(fmaf(xB0.z, sc0.z, sh0.z), flo);
            float v3 = fmaxf(fmaf(xB0.w, sc0.w, sh0.w), flo);
            float v4 = fmaxf(fmaf(xB1.x, sc1.x, sh1.x), flo);
            float v5 = fmaxf(fmaf(xB1.y, sc1.y, sh1.y), flo);
            float v6 = fmaxf(fmaf(xB1.z, sc1.z, sh1.z), flo);
            float v7 = fmaxf(fmaf(xB1.w, sc1.w, sh1.w), flo);
            if (BOND) {
                v0 += bB0.x; v1 += bB0.y; v2 += bB0.z; v3 += bB0.w;
                v4 += bB1.x; v5 += bB1.y; v6 += bB1.z; v7 += bB1.w;
            }
            a0 += fmaxf(v0, 0.f); a1 += fmaxf(v1, 0.f);
            a2 += fmaxf(v2, 0.f); a3 += fmaxf(v3, 0.f);
            a4 += fmaxf(v4, 0.f); a5 += fmaxf(v5, 0.f);
            a6 += fmaxf(v6, 0.f); a7 += fmaxf(v7, 0.f);
        }
    }
    for (; e < e1; e++) {
        int s = __ldg(&csrc[e]);
        const float4* xr = (const float4*)&Xin[(size_t)s * Ee + c0];
        float4 x0 = __ldg(xr), x1 = __ldg(xr + 1);
        float v0 = fmaxf(fmaf(x0.x, sc0.x, sh0.x), flo);
        float v1 = fmaxf(fmaf(x0.y, sc0.y, sh0.y), flo);
        float v2 = fmaxf(fmaf(x0.z, sc0.z, sh0.z), flo);
        float v3 = fmaxf(fmaf(x0.w, sc0.w, sh0.w), flo);
        float v4 = fmaxf(fmaf(x1.x, sc1.x, sh1.x), flo);
        float v5 = fmaxf(fmaf(x1.y, sc1.y, sh1.y), flo);
        float v6 = fmaxf(fmaf(x1.z, sc1.z, sh1.z), flo);
        float v7 = fmaxf(fmaf(x1.w, sc1.w, sh1.w), flo);
        if (BOND) {
            int mt = __ldg(&catr[e]);
            const float4* b0 = (const float4*)&bemb[(size_t)(mt & 7) * Ee + c0];
            const float4* b1 = (const float4*)&bemb[(size_t)(8 + ((mt >> 3) & 7)) * Ee + c0];
            const float4* b2 = (const float4*)&bemb[(size_t)(16 + ((mt >> 6) & 7)) * Ee + c0];
            float4 p0 = __ldg(b0), p1 = __ldg(b0 + 1);
            float4 q0 = __ldg(b1), q1 = __ldg(b1 + 1);
            float4 r0 = __ldg(b2), r1 = __ldg(b2 + 1);
            v0 += p0.x + q0.x + r0.x; v1 += p0.y + q0.y + r0.y;
            v2 += p0.z + q0.z + r0.z; v3 += p0.w + q0.w + r0.w;
            v4 += p1.x + q1.x + r1.x; v5 += p1.y + q1.y + r1.y;
            v6 += p1.z + q1.z + r1.z; v7 += p1.w + q1.w + r1.w;
        }
        a0 += fmaxf(v0, 0.f); a1 += fmaxf(v1, 0.f);
        a2 += fmaxf(v2, 0.f); a3 += fmaxf(v3, 0.f);
        a4 += fmaxf(v4, 0.f); a5 += fmaxf(v5, 0.f);
        a6 += fmaxf(v6, 0.f); a7 += fmaxf(v7, 0.f);
    }

    const float4* xr = (const float4*)&Xin[(size_t)node * Ee + c0];
    float4 x0 = __ldg(xr), x1 = __ldg(xr + 1);
    float s0 = fmaxf(fmaf(x0.x, sc0.x, sh0.x), flo);
    float s1 = fmaxf(fmaf(x0.y, sc0.y, sh0.y), flo);
    float s2 = fmaxf(fmaf(x0.z, sc0.z, sh0.z), flo);
    float s3 = fmaxf(fmaf(x0.w, sc0.w, sh0.w), flo);
    float s4 = fmaxf(fmaf(x1.x, sc1.x, sh1.x), flo);
    float s5 = fmaxf(fmaf(x1.y, sc1.y, sh1.y), flo);
    float s6 = fmaxf(fmaf(x1.z, sc1.z, sh1.z), flo);
    float s7 = fmaxf(fmaf(x1.w, sc1.w, sh1.w), flo);
    float m = mask ? __ldg(&mask[node]) : 1.f;
    float ef = (1.f + __ldg(eps)) * m;
    float p0 = fmaf(ef, s0, a0), p1 = fmaf(ef, s1, a1);
    float p2 = fmaf(ef, s2, a2), p3 = fmaf(ef, s3, a3);
    float p4 = fmaf(ef, s4, a4), p5 = fmaf(ef, s5, a5);
    float p6 = fmaf(ef, s6, a6), p7 = fmaf(ef, s7, a7);
    uint4 hi, lo;
    {
        __half h0 = __float2half_rn(p0), h1 = __float2half_rn(p1);
        __half h2 = __float2half_rn(p2), h3 = __float2half_rn(p3);
        __half h4 = __float2half_rn(p4), h5 = __float2half_rn(p5);
        __half h6 = __float2half_rn(p6), h7 = __float2half_rn(p7);
        hi.x = (uint32_t)__half_as_ushort(h0) | ((uint32_t)__half_as_ushort(h1) << 16);
        hi.y = (uint32_t)__half_as_ushort(h2) | ((uint32_t)__half_as_ushort(h3) << 16);
        hi.z = (uint32_t)__half_as_ushort(h4) | ((uint32_t)__half_as_ushort(h5) << 16);
        hi.w = (uint32_t)__half_as_ushort(h6) | ((uint32_t)__half_as_ushort(h7) << 16);
        lo.x = pack2h(p0 - __half2float(h0), p1 - __half2float(h1));
        lo.y = pack2h(p2 - __half2float(h2), p3 - __half2float(h3));
        lo.z = pack2h(p4 - __half2float(h4), p5 - __half2float(h5));
        lo.w = pack2h(p6 - __half2float(h6), p7 - __half2float(h7));
    }
    *(uint4*)&Ahi[(size_t)node * Ee + c0] = hi;
    *(uint4*)&Alo[(size_t)node * Ee + c0] = lo;
}

// ---------------- t1 pair -> inline BN -> relu -> split (4 elems/thread) -----
__global__ void bnrelu_split_k(const __half* __restrict__ Thi, const __half* __restrict__ Tlo,
                               const float* __restrict__ sums,
                               const float* __restrict__ g,
                               const float* __restrict__ b,
                               __half* __restrict__ Ahi, __half* __restrict__ Alo) {
    __shared__ float s_sc[Hh], s_sh[Hh];
    for (int c = threadIdx.x; c < Hh; c += blockDim.x) {
        float mean = sums[c] * (1.f / Nn);
        float var = sums[Hh + c] * (1.f / Nn) - mean * mean;
        float s = g[c] * rsqrtf(var + 1e-5f);
        s_sc[c] = s;
        s_sh[c] = b[c] - mean * s;
    }
    __syncthreads();
#pragma unroll
    for (int u = 0; u < 4; u++) {
        int i = blockIdx.x * 1024 + u * 256 + threadIdx.x;
        if (i >= Nn * Hh / 4) return;
        int c = (i & (Hh / 4 - 1)) * 4;
        uint2 vh = ((const uint2*)Thi)[i];
        uint2 vl = ((const uint2*)Tlo)[i];
        float2 h0 = __half22float2(*(__half2*)&vh.x);
        float2 h1 = __half22float2(*(__half2*)&vh.y);
        float2 l0 = __half22float2(*(__half2*)&vl.x);
        float2 l1 = __half22float2(*(__half2*)&vl.y);
        float x0 = h0.x + l0.x, x1 = h0.y + l0.y, x2 = h1.x + l1.x, x3 = h1.y + l1.y;
        x0 = fmaxf(fmaf(x0, s_sc[c + 0], s_sh[c + 0]), 0.f);
        x1 = fmaxf(fmaf(x1, s_sc[c + 1], s_sh[c + 1]), 0.f);
        x2 = fmaxf(fmaf(x2, s_sc[c + 2], s_sh[c + 2]), 0.f);
        x3 = fmaxf(fmaf(x3, s_sc[c + 3], s_sh[c + 3]), 0.f);
        __half q0 = __float2half_rn(x0), q1 = __float2half_rn(x1);
        __half q2 = __float2half_rn(x2), q3 = __float2half_rn(x3);
        uint2 hi, lo;
        hi.x = (uint32_t)__half_as_ushort(q0) | ((uint32_t)__half_as_ushort(q1) << 16);
        hi.y = (uint32_t)__half_as_ushort(q2) | ((uint32_t)__half_as_ushort(q3) << 16);
        lo.x = pack2h(x0 - __half2float(q0), x1 - __half2float(q1));
        lo.y = pack2h(x2 - __half2float(q2), x3 - __half2float(q3));
        ((uint2*)Ahi)[i] = hi;
        ((uint2*)Alo)[i] = lo;
    }
}

// ---------------- mma.sync fp16x3 GEMM: 64x128 tile, K32, 3-stage, 2 CTA/SM --
#define SA_HI 0
#define SA_LO 4096
#define SB_HI 8192
#define SB_LO 16384
#define STAGE_BYTES 24576
#define GEMM_SMEM 73728

template <bool HALF_OUT>
__global__ __launch_bounds__(256, 2) void mma_gemm_k(
    const __half* __restrict__ Ahi, const __half* __restrict__ Alo,
    const __half* __restrict__ Bhi, const __half* __restrict__ Blo,
    float* __restrict__ C, __half* __restrict__ Chi, __half* __restrict__ Clo,
    float* __restrict__ sums, int Mr, int K, int Nc) {
    extern __shared__ char smem[];
    const uint32_t sb = smem_u32(smem);
    const int tid = threadIdx.x;
    const int lane = tid & 31, wid = tid >> 5;
    const int wm = (wid >> 2) * 32;
    const int wn = (wid & 3) * 32;
    const int m0 = blockIdx.y * 64;
    const int n0 = blockIdx.x * 128;
    const int nkt = K >> 5;   // K-chunks of 32

    float acc[2][4][4];
#pragma unroll
    for (int a = 0; a < 2; a++)
#pragma unroll
        for (int b = 0; b < 4; b++)
#pragma unroll
            for (int c = 0; c < 4; c++) acc[a][b][c] = 0.f;

    // loaders: A 64 rows x 64B (1 chunk/thread/array); B 128 rows x 64B (2 chunks)
    const int arow = tid >> 2, aq = tid & 3;
    const int brow = tid >> 1, bq = tid & 1;
    const bool arow_ok = (m0 + arow) < Mr;
    const int arow_cl = arow_ok ? (m0 + arow) : 0;
    const char* pAhi = (const char*)(Ahi + (size_t)arow_cl * K);
    const char* pAlo = (const char*)(Alo + (size_t)arow_cl * K);
    const char* pBhi = (const char*)(Bhi + (size_t)(n0 + brow) * K);
    const char* pBlo = (const char*)(Blo + (size_t)(n0 + brow) * K);
    const int asz = arow_ok ? 16 : 0;
    const uint32_t aso = SW64((uint32_t)(arow * 64 + aq * 16));
    const uint32_t bso0 = SW64((uint32_t)(brow * 64 + bq * 32));
    const uint32_t bso1 = SW64((uint32_t)(brow * 64 + bq * 32 + 16));

    auto issue = [&](int stage, int kt) {
        const size_t gk = (size_t)kt * 64;  // 32 fp16 = 64 B
        const uint32_t st = sb + stage * STAGE_BYTES;
        CP_ASYNC16(st + SA_HI + aso, pAhi + gk + aq * 16, asz);
        CP_ASYNC16(st + SA_LO + aso, pAlo + gk + aq * 16, asz);
        CP_ASYNC16(st + SB_HI + bso0, pBhi + gk + bq * 32, 16);
        CP_ASYNC16(st + SB_HI + bso1, pBhi + gk + bq * 32 + 16, 16);
        CP_ASYNC16(st + SB_LO + bso0, pBlo + gk + bq * 32, 16);
        CP_ASYNC16(st + SB_LO + bso1, pBlo + gk + bq * 32 + 16, 16);
    };

    issue(0, 0); CP_COMMIT();
    issue(1, 1); CP_COMMIT();

    for (int kt = 0; kt < nkt; kt++) {
        if (kt + 2 < nkt) CP_WAIT1(); else CP_WAIT0();
        __syncthreads();
        // issue into the stage freed by iteration kt-1 (safe after the sync)
        if (kt + 2 < nkt) {
            issue((kt + 2) % 3, kt + 2);
            CP_COMMIT();
        }

        const uint32_t st = sb + (kt % 3) * STAGE_BYTES;
#pragma unroll
        for (int ks = 0; ks < 2; ks++) {
            const int k0 = ks * 16;
            const uint32_t ar = wm + (lane & 15);
            const uint32_t ac = k0 + ((lane >> 4) << 3);
            const uint32_t br = wn + (lane & 7) + ((lane >> 4) << 3);
            const uint32_t bc = k0 + (((lane >> 3) & 1) << 3);
            uint32_t bhi[8], blo[8], ah[8], al[8];
#pragma unroll
            for (int nb = 0; nb < 2; nb++) {
                uint32_t off = SW64((br + nb * 16) * 64 + bc * 2);
                LDSM_X4(bhi[nb * 4 + 0], bhi[nb * 4 + 1], bhi[nb * 4 + 2], bhi[nb * 4 + 3],
                        st + SB_HI + off);
                LDSM_X4(blo[nb * 4 + 0], blo[nb * 4 + 1], blo[nb * 4 + 2], blo[nb * 4 + 3],
                        st + SB_LO + off);
            }
#pragma unroll
            for (int mf = 0; mf < 2; mf++) {
                uint32_t off = SW64((ar + mf * 16) * 64 + ac * 2);
                LDSM_X4(ah[mf * 4 + 0], ah[mf * 4 + 1], ah[mf * 4 + 2], ah[mf * 4 + 3],
                        st + SA_HI + off);
                LDSM_X4(al[mf * 4 + 0], al[mf * 4 + 1], al[mf * 4 + 2], al[mf * 4 + 3],
                        st + SA_LO + off);
            }
#pragma unroll
            for (int mf = 0; mf < 2; mf++)
#pragma unroll
                for (int nf = 0; nf < 4; nf++) {
                    int bi = (nf >> 1) * 4 + (nf & 1) * 2;
                    MMA16816(acc[mf][nf], ah[mf * 4], ah[mf * 4 + 1], ah[mf * 4 + 2],
                             ah[mf * 4 + 3], bhi[bi], bhi[bi + 1]);
                    MMA16816(acc[mf][nf], ah[mf * 4], ah[mf * 4 + 1], ah[mf * 4 + 2],
                             ah[mf * 4 + 3], blo[bi], blo[bi + 1]);
                    MMA16816(acc[mf][nf], al[mf * 4], al[mf * 4 + 1], al[mf * 4 + 2],
                             al[mf * 4 + 3], bhi[bi], bhi[bi + 1]);
                }
        }
        __syncthreads();
    }

    // epilogue
#pragma unroll
    for (int mf = 0; mf < 2; mf++) {
        int r = m0 + wm + mf * 16 + (lane >> 2);
#pragma unroll
        for (int nf = 0; nf < 4; nf++) {
            int col = n0 + wn + nf * 8 + (lane & 3) * 2;
            float a0 = acc[mf][nf][0], a1 = acc[mf][nf][1];
            float a2 = acc[mf][nf][2], a3 = acc[mf][nf][3];
            if (HALF_OUT) {
                if (r < Mr) {
                    __half h0 = __float2half_rn(a0), h1 = __float2half_rn(a1);
                    *(uint32_t*)&Chi[(size_t)r * Nc + col] =
                        (uint32_t)__half_as_ushort(h0) | ((uint32_t)__half_as_ushort(h1) << 16);
                    *(uint32_t*)&Clo[(size_t)r * Nc + col] =
                        pack2h(a0 - __half2float(h0), a1 - __half2float(h1));
                }
                if (r + 8 < Mr) {
                    __half h2 = __float2half_rn(a2), h3 = __float2half_rn(a3);
                    *(uint32_t*)&Chi[(size_t)(r + 8) * Nc + col] =
                        (uint32_t)__half_as_ushort(h2) | ((uint32_t)__half_as_ushort(h3) << 16);
                    *(uint32_t*)&Clo[(size_t)(r + 8) * Nc + col] =
                        pack2h(a2 - __half2float(h2), a3 - __half2float(h3));
                }
            } else {
                if (r < Mr)
                    *(float2*)&C[(size_t)r * Nc + col] = make_float2(a0, a1);
                if (r + 8 < Mr)
                    *(float2*)&C[(size_t)(r + 8) * Nc + col] = make_float2(a2, a3);
            }
        }
    }

    // fused BN column stats (padded rows contribute exactly 0)
#pragma unroll
    for (int nf = 0; nf < 4; nf++) {
        float s0 = 0.f, s1 = 0.f, q0 = 0.f, q1 = 0.f;
#pragma unroll
        for (int mf = 0; mf < 2; mf++) {
            float a0 = acc[mf][nf][0], a1 = acc[mf][nf][1];
            float a2 = acc[mf][nf][2], a3 = acc[mf][nf][3];
            s0 += a0 + a2; s1 += a1 + a3;
            q0 += a0 * a0 + a2 * a2; q1 += a1 * a1 + a3 * a3;
        }
#pragma unroll
        for (int off = 4; off < 32; off <<= 1) {
            s0 += __shfl_xor_sync(0xffffffff, s0, off);
            s1 += __shfl_xor_sync(0xffffffff, s1, off);
            q0 += __shfl_xor_sync(0xffffffff, q0, off);
            q1 += __shfl_xor_sync(0xffffffff, q1, off);
        }
        if (lane < 4) {
            int c = n0 + wn + nf * 8 + lane * 2;
            atomicAdd(&sums[c], s0);
            atomicAdd(&sums[c + 1], s1);
            atomicAdd(&sums[Nc + c], q0);
            atomicAdd(&sums[Nc + c + 1], q1);
        }
    }
}

// ---------------- final BN apply (inline scale/shift) ------------------------
__global__ void bn_apply_final_k(const float* __restrict__ X,
                                 const float* __restrict__ sums,
                                 const float* __restrict__ g,
                                 const float* __restrict__ b,
                                 float* __restrict__ Y) {
    __shared__ float s_sc[Ee], s_sh[Ee];
    for (int c = threadIdx.x; c < Ee; c += blockDim.x) {
        float mean = sums[c] * (1.f / Nn);
        float var = sums[Ee + c] * (1.f / Nn) - mean * mean;
        float s = g[c] * rsqrtf(var + 1e-5f);
        s_sc[c] = s;
        s_sh[c] = b[c] - mean * s;
    }
    __syncthreads();
    int i = blockIdx.x * blockDim.x + threadIdx.x;
    if (i >= Nn * Ee / 4) return;
    int c = (i & 63) * 4;
    float4 v = ((const float4*)X)[i];
    v.x = fmaf(v.x, s_sc[c + 0], s_sh[c + 0]);
    v.y = fmaf(v.y, s_sc[c + 1], s_sh[c + 1]);
    v.z = fmaf(v.z, s_sc[c + 2], s_sh[c + 2]);
    v.w = fmaf(v.w, s_sc[c + 3], s_sh[c + 3]);
    ((float4*)Y)[i] = v;
}

// ---------------- host orchestration ----------------------------------------
struct Scratch {
    float *h, *hB, *sumsH, *sumsE, *mask;
    __half *A1hi, *A1lo, *t1hi, *t1lo, *A2hi, *A2lo;
    __half *W1Thi, *W1Tlo, *W2Thi, *W2Tlo;
    int *offs_b, *offs_l, *offs_r, *src_b, *atr_b, *src_l, *src_r;
};

extern "C" void kernel_launch(void* const* d_in, const int* in_sizes, int n_in,
                              void* d_out, int out_size) {
    const int* x       = (const int*)d_in[0];
    const int* ei      = (const int*)d_in[1];
    const int* ea      = (const int*)d_in[2];
    const int* xei     = (const int*)d_in[3];
    const void* mask_raw = d_in[4];
    const float* atom_emb = (const float*)d_in[5];
    const float* bond_emb = (const float*)d_in[6];
    const float* eps_m = (const float*)d_in[7];
    const float* W1_m  = (const float*)d_in[8];
    const float* g1_m  = (const float*)d_in[10];
    const float* be1_m = (const float*)d_in[11];
    const float* W2_m  = (const float*)d_in[12];
    const float* bn_g_m = (const float*)d_in[14];
    const float* bn_b_m = (const float*)d_in[15];
    const float* eps_e = (const float*)d_in[16];
    const float* W1_e  = (const float*)d_in[17];
    const float* g1_e  = (const float*)d_in[18];
    const float* be1_e = (const float*)d_in[19];
    const float* W2_e  = (const float*)d_in[20];
    const float* bn_g_e = (const float*)d_in[21];
    const float* bn_b_e = (const float*)d_in[22];

    const int M  = in_sizes[1] / 2;
    const int MX = in_sizes[3] / 2;

    cudaFuncSetAttribute(mma_gemm_k<true>, cudaFuncAttributeMaxDynamicSharedMemorySize, GEMM_SMEM);
    cudaFuncSetAttribute(mma_gemm_k<false>, cudaFuncAttributeMaxDynamicSharedMemorySize, GEMM_SMEM);

    Scratch S;
    cudaGetSymbolAddress((void**)&S.h, g_h);
    cudaGetSymbolAddress((void**)&S.hB, g_hB);
    cudaGetSymbolAddress((void**)&S.sumsH, g_sumsH);
    cudaGetSymbolAddress((void**)&S.sumsE, g_sumsE);
    cudaGetSymbolAddress((void**)&S.mask, g_mask);
    cudaGetSymbolAddress((void**)&S.A1hi, g_A1hi);
    cudaGetSymbolAddress((void**)&S.A1lo, g_A1lo);
    cudaGetSymbolAddress((void**)&S.t1hi, g_t1hi);
    cudaGetSymbolAddress((void**)&S.t1lo, g_t1lo);
    cudaGetSymbolAddress((void**)&S.A2hi, g_A2hi);
    cudaGetSymbolAddress((void**)&S.A2lo, g_A2lo);
    cudaGetSymbolAddress((void**)&S.W1Thi, g_W1Thi);
    cudaGetSymbolAddress((void**)&S.W1Tlo, g_W1Tlo);
    cudaGetSymbolAddress((void**)&S.W2Thi, g_W2Thi);
    cudaGetSymbolAddress((void**)&S.W2Tlo, g_W2Tlo);
    cudaGetSymbolAddress((void**)&S.offs_b, g_offs_b);
    cudaGetSymbolAddress((void**)&S.offs_l, g_offs_l);
    cudaGetSymbolAddress((void**)&S.offs_r, g_offs_r);
    cudaGetSymbolAddress((void**)&S.src_b, g_src_b);
    cudaGetSymbolAddress((void**)&S.atr_b, g_atr_b);
    cudaGetSymbolAddress((void**)&S.src_l, g_src_l);
    cudaGetSymbolAddress((void**)&S.src_r, g_src_r);

    const int TOT = M + 2 * MX;

    detect_mask_k<<<1, 256>>>(mask_raw);
    setup_k<<<79, 256>>>(mask_raw);
    atom_encode_k<<<Nn, 64>>>(x, atom_emb, S.h);
    hist_all_k<<<(TOT + 255) / 256, 256>>>(ei, xei, M, MX);
    scan_all_k<<<3, 1024>>>();
    fill_all_k<<<(TOT + 255) / 256, 256>>>(ei, xei, ea, M, MX);
    wsplit_all_k<<<dim3(16, 16, 2 * NCONV), dim3(32, 8)>>>(W1_m, W1_e, W2_m, W2_e);

    const float* prev_sums = nullptr;
    const float* prev_g = nullptr;
    const float* prev_b = nullptr;

    dim3 g1d(Hh / 128, (Nn + 63) / 64);
    dim3 g2d(Ee / 128, (Nn + 63) / 64);

    for (int l = 0; l < Ll; l++) {
        for (int j = 0; j < 3; j++) {
            int c = l * 3 + j;
            const float* Xin = (c == 0) ? S.h : S.hB;
            const float* eps;
            const float* g1;
            const float* be1;
            const float* bng;
            const float* bnb;
            const float* mask = nullptr;
            const int* offs;
            const int* csrc;
            const int* catr = nullptr;
            if (j == 0) {
                eps = eps_m + l;
                g1 = g1_m + (size_t)l * Hh;  be1 = be1_m + (size_t)l * Hh;
                bng = bn_g_m + (size_t)l * Ee; bnb = bn_b_m + (size_t)l * Ee;
                offs = S.offs_b; csrc = S.src_b; catr = S.atr_b;
            } else {
                int s = l * 2 + (j - 1);
                eps = eps_e + s;
                g1 = g1_e + (size_t)s * Hh;  be1 = be1_e + (size_t)s * Hh;
                bng = bn_g_e + (size_t)s * Ee; bnb = bn_b_e + (size_t)s * Ee;
                offs = (j == 1) ? S.offs_l : S.offs_r;
                csrc = (j == 1) ? S.src_l : S.src_r;
                mask = S.mask;
            }
            float* sumsH_c = S.sumsH + (size_t)c * 2 * Hh;
            float* sumsE_c = S.sumsE + (size_t)c * 2 * Ee;

            if (catr)
                gather_k<true><<<(Nn + 7) / 8, 256>>>(Xin, prev_sums, prev_g, prev_b,
                                                      offs, csrc, catr, bond_emb,
                                                      mask, eps, S.A1hi, S.A1lo);
            else
                gather_k<false><<<(Nn + 7) / 8, 256>>>(Xin, prev_sums, prev_g, prev_b,
                                                       offs, csrc, nullptr, nullptr,
                                                       mask, eps, S.A1hi, S.A1lo);

            mma_gemm_k<true><<<g1d, 256, GEMM_SMEM>>>(
                S.A1hi, S.A1lo,
                S.W1Thi + (size_t)c * Hh * Ee, S.W1Tlo + (size_t)c * Hh * Ee,
                nullptr, S.t1hi, S.t1lo, sumsH_c, Nn, Ee, Hh);

            bnrelu_split_k<<<2500, 256>>>(
                S.t1hi, S.t1lo, sumsH_c, g1, be1, S.A2hi, S.A2lo);

            mma_gemm_k<false><<<g2d, 256, GEMM_SMEM>>>(
                S.A2hi, S.A2lo,
                S.W2Thi + (size_t)c * Ee * Hh, S.W2Tlo + (size_t)c * Ee * Hh,
                S.hB, nullptr, nullptr, sumsE_c, Nn, Hh, Ee);

            prev_sums = sumsE_c;
            prev_g = bng;
            prev_b = bnb;
        }
    }

    bn_apply_final_k<<<(Nn * Ee / 4 + 255) / 256, 256>>>(S.hB, prev_sums, prev_g, prev_b,
                                                         (float*)d_out);
}

// round 15
// speedup vs baseline: 1.1025x; 1.0184x over previous
#include <cuda_runtime.h>
#include <cuda_fp16.h>
#include <cstddef>
#include <cstdint>

#define Nn 20000
#define Ee 256
#define Hh 512
#define Ll 5
#define NCONV 15
#define MB_CAP 320000
#define MX_CAP 160000

// ---------------- scratch (device globals; no allocations allowed) ----------
__device__ float g_h[Nn * Ee];
__device__ float g_hB[Nn * Ee];
__device__ float g_sumsH[NCONV * 2 * Hh];
__device__ float g_sumsE[NCONV * 2 * Ee];
__device__ float g_mask[Nn];
__device__ int   g_mask_dtype;

__device__ __half g_A1hi[Nn * Ee];
__device__ __half g_A1lo[Nn * Ee];
__device__ __half g_t1hi[Nn * Hh];
__device__ __half g_t1lo[Nn * Hh];
__device__ __half g_A2hi[Nn * Hh];
__device__ __half g_A2lo[Nn * Hh];
__device__ __half g_W1Thi[NCONV * Hh * Ee];
__device__ __half g_W1Tlo[NCONV * Hh * Ee];
__device__ __half g_W2Thi[NCONV * Ee * Hh];
__device__ __half g_W2Tlo[NCONV * Ee * Hh];

__device__ int g_deg[3 * Nn];
__device__ int g_cur[3 * Nn];
__device__ int g_offs_b[Nn + 1], g_offs_l[Nn + 1], g_offs_r[Nn + 1];
__device__ int g_src_b[MB_CAP];
__device__ int g_atr_b[MB_CAP];
__device__ int g_src_l[MX_CAP];
__device__ int g_src_r[MX_CAP];

// ---------------- helpers ----------------------------------------------------
__device__ __forceinline__ uint32_t smem_u32(const void* p) {
    uint32_t a;
    asm("{ .reg .u64 t; cvta.to.shared.u64 t, %1; cvt.u32.u64 %0, t; }" : "=r"(a) : "l"(p));
    return a;
}
#define SW64(off)  ((off) ^ (((off) >> 3) & 0x30))

#define LDSM_X4(r0, r1, r2, r3, addr) \
    asm volatile("ldmatrix.sync.aligned.m8n8.x4.shared.b16 {%0,%1,%2,%3}, [%4];" \
                 : "=r"(r0), "=r"(r1), "=r"(r2), "=r"(r3) : "r"(addr))

#define MMA16816(d, a0, a1, a2, a3, b0, b1) \
    asm volatile("mma.sync.aligned.m16n8k16.row.col.f32.f16.f16.f32 " \
                 "{%0,%1,%2,%3}, {%4,%5,%6,%7}, {%8,%9}, {%0,%1,%2,%3};" \
                 : "+f"((d)[0]), "+f"((d)[1]), "+f"((d)[2]), "+f"((d)[3]) \
                 : "r"(a0), "r"(a1), "r"(a2), "r"(a3), "r"(b0), "r"(b1))

#define CP_ASYNC16(dst, src, sz) \
    asm volatile("cp.async.cg.shared.global [%0], [%1], 16, %2;" \
                 :: "r"(dst), "l"(src), "r"(sz))
#define CP_COMMIT() asm volatile("cp.async.commit_group;" ::: "memory")
#define CP_WAIT0() asm volatile("cp.async.wait_group 0;" ::: "memory")
#define CP_WAIT2() asm volatile("cp.async.wait_group 2;" ::: "memory")

__device__ __forceinline__ uint32_t pack2h(float a, float b) {
    __half ha = __float2half_rn(a), hb = __float2half_rn(b);
    return (uint32_t)__half_as_ushort(ha) | ((uint32_t)__half_as_ushort(hb) << 16);
}

// ---------------- mask dtype detection ---------------------------------------
__global__ void detect_mask_k(const void* mask) {
    __shared__ int not_i32, not_f32;
    if (threadIdx.x == 0) { not_i32 = 0; not_f32 = 0; }
    __syncthreads();
    const unsigned* w = (const unsigned*)mask;
    int bad_i = 0, bad_f = 0;
    for (int i = threadIdx.x; i < Nn / 4; i += blockDim.x) {
        unsigned v = w[i];
        if (v > 1u) bad_i = 1;
        if (v != 0u && v != 0x3F800000u) bad_f = 1;
    }
    if (bad_i) atomicOr(&not_i32, 1);
    if (bad_f) atomicOr(&not_f32, 1);
    __syncthreads();
    if (threadIdx.x == 0) {
        if (!not_i32) g_mask_dtype = 0;
        else if (!not_f32) g_mask_dtype = 1;
        else g_mask_dtype = 2;
    }
}

__global__ void setup_k(const void* mask) {
    int i = blockIdx.x * blockDim.x + threadIdx.x;
    int stride = gridDim.x * blockDim.x;
    int dt = g_mask_dtype;
    for (int n = i; n < Nn; n += stride) {
        float m;
        if (dt == 0)      m = (((const int*)mask)[n] != 0) ? 1.f : 0.f;
        else if (dt == 1) m = (((const float*)mask)[n] != 0.f) ? 1.f : 0.f;
        else              m = (((const unsigned char*)mask)[n] != 0) ? 1.f : 0.f;
        g_mask[n] = m;
    }
    for (int n = i; n < 3 * Nn; n += stride) g_deg[n] = 0;
    for (int n = i; n < NCONV * 2 * Hh; n += stride) g_sumsH[n] = 0.f;
    for (int n = i; n < NCONV * 2 * Ee; n += stride) g_sumsE[n] = 0.f;
}

// ---------------- atom encoder ------------------------------------------------
__global__ void atom_encode_k(const int* __restrict__ x,
                              const float* __restrict__ emb,
                              float* __restrict__ h) {
    int n = blockIdx.x;
    int t = threadIdx.x;
    float4 acc = make_float4(0.f, 0.f, 0.f, 0.f);
#pragma unroll
    for (int f = 0; f < 9; f++) {
        int idx = __ldg(&x[n * 9 + f]);
        const float4* row = (const float4*)&emb[((size_t)(f * 128 + idx)) * Ee];
        float4 v = row[t];
        acc.x += v.x; acc.y += v.y; acc.z += v.z; acc.w += v.w;
    }
    ((float4*)h)[(size_t)n * (Ee / 4) + t] = acc;
}

// ---------------- CSR build (fused across 3 orientations) --------------------
__global__ void hist_all_k(const int* __restrict__ ei, const int* __restrict__ xei,
                           int M, int MX) {
    int e = blockIdx.x * blockDim.x + threadIdx.x;
    if (e < M) atomicAdd(&g_deg[ei[M + e]], 1);
    else if (e < M + MX) atomicAdd(&g_deg[Nn + xei[MX + (e - M)]], 1);
    else if (e < M + 2 * MX) atomicAdd(&g_deg[2 * Nn + xei[e - M - MX]], 1);
}

__global__ void scan_all_k() {
    int which = blockIdx.x;
    const int* deg = g_deg + which * Nn;
    int* cur = g_cur + which * Nn;
    int* offs = (which == 0) ? g_offs_b : (which == 1) ? g_offs_l : g_offs_r;
    __shared__ int ssum[1024];
    int t = threadIdx.x;
    const int PER = (Nn + 1023) / 1024;  // 20
    int loc[20];
    int s = 0;
#pragma unroll
    for (int i = 0; i < PER; i++) {
        int idx = t * PER + i;
        int v = (idx < Nn) ? deg[idx] : 0;
        loc[i] = s;
        s += v;
    }
    ssum[t] = s;
    __syncthreads();
    for (int off = 1; off < 1024; off <<= 1) {
        int v = (t >= off) ? ssum[t - off] : 0;
        __syncthreads();
        ssum[t] += v;
        __syncthreads();
    }
    int pre = (t > 0) ? ssum[t - 1] : 0;
#pragma unroll
    for (int i = 0; i < PER; i++) {
        int idx = t * PER + i;
        if (idx < Nn) {
            offs[idx] = pre + loc[i];
            cur[idx] = pre + loc[i];
        }
    }
    if (t == 1023) offs[Nn] = ssum[1023];
}

__global__ void fill_all_k(const int* __restrict__ ei, const int* __restrict__ xei,
                           const int* __restrict__ ea, int M, int MX) {
    int e = blockIdx.x * blockDim.x + threadIdx.x;
    if (e < M) {
        int p = atomicAdd(&g_cur[ei[M + e]], 1);
        if (p < MB_CAP) {
            g_src_b[p] = ei[e];
            g_atr_b[p] = ea[e * 3] | (ea[e * 3 + 1] << 3) | (ea[e * 3 + 2] << 6);
        }
    } else if (e < M + MX) {
        int j = e - M;
        int p = atomicAdd(&g_cur[Nn + xei[MX + j]], 1);
        if (p < MX_CAP) g_src_l[p] = xei[j];
    } else if (e < M + 2 * MX) {
        int j = e - M - MX;
        int p = atomicAdd(&g_cur[2 * Nn + xei[j]], 1);
        if (p < MX_CAP) g_src_r[p] = xei[MX + j];
    }
}

// ---------------- merged weight transpose + fp16 split ------------------------
__global__ void wsplit_all_k(const float* __restrict__ W1m, const float* __restrict__ W1e,
                             const float* __restrict__ W2m, const float* __restrict__ W2e) {
    int z = blockIdx.z;
    int which = z / NCONV;
    int c = z % NCONV;
    int l = c / 3, j = c % 3;
    const float* W;
    __half *Thi, *Tlo;
    int K, N;
    if (which == 0) {
        K = Ee; N = Hh;
        W = j ? W1e + (size_t)(l * 2 + j - 1) * Ee * Hh : W1m + (size_t)l * Ee * Hh;
        Thi = g_W1Thi + (size_t)c * Hh * Ee;
        Tlo = g_W1Tlo + (size_t)c * Hh * Ee;
    } else {
        K = Hh; N = Ee;
        W = j ? W2e + (size_t)(l * 2 + j - 1) * Hh * Ee : W2m + (size_t)l * Hh * Ee;
        Thi = g_W2Thi + (size_t)c * Ee * Hh;
        Tlo = g_W2Tlo + (size_t)c * Ee * Hh;
    }
    int kb = blockIdx.x * 32, nb = blockIdx.y * 32;
    if (kb >= K || nb >= N) return;
    __shared__ float t[32][33];
    int tx = threadIdx.x, ty = threadIdx.y;
    for (int i = ty; i < 32; i += 8)
        t[i][tx] = W[(size_t)(kb + i) * N + nb + tx];
    __syncthreads();
    for (int i = ty; i < 32; i += 8) {
        float v = t[tx][i];
        __half hi = __float2half_rn(v);
        float lo = v - __half2float(hi);
        Thi[(size_t)(nb + i) * K + kb + tx] = hi;
        Tlo[(size_t)(nb + i) * K + kb + tx] = __float2half_rn(lo);
    }
}

// ---------------- fused CSR gather (edge loop unrolled x2) --------------------
template <bool BOND>
__global__ __launch_bounds__(256) void gather_k(
    const float* __restrict__ Xin,
    const float* __restrict__ insums, const float* __restrict__ ing,
    const float* __restrict__ inb,
    const int* __restrict__ offs, const int* __restrict__ csrc,
    const int* __restrict__ catr, const float* __restrict__ bemb,
    const float* __restrict__ mask, const float* __restrict__ eps,
    __half* __restrict__ Ahi, __half* __restrict__ Alo) {
    __shared__ float s_sc[Ee], s_sh[Ee];
    for (int c = threadIdx.x; c < Ee; c += blockDim.x) {
        if (insums) {
            float mean = insums[c] * (1.f / Nn);
            float var = insums[Ee + c] * (1.f / Nn) - mean * mean;
            float s = ing[c] * rsqrtf(var + 1e-5f);
            s_sc[c] = s;
            s_sh[c] = inb[c] - mean * s;
        } else {
            s_sc[c] = 1.f;
            s_sh[c] = 0.f;
        }
    }
    __syncthreads();

    int node = blockIdx.x * 8 + (threadIdx.x >> 5);
    if (node >= Nn) return;
    int lane = threadIdx.x & 31;
    int c0 = lane * 8;
    float flo = insums ? 0.f : -3.4e38f;

    float4 sc0 = *(const float4*)&s_sc[c0], sc1 = *(const float4*)&s_sc[c0 + 4];
    float4 sh0 = *(const float4*)&s_sh[c0], sh1 = *(const float4*)&s_sh[c0 + 4];

    float a0 = 0.f, a1 = 0.f, a2 = 0.f, a3 = 0.f, a4 = 0.f, a5 = 0.f, a6 = 0.f, a7 = 0.f;
    int e0 = __ldg(&offs[node]), e1 = __ldg(&offs[node + 1]);

    int e = e0;
    for (; e + 2 <= e1; e += 2) {
        int sA = __ldg(&csrc[e]);
        int sB = __ldg(&csrc[e + 1]);
        const float4* xrA = (const float4*)&Xin[(size_t)sA * Ee + c0];
        const float4* xrB = (const float4*)&Xin[(size_t)sB * Ee + c0];
        float4 xA0 = __ldg(xrA), xA1 = __ldg(xrA + 1);
        float4 xB0 = __ldg(xrB), xB1 = __ldg(xrB + 1);
        float4 bA0, bA1, bB0, bB1;
        if (BOND) {
            int mtA = __ldg(&catr[e]);
            int mtB = __ldg(&catr[e + 1]);
            const float4* pA0 = (const float4*)&bemb[(size_t)(mtA & 7) * Ee + c0];
            const float4* pA1 = (const float4*)&bemb[(size_t)(8 + ((mtA >> 3) & 7)) * Ee + c0];
            const float4* pA2 = (const float4*)&bemb[(size_t)(16 + ((mtA >> 6) & 7)) * Ee + c0];
            const float4* pB0 = (const float4*)&bemb[(size_t)(mtB & 7) * Ee + c0];
            const float4* pB1 = (const float4*)&bemb[(size_t)(8 + ((mtB >> 3) & 7)) * Ee + c0];
            const float4* pB2 = (const float4*)&bemb[(size_t)(16 + ((mtB >> 6) & 7)) * Ee + c0];
            float4 a00 = __ldg(pA0), a01 = __ldg(pA0 + 1);
            float4 a10 = __ldg(pA1), a11 = __ldg(pA1 + 1);
            float4 a20 = __ldg(pA2), a21 = __ldg(pA2 + 1);
            float4 b00 = __ldg(pB0), b01 = __ldg(pB0 + 1);
            float4 b10 = __ldg(pB1), b11 = __ldg(pB1 + 1);
            float4 b20 = __ldg(pB2), b21 = __ldg(pB2 + 1);
            bA0.x = a00.x + a10.x + a20.x; bA0.y = a00.y + a10.y + a20.y;
            bA0.z = a00.z + a10.z + a20.z; bA0.w = a00.w + a10.w + a20.w;
            bA1.x = a01.x + a11.x + a21.x; bA1.y = a01.y + a11.y + a21.y;
            bA1.z = a01.z + a11.z + a21.z; bA1.w = a01.w + a11.w + a21.w;
            bB0.x = b00.x + b10.x + b20.x; bB0.y = b00.y + b10.y + b20.y;
            bB0.z = b00.z + b10.z + b20.z; bB0.w = b00.w + b10.w + b20.w;
            bB1.x = b01.x + b11.x + b21.x; bB1.y = b01.y + b11.y + b21.y;
            bB1.z = b01.z + b11.z + b21.z; bB1.w = b01.w + b11.w + b21.w;
        }
        {
            float v0 = fmaxf(fmaf(xA0.x, sc0.x, sh0.x), flo);
            float v1 = fmaxf(fmaf(xA0.y, sc0.y, sh0.y), flo);
            float v2 = fmaxf(fmaf(xA0.z, sc0.z, sh0.z), flo);
            float v3 = fmaxf(fmaf(xA0.w, sc0.w, sh0.w), flo);
            float v4 = fmaxf(fmaf(xA1.x, sc1.x, sh1.x), flo);
            float v5 = fmaxf(fmaf(xA1.y, sc1.y, sh1.y), flo);
            float v6 = fmaxf(fmaf(xA1.z, sc1.z, sh1.z), flo);
            float v7 = fmaxf(fmaf(xA1.w, sc1.w, sh1.w), flo);
            if (BOND) {
                v0 += bA0.x; v1 += bA0.y; v2 += bA0.z; v3 += bA0.w;
                v4 += bA1.x; v5 += bA1.y; v6 += bA1.z; v7 += bA1.w;
            }
            a0 += fmaxf(v0, 0.f); a1 += fmaxf(v1, 0.f);
            a2 += fmaxf(v2, 0.f); a3 += fmaxf(v3, 0.f);
            a4 += fmaxf(v4, 0.f); a5 += fmaxf(v5, 0.f);
            a6 += fmaxf(v6, 0.f); a7 += fmaxf(v7, 0.f);
        }
        {
            float v0 = fmaxf(fmaf(xB0.x, sc0.x, sh0.x), flo);
            float v1 = fmaxf(fmaf(xB0.y, sc0.y, sh0.y), flo);
            float v2 = fmaxf(fmaf(xB0.z, sc0.z, sh0.z), flo);
            float v3 = fmaxf(fmaf(xB0.w, sc0.w, sh0.w), flo);
            float v4 = fmaxf(fmaf(xB1.x, sc1.x, sh1.x), flo);
            float v5 = fmaxf(fmaf(xB1.y, sc1.y, sh1.y), flo);
            float v6 = fmaxf(fmaf(xB1.z, sc1.z, sh1.z), flo);
            float v7 = fmaxf(fmaf(xB1.w, sc1.w, sh1.w), flo);
            if (BOND) {
                v0 += bB0.x; v1 += bB0.y; v2 += bB0.z; v3 += bB0.w;
                v4 += bB1.x; v5 += bB1.y; v6 += bB1.z; v7 += bB1.w;
            }
            a0 += fmaxf(v0, 0.f); a1 += fmaxf(v1, 0.f);
            a2 += fmaxf(v2, 0.f); a3 += fmaxf(v3, 0.f);
            a4 += fmaxf(v4, 0.f); a5 += fmaxf(v5, 0.f);
            a6 += fmaxf(v6, 0.f); a7 += fmaxf(v7, 0.f);
        }
    }
    for (; e < e1; e++) {
        int s = __ldg(&csrc[e]);
        const float4* xr = (const float4*)&Xin[(size_t)s * Ee + c0];
        float4 x0 = __ldg(xr), x1 = __ldg(xr + 1);
        float v0 = fmaxf(fmaf(x0.x, sc0.x, sh0.x), flo);
        float v1 = fmaxf(fmaf(x0.y, sc0.y, sh0.y), flo);
        float v2 = fmaxf(fmaf(x0.z, sc0.z, sh0.z), flo);
        float v3 = fmaxf(fmaf(x0.w, sc0.w, sh0.w), flo);
        float v4 = fmaxf(fmaf(x1.x, sc1.x, sh1.x), flo);
        float v5 = fmaxf(fmaf(x1.y, sc1.y, sh1.y), flo);
        float v6 = fmaxf(fmaf(x1.z, sc1.z, sh1.z), flo);
        float v7 = fmaxf(fmaf(x1.w, sc1.w, sh1.w), flo);
        if (BOND) {
            int mt = __ldg(&catr[e]);
            const float4* b0 = (const float4*)&bemb[(size_t)(mt & 7) * Ee + c0];
            const float4* b1 = (const float4*)&bemb[(size_t)(8 + ((mt >> 3) & 7)) * Ee + c0];
            const float4* b2 = (const float4*)&bemb[(size_t)(16 + ((mt >> 6) & 7)) * Ee + c0];
            float4 p0 = __ldg(b0), p1 = __ldg(b0 + 1);
            float4 q0 = __ldg(b1), q1 = __ldg(b1 + 1);
            float4 r0 = __ldg(b2), r1 = __ldg(b2 + 1);
            v0 += p0.x + q0.x + r0.x; v1 += p0.y + q0.y + r0.y;
            v2 += p0.z + q0.z + r0.z; v3 += p0.w + q0.w + r0.w;
            v4 += p1.x + q1.x + r1.x; v5 += p1.y + q1.y + r1.y;
            v6 += p1.z + q1.z + r1.z; v7 += p1.w + q1.w + r1.w;
        }
        a0 += fmaxf(v0, 0.f); a1 += fmaxf(v1, 0.f);
        a2 += fmaxf(v2, 0.f); a3 += fmaxf(v3, 0.f);
        a4 += fmaxf(v4, 0.f); a5 += fmaxf(v5, 0.f);
        a6 += fmaxf(v6, 0.f); a7 += fmaxf(v7, 0.f);
    }

    const float4* xr = (const float4*)&Xin[(size_t)node * Ee + c0];
    float4 x0 = __ldg(xr), x1 = __ldg(xr + 1);
    float s0 = fmaxf(fmaf(x0.x, sc0.x, sh0.x), flo);
    float s1 = fmaxf(fmaf(x0.y, sc0.y, sh0.y), flo);
    float s2 = fmaxf(fmaf(x0.z, sc0.z, sh0.z), flo);
    float s3 = fmaxf(fmaf(x0.w, sc0.w, sh0.w), flo);
    float s4 = fmaxf(fmaf(x1.x, sc1.x, sh1.x), flo);
    float s5 = fmaxf(fmaf(x1.y, sc1.y, sh1.y), flo);
    float s6 = fmaxf(fmaf(x1.z, sc1.z, sh1.z), flo);
    float s7 = fmaxf(fmaf(x1.w, sc1.w, sh1.w), flo);
    float m = mask ? __ldg(&mask[node]) : 1.f;
    float ef = (1.f + __ldg(eps)) * m;
    float p0 = fmaf(ef, s0, a0), p1 = fmaf(ef, s1, a1);
    float p2 = fmaf(ef, s2, a2), p3 = fmaf(ef, s3, a3);
    float p4 = fmaf(ef, s4, a4), p5 = fmaf(ef, s5, a5);
    float p6 = fmaf(ef, s6, a6), p7 = fmaf(ef, s7, a7);
    uint4 hi, lo;
    {
        __half h0 = __float2half_rn(p0), h1 = __float2half_rn(p1);
        __half h2 = __float2half_rn(p2), h3 = __float2half_rn(p3);
        __half h4 = __float2half_rn(p4), h5 = __float2half_rn(p5);
        __half h6 = __float2half_rn(p6), h7 = __float2half_rn(p7);
        hi.x = (uint32_t)__half_as_ushort(h0) | ((uint32_t)__half_as_ushort(h1) << 16);
        hi.y = (uint32_t)__half_as_ushort(h2) | ((uint32_t)__half_as_ushort(h3) << 16);
        hi.z = (uint32_t)__half_as_ushort(h4) | ((uint32_t)__half_as_ushort(h5) << 16);
        hi.w = (uint32_t)__half_as_ushort(h6) | ((uint32_t)__half_as_ushort(h7) << 16);
        lo.x = pack2h(p0 - __half2float(h0), p1 - __half2float(h1));
        lo.y = pack2h(p2 - __half2float(h2), p3 - __half2float(h3));
        lo.z = pack2h(p4 - __half2float(h4), p5 - __half2float(h5));
        lo.w = pack2h(p6 - __half2float(h6), p7 - __half2float(h7));
    }
    *(uint4*)&Ahi[(size_t)node * Ee + c0] = hi;
    *(uint4*)&Alo[(size_t)node * Ee + c0] = lo;
}

// ---------------- t1 pair -> inline BN -> relu -> split (4 elems/thread) -----
__global__ void bnrelu_split_k(const __half* __restrict__ Thi, const __half* __restrict__ Tlo,
                               const float* __restrict__ sums,
                               const float* __restrict__ g,
                               const float* __restrict__ b,
                               __half* __restrict__ Ahi, __half* __restrict__ Alo) {
    __shared__ float s_sc[Hh], s_sh[Hh];
    for (int c = threadIdx.x; c < Hh; c += blockDim.x) {
        float mean = sums[c] * (1.f / Nn);
        float var = sums[Hh + c] * (1.f / Nn) - mean * mean;
        float s = g[c] * rsqrtf(var + 1e-5f);
        s_sc[c] = s;
        s_sh[c] = b[c] - mean * s;
    }
    __syncthreads();
#pragma unroll
    for (int u = 0; u < 4; u++) {
        int i = blockIdx.x * 1024 + u * 256 + threadIdx.x;
        if (i >= Nn * Hh / 4) return;
        int c = (i & (Hh / 4 - 1)) * 4;
        uint2 vh = ((const uint2*)Thi)[i];
        uint2 vl = ((const uint2*)Tlo)[i];
        float2 h0 = __half22float2(*(__half2*)&vh.x);
        float2 h1 = __half22float2(*(__half2*)&vh.y);
        float2 l0 = __half22float2(*(__half2*)&vl.x);
        float2 l1 = __half22float2(*(__half2*)&vl.y);
        float x0 = h0.x + l0.x, x1 = h0.y + l0.y, x2 = h1.x + l1.x, x3 = h1.y + l1.y;
        x0 = fmaxf(fmaf(x0, s_sc[c + 0], s_sh[c + 0]), 0.f);
        x1 = fmaxf(fmaf(x1, s_sc[c + 1], s_sh[c + 1]), 0.f);
        x2 = fmaxf(fmaf(x2, s_sc[c + 2], s_sh[c + 2]), 0.f);
        x3 = fmaxf(fmaf(x3, s_sc[c + 3], s_sh[c + 3]), 0.f);
        __half q0 = __float2half_rn(x0), q1 = __float2half_rn(x1);
        __half q2 = __float2half_rn(x2), q3 = __float2half_rn(x3);
        uint2 hi, lo;
        hi.x = (uint32_t)__half_as_ushort(q0) | ((uint32_t)__half_as_ushort(q1) << 16);
        hi.y = (uint32_t)__half_as_ushort(q2) | ((uint32_t)__half_as_ushort(q3) << 16);
        lo.x = pack2h(x0 - __half2float(q0), x1 - __half2float(q1));
        lo.y = pack2h(x2 - __half2float(q2), x3 - __half2float(q3));
        ((uint2*)Ahi)[i] = hi;
        ((uint2*)Alo)[i] = lo;
    }
}

// ---------------- mma.sync fp16x3 GEMM: 64x128 tile, K32, 4-stage, 2 CTA/SM --
// One __syncthreads per iteration: passing the top barrier of iter kt+1 implies
// all warps finished computing tile kt, so issuing into stage (kt+4)%4 == kt%4
// afterwards is race-free.
#define SA_HI 0
#define SA_LO 4096
#define SB_HI 8192
#define SB_LO 16384
#define STAGE_BYTES 24576
#define GEMM_SMEM 98304

template <bool HALF_OUT>
__global__ __launch_bounds__(256, 2) void mma_gemm_k(
    const __half* __restrict__ Ahi, const __half* __restrict__ Alo,
    const __half* __restrict__ Bhi, const __half* __restrict__ Blo,
    float* __restrict__ C, __half* __restrict__ Chi, __half* __restrict__ Clo,
    float* __restrict__ sums, int Mr, int K, int Nc) {
    extern __shared__ char smem[];
    const uint32_t sb = smem_u32(smem);
    const int tid = threadIdx.x;
    const int lane = tid & 31, wid = tid >> 5;
    const int wm = (wid >> 2) * 32;
    const int wn = (wid & 3) * 32;
    const int m0 = blockIdx.y * 64;
    const int n0 = blockIdx.x * 128;
    const int nkt = K >> 5;   // K-chunks of 32 (8 or 16)

    float acc[2][4][4];
#pragma unroll
    for (int a = 0; a < 2; a++)
#pragma unroll
        for (int b = 0; b < 4; b++)
#pragma unroll
            for (int c = 0; c < 4; c++) acc[a][b][c] = 0.f;

    const int arow = tid >> 2, aq = tid & 3;
    const int brow = tid >> 1, bq = tid & 1;
    const bool arow_ok = (m0 + arow) < Mr;
    const int arow_cl = arow_ok ? (m0 + arow) : 0;
    const char* pAhi = (const char*)(Ahi + (size_t)arow_cl * K);
    const char* pAlo = (const char*)(Alo + (size_t)arow_cl * K);
    const char* pBhi = (const char*)(Bhi + (size_t)(n0 + brow) * K);
    const char* pBlo = (const char*)(Blo + (size_t)(n0 + brow) * K);
    const int asz = arow_ok ? 16 : 0;
    const uint32_t aso = SW64((uint32_t)(arow * 64 + aq * 16));
    const uint32_t bso0 = SW64((uint32_t)(brow * 64 + bq * 32));
    const uint32_t bso1 = SW64((uint32_t)(brow * 64 + bq * 32 + 16));

    auto issue = [&](int stage, int kt) {
        const size_t gk = (size_t)kt * 64;
        const uint32_t st = sb + stage * STAGE_BYTES;
        CP_ASYNC16(st + SA_HI + aso, pAhi + gk + aq * 16, asz);
        CP_ASYNC16(st + SA_LO + aso, pAlo + gk + aq * 16, asz);
        CP_ASYNC16(st + SB_HI + bso0, pBhi + gk + bq * 32, 16);
        CP_ASYNC16(st + SB_HI + bso1, pBhi + gk + bq * 32 + 16, 16);
        CP_ASYNC16(st + SB_LO + bso0, pBlo + gk + bq * 32, 16);
        CP_ASYNC16(st + SB_LO + bso1, pBlo + gk + bq * 32 + 16, 16);
    };

    issue(0, 0); CP_COMMIT();
    issue(1, 1); CP_COMMIT();
    issue(2, 2); CP_COMMIT();

    for (int kt = 0; kt < nkt; kt++) {
        if (kt + 3 < nkt) CP_WAIT2(); else CP_WAIT0();
        __syncthreads();
        if (kt + 3 < nkt) {
            issue((kt + 3) & 3, kt + 3);
            CP_COMMIT();
        }

        const uint32_t st = sb + (kt & 3) * STAGE_BYTES;
#pragma unroll
        for (int ks = 0; ks < 2; ks++) {
            const int k0 = ks * 16;
            const uint32_t ar = wm + (lane & 15);
            const uint32_t ac = k0 + ((lane >> 4) << 3);
            const uint32_t br = wn + (lane & 7) + ((lane >> 4) << 3);
            const uint32_t bc = k0 + (((lane >> 3) & 1) << 3);
            uint32_t bhi[8], blo[8], ah[8], al[8];
#pragma unroll
            for (int nb = 0; nb < 2; nb++) {
                uint32_t off = SW64((br + nb * 16) * 64 + bc * 2);
                LDSM_X4(bhi[nb * 4 + 0], bhi[nb * 4 + 1], bhi[nb * 4 + 2], bhi[nb * 4 + 3],
                        st + SB_HI + off);
                LDSM_X4(blo[nb * 4 + 0], blo[nb * 4 + 1], blo[nb * 4 + 2], blo[nb * 4 + 3],
                        st + SB_LO + off);
            }
#pragma unroll
            for (int mf = 0; mf < 2; mf++) {
                uint32_t off = SW64((ar + mf * 16) * 64 + ac * 2);
                LDSM_X4(ah[mf * 4 + 0], ah[mf * 4 + 1], ah[mf * 4 + 2], ah[mf * 4 + 3],
                        st + SA_HI + off);
                LDSM_X4(al[mf * 4 + 0], al[mf * 4 + 1], al[mf * 4 + 2], al[mf * 4 + 3],
                        st + SA_LO + off);
            }
#pragma unroll
            for (int mf = 0; mf < 2; mf++)
#pragma unroll
                for (int nf = 0; nf < 4; nf++) {
                    int bi = (nf >> 1) * 4 + (nf & 1) * 2;
                    MMA16816(acc[mf][nf], ah[mf * 4], ah[mf * 4 + 1], ah[mf * 4 + 2],
                             ah[mf * 4 + 3], bhi[bi], bhi[bi + 1]);
                    MMA16816(acc[mf][nf], ah[mf * 4], ah[mf * 4 + 1], ah[mf * 4 + 2],
                             ah[mf * 4 + 3], blo[bi], blo[bi + 1]);
                    MMA16816(acc[mf][nf], al[mf * 4], al[mf * 4 + 1], al[mf * 4 + 2],
                             al[mf * 4 + 3], bhi[bi], bhi[bi + 1]);
                }
        }
    }

    // epilogue
#pragma unroll
    for (int mf = 0; mf < 2; mf++) {
        int r = m0 + wm + mf * 16 + (lane >> 2);
#pragma unroll
        for (int nf = 0; nf < 4; nf++) {
            int col = n0 + wn + nf * 8 + (lane & 3) * 2;
            float a0 = acc[mf][nf][0], a1 = acc[mf][nf][1];
            float a2 = acc[mf][nf][2], a3 = acc[mf][nf][3];
            if (HALF_OUT) {
                if (r < Mr) {
                    __half h0 = __float2half_rn(a0), h1 = __float2half_rn(a1);
                    *(uint32_t*)&Chi[(size_t)r * Nc + col] =
                        (uint32_t)__half_as_ushort(h0) | ((uint32_t)__half_as_ushort(h1) << 16);
                    *(uint32_t*)&Clo[(size_t)r * Nc + col] =
                        pack2h(a0 - __half2float(h0), a1 - __half2float(h1));
                }
                if (r + 8 < Mr) {
                    __half h2 = __float2half_rn(a2), h3 = __float2half_rn(a3);
                    *(uint32_t*)&Chi[(size_t)(r + 8) * Nc + col] =
                        (uint32_t)__half_as_ushort(h2) | ((uint32_t)__half_as_ushort(h3) << 16);
                    *(uint32_t*)&Clo[(size_t)(r + 8) * Nc + col] =
                        pack2h(a2 - __half2float(h2), a3 - __half2float(h3));
                }
            } else {
                if (r < Mr)
                    *(float2*)&C[(size_t)r * Nc + col] = make_float2(a0, a1);
                if (r + 8 < Mr)
                    *(float2*)&C[(size_t)(r + 8) * Nc + col] = make_float2(a2, a3);
            }
        }
    }

    // fused BN column stats (padded rows contribute exactly 0)
#pragma unroll
    for (int nf = 0; nf < 4; nf++) {
        float s0 = 0.f, s1 = 0.f, q0 = 0.f, q1 = 0.f;
#pragma unroll
        for (int mf = 0; mf < 2; mf++) {
            float a0 = acc[mf][nf][0], a1 = acc[mf][nf][1];
            float a2 = acc[mf][nf][2], a3 = acc[mf][nf][3];
            s0 += a0 + a2; s1 += a1 + a3;
            q0 += a0 * a0 + a2 * a2; q1 += a1 * a1 + a3 * a3;
        }
#pragma unroll
        for (int off = 4; off < 32; off <<= 1) {
            s0 += __shfl_xor_sync(0xffffffff, s0, off);
            s1 += __shfl_xor_sync(0xffffffff, s1, off);
            q0 += __shfl_xor_sync(0xffffffff, q0, off);
            q1 += __shfl_xor_sync(0xffffffff, q1, off);
        }
        if (lane < 4) {
            int c = n0 + wn + nf * 8 + lane * 2;
            atomicAdd(&sums[c], s0);
            atomicAdd(&sums[c + 1], s1);
            atomicAdd(&sums[Nc + c], q0);
            atomicAdd(&sums[Nc + c + 1], q1);
        }
    }
}

// ---------------- final BN apply (inline scale/shift) ------------------------
__global__ void bn_apply_final_k(const float* __restrict__ X,
                                 const float* __restrict__ sums,
                                 const float* __restrict__ g,
                                 const float* __restrict__ b,
                                 float* __restrict__ Y) {
    __shared__ float s_sc[Ee], s_sh[Ee];
    for (int c = threadIdx.x; c < Ee; c += blockDim.x) {
        float mean = sums[c] * (1.f / Nn);
        float var = sums[Ee + c] * (1.f / Nn) - mean * mean;
        float s = g[c] * rsqrtf(var + 1e-5f);
        s_sc[c] = s;
        s_sh[c] = b[c] - mean * s;
    }
    __syncthreads();
    int i = blockIdx.x * blockDim.x + threadIdx.x;
    if (i >= Nn * Ee / 4) return;
    int c = (i & 63) * 4;
    float4 v = ((const float4*)X)[i];
    v.x = fmaf(v.x, s_sc[c + 0], s_sh[c + 0]);
    v.y = fmaf(v.y, s_sc[c + 1], s_sh[c + 1]);
    v.z = fmaf(v.z, s_sc[c + 2], s_sh[c + 2]);
    v.w = fmaf(v.w, s_sc[c + 3], s_sh[c + 3]);
    ((float4*)Y)[i] = v;
}

// ---------------- host orchestration ----------------------------------------
struct Scratch {
    float *h, *hB, *sumsH, *sumsE, *mask;
    __half *A1hi, *A1lo, *t1hi, *t1lo, *A2hi, *A2lo;
    __half *W1Thi, *W1Tlo, *W2Thi, *W2Tlo;
    int *offs_b, *offs_l, *offs_r, *src_b, *atr_b, *src_l, *src_r;
};

extern "C" void kernel_launch(void* const* d_in, const int* in_sizes, int n_in,
                              void* d_out, int out_size) {
    const int* x       = (const int*)d_in[0];
    const int* ei      = (const int*)d_in[1];
    const int* ea      = (const int*)d_in[2];
    const int* xei     = (const int*)d_in[3];
    const void* mask_raw = d_in[4];
    const float* atom_emb = (const float*)d_in[5];
    const float* bond_emb = (const float*)d_in[6];
    const float* eps_m = (const float*)d_in[7];
    const float* W1_m  = (const float*)d_in[8];
    const float* g1_m  = (const float*)d_in[10];
    const float* be1_m = (const float*)d_in[11];
    const float* W2_m  = (const float*)d_in[12];
    const float* bn_g_m = (const float*)d_in[14];
    const float* bn_b_m = (const float*)d_in[15];
    const float* eps_e = (const float*)d_in[16];
    const float* W1_e  = (const float*)d_in[17];
    const float* g1_e  = (const float*)d_in[18];
    const float* be1_e = (const float*)d_in[19];
    const float* W2_e  = (const float*)d_in[20];
    const float* bn_g_e = (const float*)d_in[21];
    const float* bn_b_e = (const float*)d_in[22];

    const int M  = in_sizes[1] / 2;
    const int MX = in_sizes[3] / 2;

    cudaFuncSetAttribute(mma_gemm_k<true>, cudaFuncAttributeMaxDynamicSharedMemorySize, GEMM_SMEM);
    cudaFuncSetAttribute(mma_gemm_k<false>, cudaFuncAttributeMaxDynamicSharedMemorySize, GEMM_SMEM);

    Scratch S;
    cudaGetSymbolAddress((void**)&S.h, g_h);
    cudaGetSymbolAddress((void**)&S.hB, g_hB);
    cudaGetSymbolAddress((void**)&S.sumsH, g_sumsH);
    cudaGetSymbolAddress((void**)&S.sumsE, g_sumsE);
    cudaGetSymbolAddress((void**)&S.mask, g_mask);
    cudaGetSymbolAddress((void**)&S.A1hi, g_A1hi);
    cudaGetSymbolAddress((void**)&S.A1lo, g_A1lo);
    cudaGetSymbolAddress((void**)&S.t1hi, g_t1hi);
    cudaGetSymbolAddress((void**)&S.t1lo, g_t1lo);
    cudaGetSymbolAddress((void**)&S.A2hi, g_A2hi);
    cudaGetSymbolAddress((void**)&S.A2lo, g_A2lo);
    cudaGetSymbolAddress((void**)&S.W1Thi, g_W1Thi);
    cudaGetSymbolAddress((void**)&S.W1Tlo, g_W1Tlo);
    cudaGetSymbolAddress((void**)&S.W2Thi, g_W2Thi);
    cudaGetSymbolAddress((void**)&S.W2Tlo, g_W2Tlo);
    cudaGetSymbolAddress((void**)&S.offs_b, g_offs_b);
    cudaGetSymbolAddress((void**)&S.offs_l, g_offs_l);
    cudaGetSymbolAddress((void**)&S.offs_r, g_offs_r);
    cudaGetSymbolAddress((void**)&S.src_b, g_src_b);
    cudaGetSymbolAddress((void**)&S.atr_b, g_atr_b);
    cudaGetSymbolAddress((void**)&S.src_l, g_src_l);
    cudaGetSymbolAddress((void**)&S.src_r, g_src_r);

    const int TOT = M + 2 * MX;

    detect_mask_k<<<1, 256>>>(mask_raw);
    setup_k<<<79, 256>>>(mask_raw);
    atom_encode_k<<<Nn, 64>>>(x, atom_emb, S.h);
    hist_all_k<<<(TOT + 255) / 256, 256>>>(ei, xei, M, MX);
    scan_all_k<<<3, 1024>>>();
    fill_all_k<<<(TOT + 255) / 256, 256>>>(ei, xei, ea, M, MX);
    wsplit_all_k<<<dim3(16, 16, 2 * NCONV), dim3(32, 8)>>>(W1_m, W1_e, W2_m, W2_e);

    const float* prev_sums = nullptr;
    const float* prev_g = nullptr;
    const float* prev_b = nullptr;

    dim3 g1d(Hh / 128, (Nn + 63) / 64);
    dim3 g2d(Ee / 128, (Nn + 63) / 64);

    for (int l = 0; l < Ll; l++) {
        for (int j = 0; j < 3; j++) {
            int c = l * 3 + j;
            const float* Xin = (c == 0) ? S.h : S.hB;
            const float* eps;
            const float* g1;
            const float* be1;
            const float* bng;
            const float* bnb;
            const float* mask = nullptr;
            const int* offs;
            const int* csrc;
            const int* catr = nullptr;
            if (j == 0) {
                eps = eps_m + l;
                g1 = g1_m + (size_t)l * Hh;  be1 = be1_m + (size_t)l * Hh;
                bng = bn_g_m + (size_t)l * Ee; bnb = bn_b_m + (size_t)l * Ee;
                offs = S.offs_b; csrc = S.src_b; catr = S.atr_b;
            } else {
                int s = l * 2 + (j - 1);
                eps = eps_e + s;
                g1 = g1_e + (size_t)s * Hh;  be1 = be1_e + (size_t)s * Hh;
                bng = bn_g_e + (size_t)s * Ee; bnb = bn_b_e + (size_t)s * Ee;
                offs = (j == 1) ? S.offs_l : S.offs_r;
                csrc = (j == 1) ? S.src_l : S.src_r;
                mask = S.mask;
            }
            float* sumsH_c = S.sumsH + (size_t)c * 2 * Hh;
            float* sumsE_c = S.sumsE + (size_t)c * 2 * Ee;

            if (catr)
                gather_k<true><<<(Nn + 7) / 8, 256>>>(Xin, prev_sums, prev_g, prev_b,
                                                      offs, csrc, catr, bond_emb,
                                                      mask, eps, S.A1hi, S.A1lo);
            else
                gather_k<false><<<(Nn + 7) / 8, 256>>>(Xin, prev_sums, prev_g, prev_b,
                                                       offs, csrc, nullptr, nullptr,
                                                       mask, eps, S.A1hi, S.A1lo);

            mma_gemm_k<true><<<g1d, 256, GEMM_SMEM>>>(
                S.A1hi, S.A1lo,
                S.W1Thi + (size_t)c * Hh * Ee, S.W1Tlo + (size_t)c * Hh * Ee,
                nullptr, S.t1hi, S.t1lo, sumsH_c, Nn, Ee, Hh);

            bnrelu_split_k<<<2500, 256>>>(
                S.t1hi, S.t1lo, sumsH_c, g1, be1, S.A2hi, S.A2lo);

            mma_gemm_k<false><<<g2d, 256, GEMM_SMEM>>>(
                S.A2hi, S.A2lo,
                S.W2Thi + (size_t)c * Ee * Hh, S.W2Tlo + (size_t)c * Ee * Hh,
                S.hB, nullptr, nullptr, sumsE_c, Nn, Hh, Ee);

            prev_sums = sumsE_c;
            prev_g = bng;
            prev_b = bnb;
        }
    }

    bn_apply_final_k<<<(Nn * Ee / 4 + 255) / 256, 256>>>(S.hB, prev_sums, prev_g, prev_b,
                                                         (float*)d_out);
}

// round 16
// speedup vs baseline: 1.1470x; 1.0403x over previous
#include <cuda_runtime.h>
#include <cuda_fp16.h>
#include <cstddef>
#include <cstdint>

#define Nn 20000
#define Ee 256
#define Hh 512
#define Ll 5
#define NCONV 15
#define MB_CAP 320000
#define MX_CAP 160000

// ---------------- scratch (device globals; no allocations allowed) ----------
__device__ float g_h[Nn * Ee];
__device__ float g_hB[Nn * Ee];
__device__ float g_sumsH[NCONV * 2 * Hh];
__device__ float g_sumsE[NCONV * 2 * Ee];
__device__ float g_mask[Nn];
__device__ int   g_mask_dtype;

__device__ __half g_A1hi[Nn * Ee];
__device__ __half g_A1lo[Nn * Ee];
__device__ __half g_t1hi[Nn * Hh];
__device__ __half g_t1lo[Nn * Hh];
__device__ __half g_A2hi[Nn * Hh];
__device__ __half g_A2lo[Nn * Hh];
__device__ __half g_W1Thi[NCONV * Hh * Ee];
__device__ __half g_W1Tlo[NCONV * Hh * Ee];
__device__ __half g_W2Thi[NCONV * Ee * Hh];
__device__ __half g_W2Tlo[NCONV * Ee * Hh];

__device__ int g_deg[3 * Nn];
__device__ int g_cur[3 * Nn];
__device__ int g_offs_b[Nn + 1], g_offs_l[Nn + 1], g_offs_r[Nn + 1];
__device__ int g_src_b[MB_CAP];
__device__ int g_atr_b[MB_CAP];
__device__ int g_src_l[MX_CAP];
__device__ int g_src_r[MX_CAP];

// ---------------- helpers ----------------------------------------------------
__device__ __forceinline__ uint32_t smem_u32(const void* p) {
    uint32_t a;
    asm("{ .reg .u64 t; cvta.to.shared.u64 t, %1; cvt.u32.u64 %0, t; }" : "=r"(a) : "l"(p));
    return a;
}
#define SW64(off)  ((off) ^ (((off) >> 3) & 0x30))

#define LDSM_X4(r0, r1, r2, r3, addr) \
    asm volatile("ldmatrix.sync.aligned.m8n8.x4.shared.b16 {%0,%1,%2,%3}, [%4];" \
                 : "=r"(r0), "=r"(r1), "=r"(r2), "=r"(r3) : "r"(addr))

#define MMA16816(d, a0, a1, a2, a3, b0, b1) \
    asm volatile("mma.sync.aligned.m16n8k16.row.col.f32.f16.f16.f32 " \
                 "{%0,%1,%2,%3}, {%4,%5,%6,%7}, {%8,%9}, {%0,%1,%2,%3};" \
                 : "+f"((d)[0]), "+f"((d)[1]), "+f"((d)[2]), "+f"((d)[3]) \
                 : "r"(a0), "r"(a1), "r"(a2), "r"(a3), "r"(b0), "r"(b1))

#define CP_ASYNC16(dst, src, sz) \
    asm volatile("cp.async.cg.shared.global [%0], [%1], 16, %2;" \
                 :: "r"(dst), "l"(src), "r"(sz))
#define CP_COMMIT() asm volatile("cp.async.commit_group;" ::: "memory")
#define CP_WAIT0() asm volatile("cp.async.wait_group 0;" ::: "memory")
#define CP_WAIT2() asm volatile("cp.async.wait_group 2;" ::: "memory")

__device__ __forceinline__ uint32_t pack2h(float a, float b) {
    __half ha = __float2half_rn(a), hb = __float2half_rn(b);
    return (uint32_t)__half_as_ushort(ha) | ((uint32_t)__half_as_ushort(hb) << 16);
}

// ---------------- mask dtype detection ---------------------------------------
__global__ void detect_mask_k(const void* mask) {
    __shared__ int not_i32, not_f32;
    if (threadIdx.x == 0) { not_i32 = 0; not_f32 = 0; }
    __syncthreads();
    const unsigned* w = (const unsigned*)mask;
    int bad_i = 0, bad_f = 0;
    for (int i = threadIdx.x; i < Nn / 4; i += blockDim.x) {
        unsigned v = w[i];
        if (v > 1u) bad_i = 1;
        if (v != 0u && v != 0x3F800000u) bad_f = 1;
    }
    if (bad_i) atomicOr(&not_i32, 1);
    if (bad_f) atomicOr(&not_f32, 1);
    __syncthreads();
    if (threadIdx.x == 0) {
        if (!not_i32) g_mask_dtype = 0;
        else if (!not_f32) g_mask_dtype = 1;
        else g_mask_dtype = 2;
    }
}

__global__ void setup_k(const void* mask) {
    int i = blockIdx.x * blockDim.x + threadIdx.x;
    int stride = gridDim.x * blockDim.x;
    int dt = g_mask_dtype;
    for (int n = i; n < Nn; n += stride) {
        float m;
        if (dt == 0)      m = (((const int*)mask)[n] != 0) ? 1.f : 0.f;
        else if (dt == 1) m = (((const float*)mask)[n] != 0.f) ? 1.f : 0.f;
        else              m = (((const unsigned char*)mask)[n] != 0) ? 1.f : 0.f;
        g_mask[n] = m;
    }
    for (int n = i; n < 3 * Nn; n += stride) g_deg[n] = 0;
    for (int n = i; n < NCONV * 2 * Hh; n += stride) g_sumsH[n] = 0.f;
    for (int n = i; n < NCONV * 2 * Ee; n += stride) g_sumsE[n] = 0.f;
}

// ---------------- atom encoder ------------------------------------------------
__global__ void atom_encode_k(const int* __restrict__ x,
                              const float* __restrict__ emb,
                              float* __restrict__ h) {
    int n = blockIdx.x;
    int t = threadIdx.x;
    float4 acc = make_float4(0.f, 0.f, 0.f, 0.f);
#pragma unroll
    for (int f = 0; f < 9; f++) {
        int idx = __ldg(&x[n * 9 + f]);
        const float4* row = (const float4*)&emb[((size_t)(f * 128 + idx)) * Ee];
        float4 v = row[t];
        acc.x += v.x; acc.y += v.y; acc.z += v.z; acc.w += v.w;
    }
    ((float4*)h)[(size_t)n * (Ee / 4) + t] = acc;
}

// ---------------- CSR build (fused across 3 orientations) --------------------
__global__ void hist_all_k(const int* __restrict__ ei, const int* __restrict__ xei,
                           int M, int MX) {
    int e = blockIdx.x * blockDim.x + threadIdx.x;
    if (e < M) atomicAdd(&g_deg[ei[M + e]], 1);
    else if (e < M + MX) atomicAdd(&g_deg[Nn + xei[MX + (e - M)]], 1);
    else if (e < M + 2 * MX) atomicAdd(&g_deg[2 * Nn + xei[e - M - MX]], 1);
}

__global__ void scan_all_k() {
    int which = blockIdx.x;
    const int* deg = g_deg + which * Nn;
    int* cur = g_cur + which * Nn;
    int* offs = (which == 0) ? g_offs_b : (which == 1) ? g_offs_l : g_offs_r;
    __shared__ int ssum[1024];
    int t = threadIdx.x;
    const int PER = (Nn + 1023) / 1024;  // 20
    int loc[20];
    int s = 0;
#pragma unroll
    for (int i = 0; i < PER; i++) {
        int idx = t * PER + i;
        int v = (idx < Nn) ? deg[idx] : 0;
        loc[i] = s;
        s += v;
    }
    ssum[t] = s;
    __syncthreads();
    for (int off = 1; off < 1024; off <<= 1) {
        int v = (t >= off) ? ssum[t - off] : 0;
        __syncthreads();
        ssum[t] += v;
        __syncthreads();
    }
    int pre = (t > 0) ? ssum[t - 1] : 0;
#pragma unroll
    for (int i = 0; i < PER; i++) {
        int idx = t * PER + i;
        if (idx < Nn) {
            offs[idx] = pre + loc[i];
            cur[idx] = pre + loc[i];
        }
    }
    if (t == 1023) offs[Nn] = ssum[1023];
}

__global__ void fill_all_k(const int* __restrict__ ei, const int* __restrict__ xei,
                           const int* __restrict__ ea, int M, int MX) {
    int e = blockIdx.x * blockDim.x + threadIdx.x;
    if (e < M) {
        int p = atomicAdd(&g_cur[ei[M + e]], 1);
        if (p < MB_CAP) {
            g_src_b[p] = ei[e];
            g_atr_b[p] = ea[e * 3] | (ea[e * 3 + 1] << 3) | (ea[e * 3 + 2] << 6);
        }
    } else if (e < M + MX) {
        int j = e - M;
        int p = atomicAdd(&g_cur[Nn + xei[MX + j]], 1);
        if (p < MX_CAP) g_src_l[p] = xei[j];
    } else if (e < M + 2 * MX) {
        int j = e - M - MX;
        int p = atomicAdd(&g_cur[2 * Nn + xei[j]], 1);
        if (p < MX_CAP) g_src_r[p] = xei[MX + j];
    }
}

// ---------------- merged weight transpose + fp16 split ------------------------
__global__ void wsplit_all_k(const float* __restrict__ W1m, const float* __restrict__ W1e,
                             const float* __restrict__ W2m, const float* __restrict__ W2e) {
    int z = blockIdx.z;
    int which = z / NCONV;
    int c = z % NCONV;
    int l = c / 3, j = c % 3;
    const float* W;
    __half *Thi, *Tlo;
    int K, N;
    if (which == 0) {
        K = Ee; N = Hh;
        W = j ? W1e + (size_t)(l * 2 + j - 1) * Ee * Hh : W1m + (size_t)l * Ee * Hh;
        Thi = g_W1Thi + (size_t)c * Hh * Ee;
        Tlo = g_W1Tlo + (size_t)c * Hh * Ee;
    } else {
        K = Hh; N = Ee;
        W = j ? W2e + (size_t)(l * 2 + j - 1) * Hh * Ee : W2m + (size_t)l * Hh * Ee;
        Thi = g_W2Thi + (size_t)c * Ee * Hh;
        Tlo = g_W2Tlo + (size_t)c * Ee * Hh;
    }
    int kb = blockIdx.x * 32, nb = blockIdx.y * 32;
    if (kb >= K || nb >= N) return;
    __shared__ float t[32][33];
    int tx = threadIdx.x, ty = threadIdx.y;
    for (int i = ty; i < 32; i += 8)
        t[i][tx] = W[(size_t)(kb + i) * N + nb + tx];
    __syncthreads();
    for (int i = ty; i < 32; i += 8) {
        float v = t[tx][i];
        __half hi = __float2half_rn(v);
        float lo = v - __half2float(hi);
        Thi[(size_t)(nb + i) * K + kb + tx] = hi;
        Tlo[(size_t)(nb + i) * K + kb + tx] = __float2half_rn(lo);
    }
}

// ---------------- fused CSR gather (edge loop unrolled x2) --------------------
template <bool BOND>
__global__ __launch_bounds__(256) void gather_k(
    const float* __restrict__ Xin,
    const float* __restrict__ insums, const float* __restrict__ ing,
    const float* __restrict__ inb,
    const int* __restrict__ offs, const int* __restrict__ csrc,
    const int* __restrict__ catr, const float* __restrict__ bemb,
    const float* __restrict__ mask, const float* __restrict__ eps,
    __half* __restrict__ Ahi, __half* __restrict__ Alo) {
    __shared__ float s_sc[Ee], s_sh[Ee];
    for (int c = threadIdx.x; c < Ee; c += blockDim.x) {
        if (insums) {
            float mean = insums[c] * (1.f / Nn);
            float var = insums[Ee + c] * (1.f / Nn) - mean * mean;
            float s = ing[c] * rsqrtf(var + 1e-5f);
            s_sc[c] = s;
            s_sh[c] = inb[c] - mean * s;
        } else {
            s_sc[c] = 1.f;
            s_sh[c] = 0.f;
        }
    }
    __syncthreads();

    int node = blockIdx.x * 8 + (threadIdx.x >> 5);
    if (node >= Nn) return;
    int lane = threadIdx.x & 31;
    int c0 = lane * 8;
    float flo = insums ? 0.f : -3.4e38f;

    float4 sc0 = *(const float4*)&s_sc[c0], sc1 = *(const float4*)&s_sc[c0 + 4];
    float4 sh0 = *(const float4*)&s_sh[c0], sh1 = *(const float4*)&s_sh[c0 + 4];

    float a0 = 0.f, a1 = 0.f, a2 = 0.f, a3 = 0.f, a4 = 0.f, a5 = 0.f, a6 = 0.f, a7 = 0.f;
    int e0 = __ldg(&offs[node]), e1 = __ldg(&offs[node + 1]);

    int e = e0;
    for (; e + 2 <= e1; e += 2) {
        int sA = __ldg(&csrc[e]);
        int sB = __ldg(&csrc[e + 1]);
        const float4* xrA = (const float4*)&Xin[(size_t)sA * Ee + c0];
        const float4* xrB = (const float4*)&Xin[(size_t)sB * Ee + c0];
        float4 xA0 = __ldg(xrA), xA1 = __ldg(xrA + 1);
        float4 xB0 = __ldg(xrB), xB1 = __ldg(xrB + 1);
        float4 bA0, bA1, bB0, bB1;
        if (BOND) {
            int mtA = __ldg(&catr[e]);
            int mtB = __ldg(&catr[e + 1]);
            const float4* pA0 = (const float4*)&bemb[(size_t)(mtA & 7) * Ee + c0];
            const float4* pA1 = (const float4*)&bemb[(size_t)(8 + ((mtA >> 3) & 7)) * Ee + c0];
            const float4* pA2 = (const float4*)&bemb[(size_t)(16 + ((mtA >> 6) & 7)) * Ee + c0];
            const float4* pB0 = (const float4*)&bemb[(size_t)(mtB & 7) * Ee + c0];
            const float4* pB1 = (const float4*)&bemb[(size_t)(8 + ((mtB >> 3) & 7)) * Ee + c0];
            const float4* pB2 = (const float4*)&bemb[(size_t)(16 + ((mtB >> 6) & 7)) * Ee + c0];
            float4 a00 = __ldg(pA0), a01 = __ldg(pA0 + 1);
            float4 a10 = __ldg(pA1), a11 = __ldg(pA1 + 1);
            float4 a20 = __ldg(pA2), a21 = __ldg(pA2 + 1);
            float4 b00 = __ldg(pB0), b01 = __ldg(pB0 + 1);
            float4 b10 = __ldg(pB1), b11 = __ldg(pB1 + 1);
            float4 b20 = __ldg(pB2), b21 = __ldg(pB2 + 1);
            bA0.x = a00.x + a10.x + a20.x; bA0.y = a00.y + a10.y + a20.y;
            bA0.z = a00.z + a10.z + a20.z; bA0.w = a00.w + a10.w + a20.w;
            bA1.x = a01.x + a11.x + a21.x; bA1.y = a01.y + a11.y + a21.y;
            bA1.z = a01.z + a11.z + a21.z; bA1.w = a01.w + a11.w + a21.w;
            bB0.x = b00.x + b10.x + b20.x; bB0.y = b00.y + b10.y + b20.y;
            bB0.z = b00.z + b10.z + b20.z; bB0.w = b00.w + b10.w + b20.w;
            bB1.x = b01.x + b11.x + b21.x; bB1.y = b01.y + b11.y + b21.y;
            bB1.z = b01.z + b11.z + b21.z; bB1.w = b01.w + b11.w + b21.w;
        }
        {
            float v0 = fmaxf(fmaf(xA0.x, sc0.x, sh0.x), flo);
            float v1 = fmaxf(fmaf(xA0.y, sc0.y, sh0.y), flo);
            float v2 = fmaxf(fmaf(xA0.z, sc0.z, sh0.z), flo);
            float v3 = fmaxf(fmaf(xA0.w, sc0.w, sh0.w), flo);
            float v4 = fmaxf(fmaf(xA1.x, sc1.x, sh1.x), flo);
            float v5 = fmaxf(fmaf(xA1.y, sc1.y, sh1.y), flo);
            float v6 = fmaxf(fmaf(xA1.z, sc1.z, sh1.z), flo);
            float v7 = fmaxf(fmaf(xA1.w, sc1.w, sh1.w), flo);
            if (BOND) {
                v0 += bA0.x; v1 += bA0.y; v2 += bA0.z; v3 += bA0.w;
                v4 += bA1.x; v5 += bA1.y; v6 += bA1.z; v7 += bA1.w;
            }
            a0 += fmaxf(v0, 0.f); a1 += fmaxf(v1, 0.f);
            a2 += fmaxf(v2, 0.f); a3 += fmaxf(v3, 0.f);
            a4 += fmaxf(v4, 0.f); a5 += fmaxf(v5, 0.f);
            a6 += fmaxf(v6, 0.f); a7 += fmaxf(v7, 0.f);
        }
        {
            float v0 = fmaxf(fmaf(xB0.x, sc0.x, sh0.x), flo);
            float v1 = fmaxf(fmaf(xB0.y, sc0.y, sh0.y), flo);
            float v2 = fmaxf(fmaf(xB0.z, sc0.z, sh0.z), flo);
            float v3 = fmaxf(fmaf(xB0.w, sc0.w, sh0.w), flo);
            float v4 = fmaxf(fmaf(xB1.x, sc1.x, sh1.x), flo);
            float v5 = fmaxf(fmaf(xB1.y, sc1.y, sh1.y), flo);
            float v6 = fmaxf(fmaf(xB1.z, sc1.z, sh1.z), flo);
            float v7 = fmaxf(fmaf(xB1.w, sc1.w, sh1.w), flo);
            if (BOND) {
                v0 += bB0.x; v1 += bB0.y; v2 += bB0.z; v3 += bB0.w;
                v4 += bB1.x; v5 += bB1.y; v6 += bB1.z; v7 += bB1.w;
            }
            a0 += fmaxf(v0, 0.f); a1 += fmaxf(v1, 0.f);
            a2 += fmaxf(v2, 0.f); a3 += fmaxf(v3, 0.f);
            a4 += fmaxf(v4, 0.f); a5 += fmaxf(v5, 0.f);
            a6 += fmaxf(v6, 0.f); a7 += fmaxf(v7, 0.f);
        }
    }
    for (; e < e1; e++) {
        int s = __ldg(&csrc[e]);
        const float4* xr = (const float4*)&Xin[(size_t)s * Ee + c0];
        float4 x0 = __ldg(xr), x1 = __ldg(xr + 1);
        float v0 = fmaxf(fmaf(x0.x, sc0.x, sh0.x), flo);
        float v1 = fmaxf(fmaf(x0.y, sc0.y, sh0.y), flo);
        float v2 = fmaxf(fmaf(x0.z, sc0.z, sh0.z), flo);
        float v3 = fmaxf(fmaf(x0.w, sc0.w, sh0.w), flo);
        float v4 = fmaxf(fmaf(x1.x, sc1.x, sh1.x), flo);
        float v5 = fmaxf(fmaf(x1.y, sc1.y, sh1.y), flo);
        float v6 = fmaxf(fmaf(x1.z, sc1.z, sh1.z), flo);
        float v7 = fmaxf(fmaf(x1.w, sc1.w, sh1.w), flo);
        if (BOND) {
            int mt = __ldg(&catr[e]);
            const float4* b0 = (const float4*)&bemb[(size_t)(mt & 7) * Ee + c0];
            const float4* b1 = (const float4*)&bemb[(size_t)(8 + ((mt >> 3) & 7)) * Ee + c0];
            const float4* b2 = (const float4*)&bemb[(size_t)(16 + ((mt >> 6) & 7)) * Ee + c0];
            float4 p0 = __ldg(b0), p1 = __ldg(b0 + 1);
            float4 q0 = __ldg(b1), q1 = __ldg(b1 + 1);
            float4 r0 = __ldg(b2), r1 = __ldg(b2 + 1);
            v0 += p0.x + q0.x + r0.x; v1 += p0.y + q0.y + r0.y;
            v2 += p0.z + q0.z + r0.z; v3 += p0.w + q0.w + r0.w;
            v4 += p1.x + q1.x + r1.x; v5 += p1.y + q1.y + r1.y;
            v6 += p1.z + q1.z + r1.z; v7 += p1.w + q1.w + r1.w;
        }
        a0 += fmaxf(v0, 0.f); a1 += fmaxf(v1, 0.f);
        a2 += fmaxf(v2, 0.f); a3 += fmaxf(v3, 0.f);
        a4 += fmaxf(v4, 0.f); a5 += fmaxf(v5, 0.f);
        a6 += fmaxf(v6, 0.f); a7 += fmaxf(v7, 0.f);
    }

    const float4* xr = (const float4*)&Xin[(size_t)node * Ee + c0];
    float4 x0 = __ldg(xr), x1 = __ldg(xr + 1);
    float s0 = fmaxf(fmaf(x0.x, sc0.x, sh0.x), flo);
    float s1 = fmaxf(fmaf(x0.y, sc0.y, sh0.y), flo);
    float s2 = fmaxf(fmaf(x0.z, sc0.z, sh0.z), flo);
    float s3 = fmaxf(fmaf(x0.w, sc0.w, sh0.w), flo);
    float s4 = fmaxf(fmaf(x1.x, sc1.x, sh1.x), flo);
    float s5 = fmaxf(fmaf(x1.y, sc1.y, sh1.y), flo);
    float s6 = fmaxf(fmaf(x1.z, sc1.z, sh1.z), flo);
    float s7 = fmaxf(fmaf(x1.w, sc1.w, sh1.w), flo);
    float m = mask ? __ldg(&mask[node]) : 1.f;
    float ef = (1.f + __ldg(eps)) * m;
    float p0 = fmaf(ef, s0, a0), p1 = fmaf(ef, s1, a1);
    float p2 = fmaf(ef, s2, a2), p3 = fmaf(ef, s3, a3);
    float p4 = fmaf(ef, s4, a4), p5 = fmaf(ef, s5, a5);
    float p6 = fmaf(ef, s6, a6), p7 = fmaf(ef, s7, a7);
    uint4 hi, lo;
    {
        __half h0 = __float2half_rn(p0), h1 = __float2half_rn(p1);
        __half h2 = __float2half_rn(p2), h3 = __float2half_rn(p3);
        __half h4 = __float2half_rn(p4), h5 = __float2half_rn(p5);
        __half h6 = __float2half_rn(p6), h7 = __float2half_rn(p7);
        hi.x = (uint32_t)__half_as_ushort(h0) | ((uint32_t)__half_as_ushort(h1) << 16);
        hi.y = (uint32_t)__half_as_ushort(h2) | ((uint32_t)__half_as_ushort(h3) << 16);
        hi.z = (uint32_t)__half_as_ushort(h4) | ((uint32_t)__half_as_ushort(h5) << 16);
        hi.w = (uint32_t)__half_as_ushort(h6) | ((uint32_t)__half_as_ushort(h7) << 16);
        lo.x = pack2h(p0 - __half2float(h0), p1 - __half2float(h1));
        lo.y = pack2h(p2 - __half2float(h2), p3 - __half2float(h3));
        lo.z = pack2h(p4 - __half2float(h4), p5 - __half2float(h5));
        lo.w = pack2h(p6 - __half2float(h6), p7 - __half2float(h7));
    }
    *(uint4*)&Ahi[(size_t)node * Ee + c0] = hi;
    *(uint4*)&Alo[(size_t)node * Ee + c0] = lo;
}

// ---------------- t1 pair -> inline BN -> relu -> split (4 elems/thread) -----
__global__ void bnrelu_split_k(const __half* __restrict__ Thi, const __half* __restrict__ Tlo,
                               const float* __restrict__ sums,
                               const float* __restrict__ g,
                               const float* __restrict__ b,
                               __half* __restrict__ Ahi, __half* __restrict__ Alo) {
    __shared__ float s_sc[Hh], s_sh[Hh];
    for (int c = threadIdx.x; c < Hh; c += blockDim.x) {
        float mean = sums[c] * (1.f / Nn);
        float var = sums[Hh + c] * (1.f / Nn) - mean * mean;
        float s = g[c] * rsqrtf(var + 1e-5f);
        s_sc[c] = s;
        s_sh[c] = b[c] - mean * s;
    }
    __syncthreads();
#pragma unroll
    for (int u = 0; u < 4; u++) {
        int i = blockIdx.x * 1024 + u * 256 + threadIdx.x;
        if (i >= Nn * Hh / 4) return;
        int c = (i & (Hh / 4 - 1)) * 4;
        uint2 vh = ((const uint2*)Thi)[i];
        uint2 vl = ((const uint2*)Tlo)[i];
        float2 h0 = __half22float2(*(__half2*)&vh.x);
        float2 h1 = __half22float2(*(__half2*)&vh.y);
        float2 l0 = __half22float2(*(__half2*)&vl.x);
        float2 l1 = __half22float2(*(__half2*)&vl.y);
        float x0 = h0.x + l0.x, x1 = h0.y + l0.y, x2 = h1.x + l1.x, x3 = h1.y + l1.y;
        x0 = fmaxf(fmaf(x0, s_sc[c + 0], s_sh[c + 0]), 0.f);
        x1 = fmaxf(fmaf(x1, s_sc[c + 1], s_sh[c + 1]), 0.f);
        x2 = fmaxf(fmaf(x2, s_sc[c + 2], s_sh[c + 2]), 0.f);
        x3 = fmaxf(fmaf(x3, s_sc[c + 3], s_sh[c + 3]), 0.f);
        __half q0 = __float2half_rn(x0), q1 = __float2half_rn(x1);
        __half q2 = __float2half_rn(x2), q3 = __float2half_rn(x3);
        uint2 hi, lo;
        hi.x = (uint32_t)__half_as_ushort(q0) | ((uint32_t)__half_as_ushort(q1) << 16);
        hi.y = (uint32_t)__half_as_ushort(q2) | ((uint32_t)__half_as_ushort(q3) << 16);
        lo.x = pack2h(x0 - __half2float(q0), x1 - __half2float(q1));
        lo.y = pack2h(x2 - __half2float(q2), x3 - __half2float(q3));
        ((uint2*)Ahi)[i] = hi;
        ((uint2*)Alo)[i] = lo;
    }
}

// ---------------- mma.sync fp16x3 GEMM: 64xNT tile, K32, 4-stage, 2 CTA/SM ---
// NT=128: warps 2x4 (32x32 each). NT=64: warps 4x2 (16x32 each).
// One __syncthreads per iteration (stage count 4 > issue distance 3 arg).
template <bool HALF_OUT, int NT>
__global__ __launch_bounds__(256, 2) void mma_gemm_k(
    const __half* __restrict__ Ahi, const __half* __restrict__ Alo,
    const __half* __restrict__ Bhi, const __half* __restrict__ Blo,
    float* __restrict__ C, __half* __restrict__ Chi, __half* __restrict__ Clo,
    float* __restrict__ sums, int Mr, int K, int Nc) {
    constexpr int NWC = NT / 32;            // n-warp columns: 4 or 2
    constexpr int MF = (NT == 128) ? 2 : 1; // m-frags per warp
    constexpr int SA_LO_O = 4096;
    constexpr int SB_HI_O = 8192;
    constexpr int SB_LO_O = 8192 + NT * 64;
    constexpr int STAGE = 8192 + 2 * NT * 64;

    extern __shared__ char smem[];
    const uint32_t sb = smem_u32(smem);
    const int tid = threadIdx.x;
    const int lane = tid & 31, wid = tid >> 5;
    const int wm = (wid / NWC) * (MF * 16);
    const int wn = (wid % NWC) * 32;
    const int m0 = blockIdx.y * 64;
    const int n0 = blockIdx.x * NT;
    const int nkt = K >> 5;

    float acc[MF][4][4];
#pragma unroll
    for (int a = 0; a < MF; a++)
#pragma unroll
        for (int b = 0; b < 4; b++)
#pragma unroll
            for (int c = 0; c < 4; c++) acc[a][b][c] = 0.f;

    const int arow = tid >> 2, aq = tid & 3;
    const bool arow_ok = (m0 + arow) < Mr;
    const int arow_cl = arow_ok ? (m0 + arow) : 0;
    const char* pAhi = (const char*)(Ahi + (size_t)arow_cl * K);
    const char* pAlo = (const char*)(Alo + (size_t)arow_cl * K);
    const int asz = arow_ok ? 16 : 0;
    const uint32_t aso = SW64((uint32_t)(arow * 64 + aq * 16));

    // B loader: NT=128 -> 2 thr/row x 2 chunks; NT=64 -> 4 thr/row x 1 chunk
    const int brow = (NT == 128) ? (tid >> 1) : (tid >> 2);
    const int bq   = (NT == 128) ? (tid & 1) : (tid & 3);
    const char* pBhi = (const char*)(Bhi + (size_t)(n0 + brow) * K);
    const char* pBlo = (const char*)(Blo + (size_t)(n0 + brow) * K);
    const uint32_t bso0 = (NT == 128) ? SW64((uint32_t)(brow * 64 + bq * 32))
                                      : SW64((uint32_t)(brow * 64 + bq * 16));
    const uint32_t bso1 = SW64((uint32_t)(brow * 64 + bq * 32 + 16));  // NT==128 only

    auto issue = [&](int stage, int kt) {
        const size_t gk = (size_t)kt * 64;
        const uint32_t st = sb + stage * STAGE;
        CP_ASYNC16(st + 0 + aso, pAhi + gk + aq * 16, asz);
        CP_ASYNC16(st + SA_LO_O + aso, pAlo + gk + aq * 16, asz);
        if (NT == 128) {
            CP_ASYNC16(st + SB_HI_O + bso0, pBhi + gk + bq * 32, 16);
            CP_ASYNC16(st + SB_HI_O + bso1, pBhi + gk + bq * 32 + 16, 16);
            CP_ASYNC16(st + SB_LO_O + bso0, pBlo + gk + bq * 32, 16);
            CP_ASYNC16(st + SB_LO_O + bso1, pBlo + gk + bq * 32 + 16, 16);
        } else {
            CP_ASYNC16(st + SB_HI_O + bso0, pBhi + gk + bq * 16, 16);
            CP_ASYNC16(st + SB_LO_O + bso0, pBlo + gk + bq * 16, 16);
        }
    };

    issue(0, 0); CP_COMMIT();
    issue(1, 1); CP_COMMIT();
    issue(2, 2); CP_COMMIT();

    for (int kt = 0; kt < nkt; kt++) {
        if (kt + 3 < nkt) CP_WAIT2(); else CP_WAIT0();
        __syncthreads();
        if (kt + 3 < nkt) {
            issue((kt + 3) & 3, kt + 3);
            CP_COMMIT();
        }

        const uint32_t st = sb + (kt & 3) * STAGE;
#pragma unroll
        for (int ks = 0; ks < 2; ks++) {
            const int k0 = ks * 16;
            const uint32_t ar = wm + (lane & 15);
            const uint32_t ac = k0 + ((lane >> 4) << 3);
            const uint32_t br = wn + (lane & 7) + ((lane >> 4) << 3);
            const uint32_t bc = k0 + (((lane >> 3) & 1) << 3);
            uint32_t bhi[8], blo[8], ah[4 * MF], al[4 * MF];
#pragma unroll
            for (int nb = 0; nb < 2; nb++) {
                uint32_t off = SW64((br + nb * 16) * 64 + bc * 2);
                LDSM_X4(bhi[nb * 4 + 0], bhi[nb * 4 + 1], bhi[nb * 4 + 2], bhi[nb * 4 + 3],
                        st + SB_HI_O + off);
                LDSM_X4(blo[nb * 4 + 0], blo[nb * 4 + 1], blo[nb * 4 + 2], blo[nb * 4 + 3],
                        st + SB_LO_O + off);
            }
#pragma unroll
            for (int mf = 0; mf < MF; mf++) {
                uint32_t off = SW64((ar + mf * 16) * 64 + ac * 2);
                LDSM_X4(ah[mf * 4 + 0], ah[mf * 4 + 1], ah[mf * 4 + 2], ah[mf * 4 + 3],
                        st + 0 + off);
                LDSM_X4(al[mf * 4 + 0], al[mf * 4 + 1], al[mf * 4 + 2], al[mf * 4 + 3],
                        st + SA_LO_O + off);
            }
#pragma unroll
            for (int mf = 0; mf < MF; mf++)
#pragma unroll
                for (int nf = 0; nf < 4; nf++) {
                    int bi = (nf >> 1) * 4 + (nf & 1) * 2;
                    MMA16816(acc[mf][nf], ah[mf * 4], ah[mf * 4 + 1], ah[mf * 4 + 2],
                             ah[mf * 4 + 3], bhi[bi], bhi[bi + 1]);
                    MMA16816(acc[mf][nf], ah[mf * 4], ah[mf * 4 + 1], ah[mf * 4 + 2],
                             ah[mf * 4 + 3], blo[bi], blo[bi + 1]);
                    MMA16816(acc[mf][nf], al[mf * 4], al[mf * 4 + 1], al[mf * 4 + 2],
                             al[mf * 4 + 3], bhi[bi], bhi[bi + 1]);
                }
        }
    }

    // epilogue
#pragma unroll
    for (int mf = 0; mf < MF; mf++) {
        int r = m0 + wm + mf * 16 + (lane >> 2);
#pragma unroll
        for (int nf = 0; nf < 4; nf++) {
            int col = n0 + wn + nf * 8 + (lane & 3) * 2;
            float a0 = acc[mf][nf][0], a1 = acc[mf][nf][1];
            float a2 = acc[mf][nf][2], a3 = acc[mf][nf][3];
            if (HALF_OUT) {
                if (r < Mr) {
                    __half h0 = __float2half_rn(a0), h1 = __float2half_rn(a1);
                    *(uint32_t*)&Chi[(size_t)r * Nc + col] =
                        (uint32_t)__half_as_ushort(h0) | ((uint32_t)__half_as_ushort(h1) << 16);
                    *(uint32_t*)&Clo[(size_t)r * Nc + col] =
                        pack2h(a0 - __half2float(h0), a1 - __half2float(h1));
                }
                if (r + 8 < Mr) {
                    __half h2 = __float2half_rn(a2), h3 = __float2half_rn(a3);
                    *(uint32_t*)&Chi[(size_t)(r + 8) * Nc + col] =
                        (uint32_t)__half_as_ushort(h2) | ((uint32_t)__half_as_ushort(h3) << 16);
                    *(uint32_t*)&Clo[(size_t)(r + 8) * Nc + col] =
                        pack2h(a2 - __half2float(h2), a3 - __half2float(h3));
                }
            } else {
                if (r < Mr)
                    *(float2*)&C[(size_t)r * Nc + col] = make_float2(a0, a1);
                if (r + 8 < Mr)
                    *(float2*)&C[(size_t)(r + 8) * Nc + col] = make_float2(a2, a3);
            }
        }
    }

    // fused BN column stats (padded rows contribute exactly 0)
#pragma unroll
    for (int nf = 0; nf < 4; nf++) {
        float s0 = 0.f, s1 = 0.f, q0 = 0.f, q1 = 0.f;
#pragma unroll
        for (int mf = 0; mf < MF; mf++) {
            float a0 = acc[mf][nf][0], a1 = acc[mf][nf][1];
            float a2 = acc[mf][nf][2], a3 = acc[mf][nf][3];
            s0 += a0 + a2; s1 += a1 + a3;
            q0 += a0 * a0 + a2 * a2; q1 += a1 * a1 + a3 * a3;
        }
#pragma unroll
        for (int off = 4; off < 32; off <<= 1) {
            s0 += __shfl_xor_sync(0xffffffff, s0, off);
            s1 += __shfl_xor_sync(0xffffffff, s1, off);
            q0 += __shfl_xor_sync(0xffffffff, q0, off);
            q1 += __shfl_xor_sync(0xffffffff, q1, off);
        }
        if (lane < 4) {
            int c = n0 + wn + nf * 8 + lane * 2;
            atomicAdd(&sums[c], s0);
            atomicAdd(&sums[c + 1], s1);
            atomicAdd(&sums[Nc + c], q0);
            atomicAdd(&sums[Nc + c + 1], q1);
        }
    }
}

// ---------------- final BN apply (inline scale/shift) ------------------------
__global__ void bn_apply_final_k(const float* __restrict__ X,
                                 const float* __restrict__ sums,
                                 const float* __restrict__ g,
                                 const float* __restrict__ b,
                                 float* __restrict__ Y) {
    __shared__ float s_sc[Ee], s_sh[Ee];
    for (int c = threadIdx.x; c < Ee; c += blockDim.x) {
        float mean = sums[c] * (1.f / Nn);
        float var = sums[Ee + c] * (1.f / Nn) - mean * mean;
        float s = g[c] * rsqrtf(var + 1e-5f);
        s_sc[c] = s;
        s_sh[c] = b[c] - mean * s;
    }
    __syncthreads();
    int i = blockIdx.x * blockDim.x + threadIdx.x;
    if (i >= Nn * Ee / 4) return;
    int c = (i & 63) * 4;
    float4 v = ((const float4*)X)[i];
    v.x = fmaf(v.x, s_sc[c + 0], s_sh[c + 0]);
    v.y = fmaf(v.y, s_sc[c + 1], s_sh[c + 1]);
    v.z = fmaf(v.z, s_sc[c + 2], s_sh[c + 2]);
    v.w = fmaf(v.w, s_sc[c + 3], s_sh[c + 3]);
    ((float4*)Y)[i] = v;
}

// ---------------- host orchestration ----------------------------------------
struct Scratch {
    float *h, *hB, *sumsH, *sumsE, *mask;
    __half *A1hi, *A1lo, *t1hi, *t1lo, *A2hi, *A2lo;
    __half *W1Thi, *W1Tlo, *W2Thi, *W2Tlo;
    int *offs_b, *offs_l, *offs_r, *src_b, *atr_b, *src_l, *src_r;
};

extern "C" void kernel_launch(void* const* d_in, const int* in_sizes, int n_in,
                              void* d_out, int out_size) {
    const int* x       = (const int*)d_in[0];
    const int* ei      = (const int*)d_in[1];
    const int* ea      = (const int*)d_in[2];
    const int* xei     = (const int*)d_in[3];
    const void* mask_raw = d_in[4];
    const float* atom_emb = (const float*)d_in[5];
    const float* bond_emb = (const float*)d_in[6];
    const float* eps_m = (const float*)d_in[7];
    const float* W1_m  = (const float*)d_in[8];
    const float* g1_m  = (const float*)d_in[10];
    const float* be1_m = (const float*)d_in[11];
    const float* W2_m  = (const float*)d_in[12];
    const float* bn_g_m = (const float*)d_in[14];
    const float* bn_b_m = (const float*)d_in[15];
    const float* eps_e = (const float*)d_in[16];
    const float* W1_e  = (const float*)d_in[17];
    const float* g1_e  = (const float*)d_in[18];
    const float* be1_e = (const float*)d_in[19];
    const float* W2_e  = (const float*)d_in[20];
    const float* bn_g_e = (const float*)d_in[21];
    const float* bn_b_e = (const float*)d_in[22];

    const int M  = in_sizes[1] / 2;
    const int MX = in_sizes[3] / 2;

    const int SMEM1 = 8192 + 2 * 128 * 64;  // 24576 per stage
    const int SMEM2 = 8192 + 2 * 64 * 64;   // 16384 per stage
    cudaFuncSetAttribute(mma_gemm_k<true, 128>,
                         cudaFuncAttributeMaxDynamicSharedMemorySize, 4 * SMEM1);
    cudaFuncSetAttribute(mma_gemm_k<false, 64>,
                         cudaFuncAttributeMaxDynamicSharedMemorySize, 4 * SMEM2);

    Scratch S;
    cudaGetSymbolAddress((void**)&S.h, g_h);
    cudaGetSymbolAddress((void**)&S.hB, g_hB);
    cudaGetSymbolAddress((void**)&S.sumsH, g_sumsH);
    cudaGetSymbolAddress((void**)&S.sumsE, g_sumsE);
    cudaGetSymbolAddress((void**)&S.mask, g_mask);
    cudaGetSymbolAddress((void**)&S.A1hi, g_A1hi);
    cudaGetSymbolAddress((void**)&S.A1lo, g_A1lo);
    cudaGetSymbolAddress((void**)&S.t1hi, g_t1hi);
    cudaGetSymbolAddress((void**)&S.t1lo, g_t1lo);
    cudaGetSymbolAddress((void**)&S.A2hi, g_A2hi);
    cudaGetSymbolAddress((void**)&S.A2lo, g_A2lo);
    cudaGetSymbolAddress((void**)&S.W1Thi, g_W1Thi);
    cudaGetSymbolAddress((void**)&S.W1Tlo, g_W1Tlo);
    cudaGetSymbolAddress((void**)&S.W2Thi, g_W2Thi);
    cudaGetSymbolAddress((void**)&S.W2Tlo, g_W2Tlo);
    cudaGetSymbolAddress((void**)&S.offs_b, g_offs_b);
    cudaGetSymbolAddress((void**)&S.offs_l, g_offs_l);
    cudaGetSymbolAddress((void**)&S.offs_r, g_offs_r);
    cudaGetSymbolAddress((void**)&S.src_b, g_src_b);
    cudaGetSymbolAddress((void**)&S.atr_b, g_atr_b);
    cudaGetSymbolAddress((void**)&S.src_l, g_src_l);
    cudaGetSymbolAddress((void**)&S.src_r, g_src_r);

    const int TOT = M + 2 * MX;

    detect_mask_k<<<1, 256>>>(mask_raw);
    setup_k<<<79, 256>>>(mask_raw);
    atom_encode_k<<<Nn, 64>>>(x, atom_emb, S.h);
    hist_all_k<<<(TOT + 255) / 256, 256>>>(ei, xei, M, MX);
    scan_all_k<<<3, 1024>>>();
    fill_all_k<<<(TOT + 255) / 256, 256>>>(ei, xei, ea, M, MX);
    wsplit_all_k<<<dim3(16, 16, 2 * NCONV), dim3(32, 8)>>>(W1_m, W1_e, W2_m, W2_e);

    const float* prev_sums = nullptr;
    const float* prev_g = nullptr;
    const float* prev_b = nullptr;

    dim3 g1d(Hh / 128, (Nn + 63) / 64);   // GEMM1: 64x128 tiles
    dim3 g2d(Ee / 64, (Nn + 63) / 64);    // GEMM2: 64x64 tiles (wave-quantization fix)

    for (int l = 0; l < Ll; l++) {
        for (int j = 0; j < 3; j++) {
            int c = l * 3 + j;
            const float* Xin = (c == 0) ? S.h : S.hB;
            const float* eps;
            const float* g1;
            const float* be1;
            const float* bng;
            const float* bnb;
            const float* mask = nullptr;
            const int* offs;
            const int* csrc;
            const int* catr = nullptr;
            if (j == 0) {
                eps = eps_m + l;
                g1 = g1_m + (size_t)l * Hh;  be1 = be1_m + (size_t)l * Hh;
                bng = bn_g_m + (size_t)l * Ee; bnb = bn_b_m + (size_t)l * Ee;
                offs = S.offs_b; csrc = S.src_b; catr = S.atr_b;
            } else {
                int s = l * 2 + (j - 1);
                eps = eps_e + s;
                g1 = g1_e + (size_t)s * Hh;  be1 = be1_e + (size_t)s * Hh;
                bng = bn_g_e + (size_t)s * Ee; bnb = bn_b_e + (size_t)s * Ee;
                offs = (j == 1) ? S.offs_l : S.offs_r;
                csrc = (j == 1) ? S.src_l : S.src_r;
                mask = S.mask;
            }
            float* sumsH_c = S.sumsH + (size_t)c * 2 * Hh;
            float* sumsE_c = S.sumsE + (size_t)c * 2 * Ee;

            if (catr)
                gather_k<true><<<(Nn + 7) / 8, 256>>>(Xin, prev_sums, prev_g, prev_b,
                                                      offs, csrc, catr, bond_emb,
                                                      mask, eps, S.A1hi, S.A1lo);
            else
                gather_k<false><<<(Nn + 7) / 8, 256>>>(Xin, prev_sums, prev_g, prev_b,
                                                       offs, csrc, nullptr, nullptr,
                                                       mask, eps, S.A1hi, S.A1lo);

            mma_gemm_k<true, 128><<<g1d, 256, 4 * SMEM1>>>(
                S.A1hi, S.A1lo,
                S.W1Thi + (size_t)c * Hh * Ee, S.W1Tlo + (size_t)c * Hh * Ee,
                nullptr, S.t1hi, S.t1lo, sumsH_c, Nn, Ee, Hh);

            bnrelu_split_k<<<2500, 256>>>(
                S.t1hi, S.t1lo, sumsH_c, g1, be1, S.A2hi, S.A2lo);

            mma_gemm_k<false, 64><<<g2d, 256, 4 * SMEM2>>>(
                S.A2hi, S.A2lo,
                S.W2Thi + (size_t)c * Ee * Hh, S.W2Tlo + (size_t)c * Ee * Hh,
                S.hB, nullptr, nullptr, sumsE_c, Nn, Hh, Ee);

            prev_sums = sumsE_c;
            prev_g = bng;
            prev_b = bnb;
        }
    }

    bn_apply_final_k<<<(Nn * Ee / 4 + 255) / 256, 256>>>(S.hB, prev_sums, prev_g, prev_b,
                                                         (float*)d_out);
}

// round 17
// speedup vs baseline: 1.1541x; 1.0062x over previous
#include <cuda_runtime.h>
#include <cuda_fp16.h>
#include <cstddef>
#include <cstdint>

#define Nn 20000
#define Ee 256
#define Hh 512
#define Ll 5
#define NCONV 15
#define MB_CAP 320000
#define MX_CAP 160000

// ---------------- scratch (device globals; no allocations allowed) ----------
__device__ float g_h[Nn * Ee];
__device__ float g_hB[Nn * Ee];
__device__ float g_sumsH[NCONV * 2 * Hh];
__device__ float g_sumsE[NCONV * 2 * Ee];
__device__ float g_mask[Nn];
__device__ int   g_mask_dtype;

__device__ __half g_A1hi[Nn * Ee];
__device__ __half g_A1lo[Nn * Ee];
__device__ __half g_t1hi[Nn * Hh];
__device__ __half g_t1lo[Nn * Hh];
__device__ __half g_A2hi[Nn * Hh];
__device__ __half g_A2lo[Nn * Hh];
__device__ __half g_W1Thi[NCONV * Hh * Ee];
__device__ __half g_W1Tlo[NCONV * Hh * Ee];
__device__ __half g_W2Thi[NCONV * Ee * Hh];
__device__ __half g_W2Tlo[NCONV * Ee * Hh];

__device__ int g_deg[3 * Nn];
__device__ int g_cur[3 * Nn];
__device__ int g_offs_b[Nn + 1], g_offs_l[Nn + 1], g_offs_r[Nn + 1];
__device__ int g_src_b[MB_CAP];
__device__ int g_atr_b[MB_CAP];
__device__ int g_src_l[MX_CAP];
__device__ int g_src_r[MX_CAP];

// ---------------- helpers ----------------------------------------------------
__device__ __forceinline__ uint32_t smem_u32(const void* p) {
    uint32_t a;
    asm("{ .reg .u64 t; cvta.to.shared.u64 t, %1; cvt.u32.u64 %0, t; }" : "=r"(a) : "l"(p));
    return a;
}
#define SW64(off)  ((off) ^ (((off) >> 3) & 0x30))

#define LDSM_X4(r0, r1, r2, r3, addr) \
    asm volatile("ldmatrix.sync.aligned.m8n8.x4.shared.b16 {%0,%1,%2,%3}, [%4];" \
                 : "=r"(r0), "=r"(r1), "=r"(r2), "=r"(r3) : "r"(addr))

#define MMA16816(d, a0, a1, a2, a3, b0, b1) \
    asm volatile("mma.sync.aligned.m16n8k16.row.col.f32.f16.f16.f32 " \
                 "{%0,%1,%2,%3}, {%4,%5,%6,%7}, {%8,%9}, {%0,%1,%2,%3};" \
                 : "+f"((d)[0]), "+f"((d)[1]), "+f"((d)[2]), "+f"((d)[3]) \
                 : "r"(a0), "r"(a1), "r"(a2), "r"(a3), "r"(b0), "r"(b1))

#define CP_ASYNC16(dst, src, sz) \
    asm volatile("cp.async.cg.shared.global [%0], [%1], 16, %2;" \
                 :: "r"(dst), "l"(src), "r"(sz))
#define CP_COMMIT() asm volatile("cp.async.commit_group;" ::: "memory")
#define CP_WAIT0() asm volatile("cp.async.wait_group 0;" ::: "memory")
#define CP_WAIT2() asm volatile("cp.async.wait_group 2;" ::: "memory")

__device__ __forceinline__ uint32_t pack2h(float a, float b) {
    __half ha = __float2half_rn(a), hb = __float2half_rn(b);
    return (uint32_t)__half_as_ushort(ha) | ((uint32_t)__half_as_ushort(hb) << 16);
}

// ---------------- mask dtype detection ---------------------------------------
__global__ void detect_mask_k(const void* mask) {
    __shared__ int not_i32, not_f32;
    if (threadIdx.x == 0) { not_i32 = 0; not_f32 = 0; }
    __syncthreads();
    const unsigned* w = (const unsigned*)mask;
    int bad_i = 0, bad_f = 0;
    for (int i = threadIdx.x; i < Nn / 4; i += blockDim.x) {
        unsigned v = w[i];
        if (v > 1u) bad_i = 1;
        if (v != 0u && v != 0x3F800000u) bad_f = 1;
    }
    if (bad_i) atomicOr(&not_i32, 1);
    if (bad_f) atomicOr(&not_f32, 1);
    __syncthreads();
    if (threadIdx.x == 0) {
        if (!not_i32) g_mask_dtype = 0;
        else if (!not_f32) g_mask_dtype = 1;
        else g_mask_dtype = 2;
    }
}

__global__ void setup_k(const void* mask) {
    int i = blockIdx.x * blockDim.x + threadIdx.x;
    int stride = gridDim.x * blockDim.x;
    int dt = g_mask_dtype;
    for (int n = i; n < Nn; n += stride) {
        float m;
        if (dt == 0)      m = (((const int*)mask)[n] != 0) ? 1.f : 0.f;
        else if (dt == 1) m = (((const float*)mask)[n] != 0.f) ? 1.f : 0.f;
        else              m = (((const unsigned char*)mask)[n] != 0) ? 1.f : 0.f;
        g_mask[n] = m;
    }
    for (int n = i; n < 3 * Nn; n += stride) g_deg[n] = 0;
    for (int n = i; n < NCONV * 2 * Hh; n += stride) g_sumsH[n] = 0.f;
    for (int n = i; n < NCONV * 2 * Ee; n += stride) g_sumsE[n] = 0.f;
}

// ---------------- atom encoder ------------------------------------------------
__global__ void atom_encode_k(const int* __restrict__ x,
                              const float* __restrict__ emb,
                              float* __restrict__ h) {
    int n = blockIdx.x;
    int t = threadIdx.x;
    float4 acc = make_float4(0.f, 0.f, 0.f, 0.f);
#pragma unroll
    for (int f = 0; f < 9; f++) {
        int idx = __ldg(&x[n * 9 + f]);
        const float4* row = (const float4*)&emb[((size_t)(f * 128 + idx)) * Ee];
        float4 v = row[t];
        acc.x += v.x; acc.y += v.y; acc.z += v.z; acc.w += v.w;
    }
    ((float4*)h)[(size_t)n * (Ee / 4) + t] = acc;
}

// ---------------- CSR build (fused across 3 orientations) --------------------
__global__ void hist_all_k(const int* __restrict__ ei, const int* __restrict__ xei,
                           int M, int MX) {
    int e = blockIdx.x * blockDim.x + threadIdx.x;
    if (e < M) atomicAdd(&g_deg[ei[M + e]], 1);
    else if (e < M + MX) atomicAdd(&g_deg[Nn + xei[MX + (e - M)]], 1);
    else if (e < M + 2 * MX) atomicAdd(&g_deg[2 * Nn + xei[e - M - MX]], 1);
}

__global__ void scan_all_k() {
    int which = blockIdx.x;
    const int* deg = g_deg + which * Nn;
    int* cur = g_cur + which * Nn;
    int* offs = (which == 0) ? g_offs_b : (which == 1) ? g_offs_l : g_offs_r;
    __shared__ int ssum[1024];
    int t = threadIdx.x;
    const int PER = (Nn + 1023) / 1024;  // 20
    int loc[20];
    int s = 0;
#pragma unroll
    for (int i = 0; i < PER; i++) {
        int idx = t * PER + i;
        int v = (idx < Nn) ? deg[idx] : 0;
        loc[i] = s;
        s += v;
    }
    ssum[t] = s;
    __syncthreads();
    for (int off = 1; off < 1024; off <<= 1) {
        int v = (t >= off) ? ssum[t - off] : 0;
        __syncthreads();
        ssum[t] += v;
        __syncthreads();
    }
    int pre = (t > 0) ? ssum[t - 1] : 0;
#pragma unroll
    for (int i = 0; i < PER; i++) {
        int idx = t * PER + i;
        if (idx < Nn) {
            offs[idx] = pre + loc[i];
            cur[idx] = pre + loc[i];
        }
    }
    if (t == 1023) offs[Nn] = ssum[1023];
}

__global__ void fill_all_k(const int* __restrict__ ei, const int* __restrict__ xei,
                           const int* __restrict__ ea, int M, int MX) {
    int e = blockIdx.x * blockDim.x + threadIdx.x;
    if (e < M) {
        int p = atomicAdd(&g_cur[ei[M + e]], 1);
        if (p < MB_CAP) {
            g_src_b[p] = ei[e];
            g_atr_b[p] = ea[e * 3] | (ea[e * 3 + 1] << 3) | (ea[e * 3 + 2] << 6);
        }
    } else if (e < M + MX) {
        int j = e - M;
        int p = atomicAdd(&g_cur[Nn + xei[MX + j]], 1);
        if (p < MX_CAP) g_src_l[p] = xei[j];
    } else if (e < M + 2 * MX) {
        int j = e - M - MX;
        int p = atomicAdd(&g_cur[2 * Nn + xei[j]], 1);
        if (p < MX_CAP) g_src_r[p] = xei[MX + j];
    }
}

// ---------------- merged weight transpose + fp16 split ------------------------
__global__ void wsplit_all_k(const float* __restrict__ W1m, const float* __restrict__ W1e,
                             const float* __restrict__ W2m, const float* __restrict__ W2e) {
    int z = blockIdx.z;
    int which = z / NCONV;
    int c = z % NCONV;
    int l = c / 3, j = c % 3;
    const float* W;
    __half *Thi, *Tlo;
    int K, N;
    if (which == 0) {
        K = Ee; N = Hh;
        W = j ? W1e + (size_t)(l * 2 + j - 1) * Ee * Hh : W1m + (size_t)l * Ee * Hh;
        Thi = g_W1Thi + (size_t)c * Hh * Ee;
        Tlo = g_W1Tlo + (size_t)c * Hh * Ee;
    } else {
        K = Hh; N = Ee;
        W = j ? W2e + (size_t)(l * 2 + j - 1) * Hh * Ee : W2m + (size_t)l * Hh * Ee;
        Thi = g_W2Thi + (size_t)c * Ee * Hh;
        Tlo = g_W2Tlo + (size_t)c * Ee * Hh;
    }
    int kb = blockIdx.x * 32, nb = blockIdx.y * 32;
    if (kb >= K || nb >= N) return;
    __shared__ float t[32][33];
    int tx = threadIdx.x, ty = threadIdx.y;
    for (int i = ty; i < 32; i += 8)
        t[i][tx] = W[(size_t)(kb + i) * N + nb + tx];
    __syncthreads();
    for (int i = ty; i < 32; i += 8) {
        float v = t[tx][i];
        __half hi = __float2half_rn(v);
        float lo = v - __half2float(hi);
        Thi[(size_t)(nb + i) * K + kb + tx] = hi;
        Tlo[(size_t)(nb + i) * K + kb + tx] = __float2half_rn(lo);
    }
}

// ---------------- fused CSR gather (edge loop unrolled x2) --------------------
template <bool BOND>
__global__ __launch_bounds__(256) void gather_k(
    const float* __restrict__ Xin,
    const float* __restrict__ insums, const float* __restrict__ ing,
    const float* __restrict__ inb,
    const int* __restrict__ offs, const int* __restrict__ csrc,
    const int* __restrict__ catr, const float* __restrict__ bemb,
    const float* __restrict__ mask, const float* __restrict__ eps,
    __half* __restrict__ Ahi, __half* __restrict__ Alo) {
    __shared__ float s_sc[Ee], s_sh[Ee];
    for (int c = threadIdx.x; c < Ee; c += blockDim.x) {
        if (insums) {
            float mean = insums[c] * (1.f / Nn);
            float var = insums[Ee + c] * (1.f / Nn) - mean * mean;
            float s = ing[c] * rsqrtf(var + 1e-5f);
            s_sc[c] = s;
            s_sh[c] = inb[c] - mean * s;
        } else {
            s_sc[c] = 1.f;
            s_sh[c] = 0.f;
        }
    }
    __syncthreads();

    int node = blockIdx.x * 8 + (threadIdx.x >> 5);
    if (node >= Nn) return;
    int lane = threadIdx.x & 31;
    int c0 = lane * 8;
    float flo = insums ? 0.f : -3.4e38f;

    float4 sc0 = *(const float4*)&s_sc[c0], sc1 = *(const float4*)&s_sc[c0 + 4];
    float4 sh0 = *(const float4*)&s_sh[c0], sh1 = *(const float4*)&s_sh[c0 + 4];

    float a0 = 0.f, a1 = 0.f, a2 = 0.f, a3 = 0.f, a4 = 0.f, a5 = 0.f, a6 = 0.f, a7 = 0.f;
    int e0 = __ldg(&offs[node]), e1 = __ldg(&offs[node + 1]);

    int e = e0;
    for (; e + 2 <= e1; e += 2) {
        int sA = __ldg(&csrc[e]);
        int sB = __ldg(&csrc[e + 1]);
        const float4* xrA = (const float4*)&Xin[(size_t)sA * Ee + c0];
        const float4* xrB = (const float4*)&Xin[(size_t)sB * Ee + c0];
        float4 xA0 = __ldg(xrA), xA1 = __ldg(xrA + 1);
        float4 xB0 = __ldg(xrB), xB1 = __ldg(xrB + 1);
        float4 bA0, bA1, bB0, bB1;
        if (BOND) {
            int mtA = __ldg(&catr[e]);
            int mtB = __ldg(&catr[e + 1]);
            const float4* pA0 = (const float4*)&bemb[(size_t)(mtA & 7) * Ee + c0];
            const float4* pA1 = (const float4*)&bemb[(size_t)(8 + ((mtA >> 3) & 7)) * Ee + c0];
            const float4* pA2 = (const float4*)&bemb[(size_t)(16 + ((mtA >> 6) & 7)) * Ee + c0];
            const float4* pB0 = (const float4*)&bemb[(size_t)(mtB & 7) * Ee + c0];
            const float4* pB1 = (const float4*)&bemb[(size_t)(8 + ((mtB >> 3) & 7)) * Ee + c0];
            const float4* pB2 = (const float4*)&bemb[(size_t)(16 + ((mtB >> 6) & 7)) * Ee + c0];
            float4 a00 = __ldg(pA0), a01 = __ldg(pA0 + 1);
            float4 a10 = __ldg(pA1), a11 = __ldg(pA1 + 1);
            float4 a20 = __ldg(pA2), a21 = __ldg(pA2 + 1);
            float4 b00 = __ldg(pB0), b01 = __ldg(pB0 + 1);
            float4 b10 = __ldg(pB1), b11 = __ldg(pB1 + 1);
            float4 b20 = __ldg(pB2), b21 = __ldg(pB2 + 1);
            bA0.x = a00.x + a10.x + a20.x; bA0.y = a00.y + a10.y + a20.y;
            bA0.z = a00.z + a10.z + a20.z; bA0.w = a00.w + a10.w + a20.w;
            bA1.x = a01.x + a11.x + a21.x; bA1.y = a01.y + a11.y + a21.y;
            bA1.z = a01.z + a11.z + a21.z; bA1.w = a01.w + a11.w + a21.w;
            bB0.x = b00.x + b10.x + b20.x; bB0.y = b00.y + b10.y + b20.y;
            bB0.z = b00.z + b10.z + b20.z; bB0.w = b00.w + b10.w + b20.w;
            bB1.x = b01.x + b11.x + b21.x; bB1.y = b01.y + b11.y + b21.y;
            bB1.z = b01.z + b11.z + b21.z; bB1.w = b01.w + b11.w + b21.w;
        }
        {
            float v0 = fmaxf(fmaf(xA0.x, sc0.x, sh0.x), flo);
            float v1 = fmaxf(fmaf(xA0.y, sc0.y, sh0.y), flo);
            float v2 = fmaxf(fmaf(xA0.z, sc0.z, sh0.z), flo);
            float v3 = fmaxf(fmaf(xA0.w, sc0.w, sh0.w), flo);
            float v4 = fmaxf(fmaf(xA1.x, sc1.x, sh1.x), flo);
            float v5 = fmaxf(fmaf(xA1.y, sc1.y, sh1.y), flo);
            float v6 = fmaxf(fmaf(xA1.z, sc1.z, sh1.z), flo);
            float v7 = fmaxf(fmaf(xA1.w, sc1.w, sh1.w), flo);
            if (BOND) {
                v0 += bA0.x; v1 += bA0.y; v2 += bA0.z; v3 += bA0.w;
                v4 += bA1.x; v5 += bA1.y; v6 += bA1.z; v7 += bA1.w;
            }
            a0 += fmaxf(v0, 0.f); a1 += fmaxf(v1, 0.f);
            a2 += fmaxf(v2, 0.f); a3 += fmaxf(v3, 0.f);
            a4 += fmaxf(v4, 0.f); a5 += fmaxf(v5, 0.f);
            a6 += fmaxf(v6, 0.f); a7 += fmaxf(v7, 0.f);
        }
        {
            float v0 = fmaxf(fmaf(xB0.x, sc0.x, sh0.x), flo);
            float v1 = fmaxf(fmaf(xB0.y, sc0.y, sh0.y), flo);
            float v2 = fmaxf(fmaf(xB0.z, sc0.z, sh0.z), flo);
            float v3 = fmaxf(fmaf(xB0.w, sc0.w, sh0.w), flo);
            float v4 = fmaxf(fmaf(xB1.x, sc1.x, sh1.x), flo);
            float v5 = fmaxf(fmaf(xB1.y, sc1.y, sh1.y), flo);
            float v6 = fmaxf(fmaf(xB1.z, sc1.z, sh1.z), flo);
            float v7 = fmaxf(fmaf(xB1.w, sc1.w, sh1.w), flo);
            if (BOND) {
                v0 += bB0.x; v1 += bB0.y; v2 += bB0.z; v3 += bB0.w;
                v4 += bB1.x; v5 += bB1.y; v6 += bB1.z; v7 += bB1.w;
            }
            a0 += fmaxf(v0, 0.f); a1 += fmaxf(v1, 0.f);
            a2 += fmaxf(v2, 0.f); a3 += fmaxf(v3, 0.f);
            a4 += fmaxf(v4, 0.f); a5 += fmaxf(v5, 0.f);
            a6 += fmaxf(v6, 0.f); a7 += fmaxf(v7, 0.f);
        }
    }
    for (; e < e1; e++) {
        int s = __ldg(&csrc[e]);
        const float4* xr = (const float4*)&Xin[(size_t)s * Ee + c0];
        float4 x0 = __ldg(xr), x1 = __ldg(xr + 1);
        float v0 = fmaxf(fmaf(x0.x, sc0.x, sh0.x), flo);
        float v1 = fmaxf(fmaf(x0.y, sc0.y, sh0.y), flo);
        float v2 = fmaxf(fmaf(x0.z, sc0.z, sh0.z), flo);
        float v3 = fmaxf(fmaf(x0.w, sc0.w, sh0.w), flo);
        float v4 = fmaxf(fmaf(x1.x, sc1.x, sh1.x), flo);
        float v5 = fmaxf(fmaf(x1.y, sc1.y, sh1.y), flo);
        float v6 = fmaxf(fmaf(x1.z, sc1.z, sh1.z), flo);
        float v7 = fmaxf(fmaf(x1.w, sc1.w, sh1.w), flo);
        if (BOND) {
            int mt = __ldg(&catr[e]);
            const float4* b0 = (const float4*)&bemb[(size_t)(mt & 7) * Ee + c0];
            const float4* b1 = (const float4*)&bemb[(size_t)(8 + ((mt >> 3) & 7)) * Ee + c0];
            const float4* b2 = (const float4*)&bemb[(size_t)(16 + ((mt >> 6) & 7)) * Ee + c0];
            float4 p0 = __ldg(b0), p1 = __ldg(b0 + 1);
            float4 q0 = __ldg(b1), q1 = __ldg(b1 + 1);
            float4 r0 = __ldg(b2), r1 = __ldg(b2 + 1);
            v0 += p0.x + q0.x + r0.x; v1 += p0.y + q0.y + r0.y;
            v2 += p0.z + q0.z + r0.z; v3 += p0.w + q0.w + r0.w;
            v4 += p1.x + q1.x + r1.x; v5 += p1.y + q1.y + r1.y;
            v6 += p1.z + q1.z + r1.z; v7 += p1.w + q1.w + r1.w;
        }
        a0 += fmaxf(v0, 0.f); a1 += fmaxf(v1, 0.f);
        a2 += fmaxf(v2, 0.f); a3 += fmaxf(v3, 0.f);
        a4 += fmaxf(v4, 0.f); a5 += fmaxf(v5, 0.f);
        a6 += fmaxf(v6, 0.f); a7 += fmaxf(v7, 0.f);
    }

    const float4* xr = (const float4*)&Xin[(size_t)node * Ee + c0];
    float4 x0 = __ldg(xr), x1 = __ldg(xr + 1);
    float s0 = fmaxf(fmaf(x0.x, sc0.x, sh0.x), flo);
    float s1 = fmaxf(fmaf(x0.y, sc0.y, sh0.y), flo);
    float s2 = fmaxf(fmaf(x0.z, sc0.z, sh0.z), flo);
    float s3 = fmaxf(fmaf(x0.w, sc0.w, sh0.w), flo);
    float s4 = fmaxf(fmaf(x1.x, sc1.x, sh1.x), flo);
    float s5 = fmaxf(fmaf(x1.y, sc1.y, sh1.y), flo);
    float s6 = fmaxf(fmaf(x1.z, sc1.z, sh1.z), flo);
    float s7 = fmaxf(fmaf(x1.w, sc1.w, sh1.w), flo);
    float m = mask ? __ldg(&mask[node]) : 1.f;
    float ef = (1.f + __ldg(eps)) * m;
    float p0 = fmaf(ef, s0, a0), p1 = fmaf(ef, s1, a1);
    float p2 = fmaf(ef, s2, a2), p3 = fmaf(ef, s3, a3);
    float p4 = fmaf(ef, s4, a4), p5 = fmaf(ef, s5, a5);
    float p6 = fmaf(ef, s6, a6), p7 = fmaf(ef, s7, a7);
    uint4 hi, lo;
    {
        __half h0 = __float2half_rn(p0), h1 = __float2half_rn(p1);
        __half h2 = __float2half_rn(p2), h3 = __float2half_rn(p3);
        __half h4 = __float2half_rn(p4), h5 = __float2half_rn(p5);
        __half h6 = __float2half_rn(p6), h7 = __float2half_rn(p7);
        hi.x = (uint32_t)__half_as_ushort(h0) | ((uint32_t)__half_as_ushort(h1) << 16);
        hi.y = (uint32_t)__half_as_ushort(h2) | ((uint32_t)__half_as_ushort(h3) << 16);
        hi.z = (uint32_t)__half_as_ushort(h4) | ((uint32_t)__half_as_ushort(h5) << 16);
        hi.w = (uint32_t)__half_as_ushort(h6) | ((uint32_t)__half_as_ushort(h7) << 16);
        lo.x = pack2h(p0 - __half2float(h0), p1 - __half2float(h1));
        lo.y = pack2h(p2 - __half2float(h2), p3 - __half2float(h3));
        lo.z = pack2h(p4 - __half2float(h4), p5 - __half2float(h5));
        lo.w = pack2h(p6 - __half2float(h6), p7 - __half2float(h7));
    }
    *(uint4*)&Ahi[(size_t)node * Ee + c0] = hi;
    *(uint4*)&Alo[(size_t)node * Ee + c0] = lo;
}

// ---------------- t1 pair -> inline BN -> relu -> split (4 elems/thread) -----
__global__ void bnrelu_split_k(const __half* __restrict__ Thi, const __half* __restrict__ Tlo,
                               const float* __restrict__ sums,
                               const float* __restrict__ g,
                               const float* __restrict__ b,
                               __half* __restrict__ Ahi, __half* __restrict__ Alo) {
    __shared__ float s_sc[Hh], s_sh[Hh];
    for (int c = threadIdx.x; c < Hh; c += blockDim.x) {
        float mean = sums[c] * (1.f / Nn);
        float var = sums[Hh + c] * (1.f / Nn) - mean * mean;
        float s = g[c] * rsqrtf(var + 1e-5f);
        s_sc[c] = s;
        s_sh[c] = b[c] - mean * s;
    }
    __syncthreads();
#pragma unroll
    for (int u = 0; u < 4; u++) {
        int i = blockIdx.x * 1024 + u * 256 + threadIdx.x;
        if (i >= Nn * Hh / 4) return;
        int c = (i & (Hh / 4 - 1)) * 4;
        uint2 vh = ((const uint2*)Thi)[i];
        uint2 vl = ((const uint2*)Tlo)[i];
        float2 h0 = __half22float2(*(__half2*)&vh.x);
        float2 h1 = __half22float2(*(__half2*)&vh.y);
        float2 l0 = __half22float2(*(__half2*)&vl.x);
        float2 l1 = __half22float2(*(__half2*)&vl.y);
        float x0 = h0.x + l0.x, x1 = h0.y + l0.y, x2 = h1.x + l1.x, x3 = h1.y + l1.y;
        x0 = fmaxf(fmaf(x0, s_sc[c + 0], s_sh[c + 0]), 0.f);
        x1 = fmaxf(fmaf(x1, s_sc[c + 1], s_sh[c + 1]), 0.f);
        x2 = fmaxf(fmaf(x2, s_sc[c + 2], s_sh[c + 2]), 0.f);
        x3 = fmaxf(fmaf(x3, s_sc[c + 3], s_sh[c + 3]), 0.f);
        __half q0 = __float2half_rn(x0), q1 = __float2half_rn(x1);
        __half q2 = __float2half_rn(x2), q3 = __float2half_rn(x3);
        uint2 hi, lo;
        hi.x = (uint32_t)__half_as_ushort(q0) | ((uint32_t)__half_as_ushort(q1) << 16);
        hi.y = (uint32_t)__half_as_ushort(q2) | ((uint32_t)__half_as_ushort(q3) << 16);
        lo.x = pack2h(x0 - __half2float(q0), x1 - __half2float(q1));
        lo.y = pack2h(x2 - __half2float(q2), x3 - __half2float(q3));
        ((uint2*)Ahi)[i] = hi;
        ((uint2*)Alo)[i] = lo;
    }
}

// ---------------- mma.sync fp16x3 GEMM: 64xNT tile, K32, 4-stage, 2 CTA/SM ---
// NT=128: warps 2x4 (32x32 each). NT=64: warps 4x2 (16x32 each).
// One __syncthreads per iteration (stage count 4 > issue distance 3 arg).
template <bool HALF_OUT, int NT>
__global__ __launch_bounds__(256, 2) void mma_gemm_k(
    const __half* __restrict__ Ahi, const __half* __restrict__ Alo,
    const __half* __restrict__ Bhi, const __half* __restrict__ Blo,
    float* __restrict__ C, __half* __restrict__ Chi, __half* __restrict__ Clo,
    float* __restrict__ sums, int Mr, int K, int Nc) {
    constexpr int NWC = NT / 32;            // n-warp columns: 4 or 2
    constexpr int MF = (NT == 128) ? 2 : 1; // m-frags per warp
    constexpr int SA_LO_O = 4096;
    constexpr int SB_HI_O = 8192;
    constexpr int SB_LO_O = 8192 + NT * 64;
    constexpr int STAGE = 8192 + 2 * NT * 64;

    extern __shared__ char smem[];
    const uint32_t sb = smem_u32(smem);
    const int tid = threadIdx.x;
    const int lane = tid & 31, wid = tid >> 5;
    const int wm = (wid / NWC) * (MF * 16);
    const int wn = (wid % NWC) * 32;
    const int m0 = blockIdx.y * 64;
    const int n0 = blockIdx.x * NT;
    const int nkt = K >> 5;

    float acc[MF][4][4];
#pragma unroll
    for (int a = 0; a < MF; a++)
#pragma unroll
        for (int b = 0; b < 4; b++)
#pragma unroll
            for (int c = 0; c < 4; c++) acc[a][b][c] = 0.f;

    const int arow = tid >> 2, aq = tid & 3;
    const bool arow_ok = (m0 + arow) < Mr;
    const int arow_cl = arow_ok ? (m0 + arow) : 0;
    const char* pAhi = (const char*)(Ahi + (size_t)arow_cl * K);
    const char* pAlo = (const char*)(Alo + (size_t)arow_cl * K);
    const int asz = arow_ok ? 16 : 0;
    const uint32_t aso = SW64((uint32_t)(arow * 64 + aq * 16));

    // B loader: NT=128 -> 2 thr/row x 2 chunks; NT=64 -> 4 thr/row x 1 chunk
    const int brow = (NT == 128) ? (tid >> 1) : (tid >> 2);
    const int bq   = (NT == 128) ? (tid & 1) : (tid & 3);
    const char* pBhi = (const char*)(Bhi + (size_t)(n0 + brow) * K);
    const char* pBlo = (const char*)(Blo + (size_t)(n0 + brow) * K);
    const uint32_t bso0 = (NT == 128) ? SW64((uint32_t)(brow * 64 + bq * 32))
                                      : SW64((uint32_t)(brow * 64 + bq * 16));
    const uint32_t bso1 = SW64((uint32_t)(brow * 64 + bq * 32 + 16));  // NT==128 only

    auto issue = [&](int stage, int kt) {
        const size_t gk = (size_t)kt * 64;
        const uint32_t st = sb + stage * STAGE;
        CP_ASYNC16(st + 0 + aso, pAhi + gk + aq * 16, asz);
        CP_ASYNC16(st + SA_LO_O + aso, pAlo + gk + aq * 16, asz);
        if (NT == 128) {
            CP_ASYNC16(st + SB_HI_O + bso0, pBhi + gk + bq * 32, 16);
            CP_ASYNC16(st + SB_HI_O + bso1, pBhi + gk + bq * 32 + 16, 16);
            CP_ASYNC16(st + SB_LO_O + bso0, pBlo + gk + bq * 32, 16);
            CP_ASYNC16(st + SB_LO_O + bso1, pBlo + gk + bq * 32 + 16, 16);
        } else {
            CP_ASYNC16(st + SB_HI_O + bso0, pBhi + gk + bq * 16, 16);
            CP_ASYNC16(st + SB_LO_O + bso0, pBlo + gk + bq * 16, 16);
        }
    };

    issue(0, 0); CP_COMMIT();
    issue(1, 1); CP_COMMIT();
    issue(2, 2); CP_COMMIT();

    for (int kt = 0; kt < nkt; kt++) {
        if (kt + 3 < nkt) CP_WAIT2(); else CP_WAIT0();
        __syncthreads();
        if (kt + 3 < nkt) {
            issue((kt + 3) & 3, kt + 3);
            CP_COMMIT();
        }

        const uint32_t st = sb + (kt & 3) * STAGE;
#pragma unroll
        for (int ks = 0; ks < 2; ks++) {
            const int k0 = ks * 16;
            const uint32_t ar = wm + (lane & 15);
            const uint32_t ac = k0 + ((lane >> 4) << 3);
            const uint32_t br = wn + (lane & 7) + ((lane >> 4) << 3);
            const uint32_t bc = k0 + (((lane >> 3) & 1) << 3);
            uint32_t bhi[8], blo[8], ah[4 * MF], al[4 * MF];
#pragma unroll
            for (int nb = 0; nb < 2; nb++) {
                uint32_t off = SW64((br + nb * 16) * 64 + bc * 2);
                LDSM_X4(bhi[nb * 4 + 0], bhi[nb * 4 + 1], bhi[nb * 4 + 2], bhi[nb * 4 + 3],
                        st + SB_HI_O + off);
                LDSM_X4(blo[nb * 4 + 0], blo[nb * 4 + 1], blo[nb * 4 + 2], blo[nb * 4 + 3],
                        st + SB_LO_O + off);
            }
#pragma unroll
            for (int mf = 0; mf < MF; mf++) {
                uint32_t off = SW64((ar + mf * 16) * 64 + ac * 2);
                LDSM_X4(ah[mf * 4 + 0], ah[mf * 4 + 1], ah[mf * 4 + 2], ah[mf * 4 + 3],
                        st + 0 + off);
                LDSM_X4(al[mf * 4 + 0], al[mf * 4 + 1], al[mf * 4 + 2], al[mf * 4 + 3],
                        st + SA_LO_O + off);
            }
#pragma unroll
            for (int mf = 0; mf < MF; mf++)
#pragma unroll
                for (int nf = 0; nf < 4; nf++) {
                    int bi = (nf >> 1) * 4 + (nf & 1) * 2;
                    MMA16816(acc[mf][nf], ah[mf * 4], ah[mf * 4 + 1], ah[mf * 4 + 2],
                             ah[mf * 4 + 3], bhi[bi], bhi[bi + 1]);
                    MMA16816(acc[mf][nf], ah[mf * 4], ah[mf * 4 + 1], ah[mf * 4 + 2],
                             ah[mf * 4 + 3], blo[bi], blo[bi + 1]);
                    MMA16816(acc[mf][nf], al[mf * 4], al[mf * 4 + 1], al[mf * 4 + 2],
                             al[mf * 4 + 3], bhi[bi], bhi[bi + 1]);
                }
        }
    }

    // epilogue
#pragma unroll
    for (int mf = 0; mf < MF; mf++) {
        int r = m0 + wm + mf * 16 + (lane >> 2);
#pragma unroll
        for (int nf = 0; nf < 4; nf++) {
            int col = n0 + wn + nf * 8 + (lane & 3) * 2;
            float a0 = acc[mf][nf][0], a1 = acc[mf][nf][1];
            float a2 = acc[mf][nf][2], a3 = acc[mf][nf][3];
            if (HALF_OUT) {
                if (r < Mr) {
                    __half h0 = __float2half_rn(a0), h1 = __float2half_rn(a1);
                    *(uint32_t*)&Chi[(size_t)r * Nc + col] =
                        (uint32_t)__half_as_ushort(h0) | ((uint32_t)__half_as_ushort(h1) << 16);
                    *(uint32_t*)&Clo[(size_t)r * Nc + col] =
                        pack2h(a0 - __half2float(h0), a1 - __half2float(h1));
                }
                if (r + 8 < Mr) {
                    __half h2 = __float2half_rn(a2), h3 = __float2half_rn(a3);
                    *(uint32_t*)&Chi[(size_t)(r + 8) * Nc + col] =
                        (uint32_t)__half_as_ushort(h2) | ((uint32_t)__half_as_ushort(h3) << 16);
                    *(uint32_t*)&Clo[(size_t)(r + 8) * Nc + col] =
                        pack2h(a2 - __half2float(h2), a3 - __half2float(h3));
                }
            } else {
                if (r < Mr)
                    *(float2*)&C[(size_t)r * Nc + col] = make_float2(a0, a1);
                if (r + 8 < Mr)
                    *(float2*)&C[(size_t)(r + 8) * Nc + col] = make_float2(a2, a3);
            }
        }
    }

    // fused BN column stats (padded rows contribute exactly 0)
#pragma unroll
    for (int nf = 0; nf < 4; nf++) {
        float s0 = 0.f, s1 = 0.f, q0 = 0.f, q1 = 0.f;
#pragma unroll
        for (int mf = 0; mf < MF; mf++) {
            float a0 = acc[mf][nf][0], a1 = acc[mf][nf][1];
            float a2 = acc[mf][nf][2], a3 = acc[mf][nf][3];
            s0 += a0 + a2; s1 += a1 + a3;
            q0 += a0 * a0 + a2 * a2; q1 += a1 * a1 + a3 * a3;
        }
#pragma unroll
        for (int off = 4; off < 32; off <<= 1) {
            s0 += __shfl_xor_sync(0xffffffff, s0, off);
            s1 += __shfl_xor_sync(0xffffffff, s1, off);
            q0 += __shfl_xor_sync(0xffffffff, q0, off);
            q1 += __shfl_xor_sync(0xffffffff, q1, off);
        }
        if (lane < 4) {
            int c = n0 + wn + nf * 8 + lane * 2;
            atomicAdd(&sums[c], s0);
            atomicAdd(&sums[c + 1], s1);
            atomicAdd(&sums[Nc + c], q0);
            atomicAdd(&sums[Nc + c + 1], q1);
        }
    }
}

// ---------------- final BN apply (inline scale/shift) ------------------------
__global__ void bn_apply_final_k(const float* __restrict__ X,
                                 const float* __restrict__ sums,
                                 const float* __restrict__ g,
                                 const float* __restrict__ b,
                                 float* __restrict__ Y) {
    __shared__ float s_sc[Ee], s_sh[Ee];
    for (int c = threadIdx.x; c < Ee; c += blockDim.x) {
        float mean = sums[c] * (1.f / Nn);
        float var = sums[Ee + c] * (1.f / Nn) - mean * mean;
        float s = g[c] * rsqrtf(var + 1e-5f);
        s_sc[c] = s;
        s_sh[c] = b[c] - mean * s;
    }
    __syncthreads();
    int i = blockIdx.x * blockDim.x + threadIdx.x;
    if (i >= Nn * Ee / 4) return;
    int c = (i & 63) * 4;
    float4 v = ((const float4*)X)[i];
    v.x = fmaf(v.x, s_sc[c + 0], s_sh[c + 0]);
    v.y = fmaf(v.y, s_sc[c + 1], s_sh[c + 1]);
    v.z = fmaf(v.z, s_sc[c + 2], s_sh[c + 2]);
    v.w = fmaf(v.w, s_sc[c + 3], s_sh[c + 3]);
    ((float4*)Y)[i] = v;
}

// ---------------- host orchestration ----------------------------------------
struct Scratch {
    float *h, *hB, *sumsH, *sumsE, *mask;
    __half *A1hi, *A1lo, *t1hi, *t1lo, *A2hi, *A2lo;
    __half *W1Thi, *W1Tlo, *W2Thi, *W2Tlo;
    int *offs_b, *offs_l, *offs_r, *src_b, *atr_b, *src_l, *src_r;
};

extern "C" void kernel_launch(void* const* d_in, const int* in_sizes, int n_in,
                              void* d_out, int out_size) {
    const int* x       = (const int*)d_in[0];
    const int* ei      = (const int*)d_in[1];
    const int* ea      = (const int*)d_in[2];
    const int* xei     = (const int*)d_in[3];
    const void* mask_raw = d_in[4];
    const float* atom_emb = (const float*)d_in[5];
    const float* bond_emb = (const float*)d_in[6];
    const float* eps_m = (const float*)d_in[7];
    const float* W1_m  = (const float*)d_in[8];
    const float* g1_m  = (const float*)d_in[10];
    const float* be1_m = (const float*)d_in[11];
    const float* W2_m  = (const float*)d_in[12];
    const float* bn_g_m = (const float*)d_in[14];
    const float* bn_b_m = (const float*)d_in[15];
    const float* eps_e = (const float*)d_in[16];
    const float* W1_e  = (const float*)d_in[17];
    const float* g1_e  = (const float*)d_in[18];
    const float* be1_e = (const float*)d_in[19];
    const float* W2_e  = (const float*)d_in[20];
    const float* bn_g_e = (const float*)d_in[21];
    const float* bn_b_e = (const float*)d_in[22];

    const int M  = in_sizes[1] / 2;
    const int MX = in_sizes[3] / 2;

    const int SMEM64 = 8192 + 2 * 64 * 64;   // 16384 per stage (NT=64)
    cudaFuncSetAttribute(mma_gemm_k<true, 64>,
                         cudaFuncAttributeMaxDynamicSharedMemorySize, 4 * SMEM64);
    cudaFuncSetAttribute(mma_gemm_k<false, 64>,
                         cudaFuncAttributeMaxDynamicSharedMemorySize, 4 * SMEM64);

    Scratch S;
    cudaGetSymbolAddress((void**)&S.h, g_h);
    cudaGetSymbolAddress((void**)&S.hB, g_hB);
    cudaGetSymbolAddress((void**)&S.sumsH, g_sumsH);
    cudaGetSymbolAddress((void**)&S.sumsE, g_sumsE);
    cudaGetSymbolAddress((void**)&S.mask, g_mask);
    cudaGetSymbolAddress((void**)&S.A1hi, g_A1hi);
    cudaGetSymbolAddress((void**)&S.A1lo, g_A1lo);
    cudaGetSymbolAddress((void**)&S.t1hi, g_t1hi);
    cudaGetSymbolAddress((void**)&S.t1lo, g_t1lo);
    cudaGetSymbolAddress((void**)&S.A2hi, g_A2hi);
    cudaGetSymbolAddress((void**)&S.A2lo, g_A2lo);
    cudaGetSymbolAddress((void**)&S.W1Thi, g_W1Thi);
    cudaGetSymbolAddress((void**)&S.W1Tlo, g_W1Tlo);
    cudaGetSymbolAddress((void**)&S.W2Thi, g_W2Thi);
    cudaGetSymbolAddress((void**)&S.W2Tlo, g_W2Tlo);
    cudaGetSymbolAddress((void**)&S.offs_b, g_offs_b);
    cudaGetSymbolAddress((void**)&S.offs_l, g_offs_l);
    cudaGetSymbolAddress((void**)&S.offs_r, g_offs_r);
    cudaGetSymbolAddress((void**)&S.src_b, g_src_b);
    cudaGetSymbolAddress((void**)&S.atr_b, g_atr_b);
    cudaGetSymbolAddress((void**)&S.src_l, g_src_l);
    cudaGetSymbolAddress((void**)&S.src_r, g_src_r);

    const int TOT = M + 2 * MX;

    detect_mask_k<<<1, 256>>>(mask_raw);
    setup_k<<<79, 256>>>(mask_raw);
    atom_encode_k<<<Nn, 64>>>(x, atom_emb, S.h);
    hist_all_k<<<(TOT + 255) / 256, 256>>>(ei, xei, M, MX);
    scan_all_k<<<3, 1024>>>();
    fill_all_k<<<(TOT + 255) / 256, 256>>>(ei, xei, ea, M, MX);
    wsplit_all_k<<<dim3(16, 16, 2 * NCONV), dim3(32, 8)>>>(W1_m, W1_e, W2_m, W2_e);

    const float* prev_sums = nullptr;
    const float* prev_g = nullptr;
    const float* prev_b = nullptr;

    dim3 g1d(Hh / 64, (Nn + 63) / 64);    // GEMM1: 64x64 tiles (wave-quantization fix)
    dim3 g2d(Ee / 64, (Nn + 63) / 64);    // GEMM2: 64x64 tiles

    for (int l = 0; l < Ll; l++) {
        for (int j = 0; j < 3; j++) {
            int c = l * 3 + j;
            const float* Xin = (c == 0) ? S.h : S.hB;
            const float* eps;
            const float* g1;
            const float* be1;
            const float* bng;
            const float* bnb;
            const float* mask = nullptr;
            const int* offs;
            const int* csrc;
            const int* catr = nullptr;
            if (j == 0) {
                eps = eps_m + l;
                g1 = g1_m + (size_t)l * Hh;  be1 = be1_m + (size_t)l * Hh;
                bng = bn_g_m + (size_t)l * Ee; bnb = bn_b_m + (size_t)l * Ee;
                offs = S.offs_b; csrc = S.src_b; catr = S.atr_b;
            } else {
                int s = l * 2 + (j - 1);
                eps = eps_e + s;
                g1 = g1_e + (size_t)s * Hh;  be1 = be1_e + (size_t)s * Hh;
                bng = bn_g_e + (size_t)s * Ee; bnb = bn_b_e + (size_t)s * Ee;
                offs = (j == 1) ? S.offs_l : S.offs_r;
                csrc = (j == 1) ? S.src_l : S.src_r;
                mask = S.mask;
            }
            float* sumsH_c = S.sumsH + (size_t)c * 2 * Hh;
            float* sumsE_c = S.sumsE + (size_t)c * 2 * Ee;

            if (catr)
                gather_k<true><<<(Nn + 7) / 8, 256>>>(Xin, prev_sums, prev_g, prev_b,
                                                      offs, csrc, catr, bond_emb,
                                                      mask, eps, S.A1hi, S.A1lo);
            else
                gather_k<false><<<(Nn + 7) / 8, 256>>>(Xin, prev_sums, prev_g, prev_b,
                                                       offs, csrc, nullptr, nullptr,
                                                       mask, eps, S.A1hi, S.A1lo);

            mma_gemm_k<true, 64><<<g1d, 256, 4 * SMEM64>>>(
                S.A1hi, S.A1lo,
                S.W1Thi + (size_t)c * Hh * Ee, S.W1Tlo + (size_t)c * Hh * Ee,
                nullptr, S.t1hi, S.t1lo, sumsH_c, Nn, Ee, Hh);

            bnrelu_split_k<<<2500, 256>>>(
                S.t1hi, S.t1lo, sumsH_c, g1, be1, S.A2hi, S.A2lo);

            mma_gemm_k<false, 64><<<g2d, 256, 4 * SMEM64>>>(
                S.A2hi, S.A2lo,
                S.W2Thi + (size_t)c * Ee * Hh, S.W2Tlo + (size_t)c * Ee * Hh,
                S.hB, nullptr, nullptr, sumsE_c, Nn, Hh, Ee);

            prev_sums = sumsE_c;
            prev_g = bng;
            prev_b = bnb;
        }
    }

    bn_apply_final_k<<<(Nn * Ee / 4 + 255) / 256, 256>>>(S.hB, prev_sums, prev_g, prev_b,
                                                         (float*)d_out);
}